// round 3
// baseline (speedup 1.0000x reference)
#include <cuda_runtime.h>
#include <cuda_bf16.h>
#include <cstdint>

#define N_NODES 50000
#define N_EDGES 800000
#define TOT_ADJ (N_EDGES + N_NODES)
#define HID 512           // HEADS*OUT_CH
#define IN_CH 128
#define OUT_CH 128
#define HEADS 4
#define NEG_SLOPE 0.2f
#define LN_EPS 1e-5f
#define CAP 256           // smem edge cache per node (deg ~Poisson(17); fallback path covers >CAP)

// ---------------- device scratch (static, no allocation) ----------------
__device__ float g_h[(size_t)N_NODES * HID];     // h = x @ lin_w
__device__ float g_act[(size_t)N_NODES * HID];   // relu(agg + gat_bias)
__device__ float g_asrc[N_NODES * HEADS];
__device__ float g_adst[N_NODES * HEADS];
__device__ int   g_src[N_EDGES];
__device__ int   g_dst[N_EDGES];
__device__ int   g_cnt[N_NODES];
__device__ int   g_cur[N_NODES];
__device__ int   g_off[N_NODES + 1];
__device__ int   g_adj[TOT_ADJ];
__device__ int   g_is64;

// ---------------- dtype probe: edge_index int32 vs int64 ----------------
// If the buffer really holds int64 indices, every 8-byte word is in [0, N_NODES).
// If it holds int32, an 8-byte read combines two random indices; the high word
// is a random value in [0, 50000) so the composite is >= 2^32 almost surely.
__global__ void detect_k(const void* ei) {
    if (threadIdx.x != 0) return;
    const long long* p = (const long long*)ei;
    int ok = 1;
    for (int i = 0; i < 4096; i += 7) {          // strided sample, 586 probes
        long long v = p[i];
        if (v < 0 || v >= N_NODES) { ok = 0; break; }
    }
    g_is64 = ok;
}

__global__ void convert_k(const void* ei) {
    int i = blockIdx.x * blockDim.x + threadIdx.x;
    if (i >= N_EDGES) return;
    if (g_is64) {
        const long long* p = (const long long*)ei;
        g_src[i] = (int)p[i];
        g_dst[i] = (int)p[N_EDGES + i];
    } else {
        const int* p = (const int*)ei;
        g_src[i] = p[i];
        g_dst[i] = p[N_EDGES + i];
    }
}

// ---------------- CSR build ----------------
__global__ void init_cnt_k() {
    int i = blockIdx.x * blockDim.x + threadIdx.x;
    if (i < N_NODES) g_cnt[i] = 1;   // self loop
}

__global__ void hist_k() {
    int i = blockIdx.x * blockDim.x + threadIdx.x;
    if (i < N_EDGES) atomicAdd(&g_cnt[g_dst[i]], 1);
}

__global__ void scan_k() {
    __shared__ int part[1024];
    const int T = 1024;
    const int CH = (N_NODES + T - 1) / T;   // 49
    int tid = threadIdx.x;
    int base = tid * CH;
    int s = 0;
    for (int j = 0; j < CH; j++) {
        int i = base + j;
        if (i < N_NODES) s += g_cnt[i];
    }
    part[tid] = s;
    __syncthreads();
    for (int st = 1; st < T; st <<= 1) {
        int v = (tid >= st) ? part[tid - st] : 0;
        __syncthreads();
        part[tid] += v;
        __syncthreads();
    }
    int run = (tid == 0) ? 0 : part[tid - 1];
    for (int j = 0; j < CH; j++) {
        int i = base + j;
        if (i < N_NODES) { g_off[i] = run; run += g_cnt[i]; }
    }
    if (base < N_NODES && base + CH >= N_NODES) g_off[N_NODES] = run;
}

__global__ void selfloop_k() {
    int i = blockIdx.x * blockDim.x + threadIdx.x;
    if (i < N_NODES) {
        g_adj[g_off[i]] = i;   // self loop first
        g_cur[i] = 1;
    }
}

__global__ void scatter_k() {
    int i = blockIdx.x * blockDim.x + threadIdx.x;
    if (i >= N_EDGES) return;
    int d = g_dst[i];
    int pos = g_off[d] + atomicAdd(&g_cur[d], 1);
    g_adj[pos] = g_src[i];
}

// ---------------- GEMM1: h = x @ lin_w  [N,128]x[128,512] ----------------
// Static smem budget: sA 32 KB (full K) + sB 16 KB (64-wide K-chunk) = 48 KB.
__global__ __launch_bounds__(256) void gemm1_k(const float* __restrict__ x,
                                               const float* __restrict__ w) {
    __shared__ float sA[64 * 128];   // [m][k]   32 KB
    __shared__ float sB[64 * 64];    // [k][n]   16 KB (one K-chunk)
    int tid = threadIdx.x;
    int m0 = blockIdx.y * 64;
    int n0 = blockIdx.x * 64;

#pragma unroll
    for (int p = 0; p < 8; p++) {
        int idx = tid + p * 256;
        int row = idx >> 5, c4 = idx & 31;
        int gr = m0 + row;
        float4 v = (gr < N_NODES) ? *(const float4*)&x[(size_t)gr * 128 + c4 * 4]
                                  : make_float4(0.f, 0.f, 0.f, 0.f);
        *(float4*)&sA[row * 128 + c4 * 4] = v;
    }

    int tx = tid & 15, ty = tid >> 4;
    float4 acc[4];
#pragma unroll
    for (int j = 0; j < 4; j++) acc[j] = make_float4(0.f, 0.f, 0.f, 0.f);

    for (int kc = 0; kc < 128; kc += 64) {
        __syncthreads();
#pragma unroll
        for (int p = 0; p < 4; p++) {
            int idx = tid + p * 256;             // float4 id in [0,1024)
            int k = idx >> 4, n4 = idx & 15;     // k in [0,64), n4 in [0,16)
            *(float4*)&sB[k * 64 + n4 * 4] =
                *(const float4*)&w[(size_t)(kc + k) * HID + n0 + n4 * 4];
        }
        __syncthreads();

        for (int kk = 0; kk < 64; kk += 4) {
            float4 a[4], b[4];
#pragma unroll
            for (int j = 0; j < 4; j++)
                a[j] = *(const float4*)&sA[(ty * 4 + j) * 128 + kc + kk];
#pragma unroll
            for (int u = 0; u < 4; u++)
                b[u] = *(const float4*)&sB[(kk + u) * 64 + tx * 4];
#pragma unroll
            for (int j = 0; j < 4; j++) {
                acc[j].x += a[j].x * b[0].x + a[j].y * b[1].x + a[j].z * b[2].x + a[j].w * b[3].x;
                acc[j].y += a[j].x * b[0].y + a[j].y * b[1].y + a[j].z * b[2].y + a[j].w * b[3].y;
                acc[j].z += a[j].x * b[0].z + a[j].y * b[1].z + a[j].z * b[2].z + a[j].w * b[3].z;
                acc[j].w += a[j].x * b[0].w + a[j].y * b[1].w + a[j].z * b[2].w + a[j].w * b[3].w;
            }
        }
    }
#pragma unroll
    for (int j = 0; j < 4; j++) {
        int gr = m0 + ty * 4 + j;
        if (gr < N_NODES)
            *(float4*)&g_h[(size_t)gr * HID + n0 + tx * 4] = acc[j];
    }
}

// ---------------- attention coefficients ----------------
__global__ __launch_bounds__(128) void attn_k(const float* __restrict__ att_src,
                                              const float* __restrict__ att_dst) {
    int node = blockIdx.x;
    int warp = threadIdx.x >> 5;   // = head
    int lane = threadIdx.x & 31;
    float4 v = *(const float4*)&g_h[(size_t)node * HID + warp * 128 + lane * 4];
    float4 a = *(const float4*)&att_src[warp * 128 + lane * 4];
    float4 b = *(const float4*)&att_dst[warp * 128 + lane * 4];
    float ds = v.x * a.x + v.y * a.y + v.z * a.z + v.w * a.w;
    float dd = v.x * b.x + v.y * b.y + v.z * b.z + v.w * b.w;
#pragma unroll
    for (int o = 16; o; o >>= 1) {
        ds += __shfl_xor_sync(0xffffffffu, ds, o);
        dd += __shfl_xor_sync(0xffffffffu, dd, o);
    }
    if (lane == 0) {
        g_asrc[node * HEADS + warp] = ds;
        g_adst[node * HEADS + warp] = dd;
    }
}

// ---------------- per-node softmax + weighted aggregation ----------------
__device__ __forceinline__ float leaky(float e) { return e > 0.f ? e : NEG_SLOPE * e; }

__global__ __launch_bounds__(128) void agg_k(const float* __restrict__ gat_bias) {
    __shared__ int   sadj[CAP];
    __shared__ float se[HEADS][CAP];
    __shared__ float red[HEADS][128];
    int d = blockIdx.x;
    int tid = threadIdx.x;
    int beg = g_off[d];
    int deg = g_off[d + 1] - beg;
    float4 adv = *(const float4*)&g_adst[d * HEADS];
    float ad0 = adv.x, ad1 = adv.y, ad2 = adv.z, ad3 = adv.w;
    bool cached = (deg <= CAP);

    float mx0 = -1e30f, mx1 = -1e30f, mx2 = -1e30f, mx3 = -1e30f;
    if (cached) {
        for (int i = tid; i < deg; i += 128) {
            int s = g_adj[beg + i];
            sadj[i] = s;
            float4 as = *(const float4*)&g_asrc[s * HEADS];
            float e0 = leaky(as.x + ad0); se[0][i] = e0; mx0 = fmaxf(mx0, e0);
            float e1 = leaky(as.y + ad1); se[1][i] = e1; mx1 = fmaxf(mx1, e1);
            float e2 = leaky(as.z + ad2); se[2][i] = e2; mx2 = fmaxf(mx2, e2);
            float e3 = leaky(as.w + ad3); se[3][i] = e3; mx3 = fmaxf(mx3, e3);
        }
    } else {
        for (int i = tid; i < deg; i += 128) {
            int s = g_adj[beg + i];
            float4 as = *(const float4*)&g_asrc[s * HEADS];
            mx0 = fmaxf(mx0, leaky(as.x + ad0));
            mx1 = fmaxf(mx1, leaky(as.y + ad1));
            mx2 = fmaxf(mx2, leaky(as.z + ad2));
            mx3 = fmaxf(mx3, leaky(as.w + ad3));
        }
    }
    red[0][tid] = mx0; red[1][tid] = mx1; red[2][tid] = mx2; red[3][tid] = mx3;
    __syncthreads();
    for (int st = 64; st; st >>= 1) {
        if (tid < st) {
#pragma unroll
            for (int h = 0; h < HEADS; h++)
                red[h][tid] = fmaxf(red[h][tid], red[h][tid + st]);
        }
        __syncthreads();
    }
    float m0 = red[0][0], m1 = red[1][0], m2 = red[2][0], m3 = red[3][0];
    __syncthreads();

    float s0 = 0.f, s1 = 0.f, s2 = 0.f, s3 = 0.f;
    if (cached) {
        for (int i = tid; i < deg; i += 128) {
            float a0 = expf(se[0][i] - m0); se[0][i] = a0; s0 += a0;
            float a1 = expf(se[1][i] - m1); se[1][i] = a1; s1 += a1;
            float a2 = expf(se[2][i] - m2); se[2][i] = a2; s2 += a2;
            float a3 = expf(se[3][i] - m3); se[3][i] = a3; s3 += a3;
        }
    } else {
        for (int i = tid; i < deg; i += 128) {
            int s = g_adj[beg + i];
            float4 as = *(const float4*)&g_asrc[s * HEADS];
            s0 += expf(leaky(as.x + ad0) - m0);
            s1 += expf(leaky(as.y + ad1) - m1);
            s2 += expf(leaky(as.z + ad2) - m2);
            s3 += expf(leaky(as.w + ad3) - m3);
        }
    }
    red[0][tid] = s0; red[1][tid] = s1; red[2][tid] = s2; red[3][tid] = s3;
    __syncthreads();
    for (int st = 64; st; st >>= 1) {
        if (tid < st) {
#pragma unroll
            for (int h = 0; h < HEADS; h++)
                red[h][tid] += red[h][tid + st];
        }
        __syncthreads();
    }
    float inv0 = 1.f / (red[0][0] + 1e-16f);
    float inv1 = 1.f / (red[1][0] + 1e-16f);
    float inv2 = 1.f / (red[2][0] + 1e-16f);
    float inv3 = 1.f / (red[3][0] + 1e-16f);

    int head = tid >> 5;
    float mh   = head == 0 ? m0  : head == 1 ? m1  : head == 2 ? m2  : m3;
    float invh = head == 0 ? inv0 : head == 1 ? inv1 : head == 2 ? inv2 : inv3;
    float adh  = head == 0 ? ad0 : head == 1 ? ad1 : head == 2 ? ad2 : ad3;

    float4 acc = make_float4(0.f, 0.f, 0.f, 0.f);
    const float4* hp = (const float4*)g_h;
    if (cached) {
#pragma unroll 4
        for (int i = 0; i < deg; i++) {
            float alpha = se[head][i] * invh;
            float4 v = hp[(size_t)sadj[i] * 128 + tid];
            acc.x += v.x * alpha; acc.y += v.y * alpha;
            acc.z += v.z * alpha; acc.w += v.w * alpha;
        }
    } else {
        for (int i = 0; i < deg; i++) {
            int s = g_adj[beg + i];
            float e = leaky(g_asrc[s * HEADS + head] + adh);
            float alpha = expf(e - mh) * invh;
            float4 v = hp[(size_t)s * 128 + tid];
            acc.x += v.x * alpha; acc.y += v.y * alpha;
            acc.z += v.z * alpha; acc.w += v.w * alpha;
        }
    }
    float4 b = ((const float4*)gat_bias)[tid];
    acc.x = fmaxf(acc.x + b.x, 0.f);
    acc.y = fmaxf(acc.y + b.y, 0.f);
    acc.z = fmaxf(acc.z + b.z, 0.f);
    acc.w = fmaxf(acc.w + b.w, 0.f);
    ((float4*)g_act)[(size_t)d * 128 + tid] = acc;
}

// ---------------- GEMM2 + bias + residual + LayerNorm ----------------
__global__ __launch_bounds__(128) void gemm2_ln_k(const float* __restrict__ proj_w,
                                                  const float* __restrict__ proj_b,
                                                  const float* __restrict__ x,
                                                  const float* __restrict__ lng,
                                                  const float* __restrict__ lnb,
                                                  float* __restrict__ out) {
    __shared__ float sAct[16 * HID];     // 32 KB
    __shared__ float smu[16], srs[16];
    int tid = threadIdx.x;               // 128; tid = output column
    int r0 = blockIdx.x * 16;

#pragma unroll
    for (int p = 0; p < 16; p++) {
        int idx = tid + p * 128;         // float4 index
        *(float4*)&sAct[idx * 4] = *(const float4*)&g_act[(size_t)r0 * HID + idx * 4];
    }
    __syncthreads();

    float acc[16];
#pragma unroll
    for (int r = 0; r < 16; r++) acc[r] = 0.f;

#pragma unroll 2
    for (int k = 0; k < HID; k += 4) {
        float w0 = proj_w[(k + 0) * OUT_CH + tid];
        float w1 = proj_w[(k + 1) * OUT_CH + tid];
        float w2 = proj_w[(k + 2) * OUT_CH + tid];
        float w3 = proj_w[(k + 3) * OUT_CH + tid];
#pragma unroll
        for (int r = 0; r < 16; r++) {
            float4 a = *(const float4*)&sAct[r * HID + k];
            acc[r] += a.x * w0 + a.y * w1 + a.z * w2 + a.w * w3;
        }
    }

    float pb = proj_b[tid], gg = lng[tid], bb = lnb[tid];
    float yv[16];
#pragma unroll
    for (int r = 0; r < 16; r++)
        yv[r] = acc[r] + pb + x[(size_t)(r0 + r) * OUT_CH + tid];

    __syncthreads();
#pragma unroll
    for (int r = 0; r < 16; r++) sAct[r * 128 + tid] = yv[r];
    __syncthreads();

    int warp = tid >> 5, lane = tid & 31;
    for (int q = 0; q < 4; q++) {
        int r = warp * 4 + q;
        float s1 = 0.f, s2 = 0.f;
        for (int j = lane; j < 128; j += 32) {
            float v = sAct[r * 128 + j];
            s1 += v; s2 += v * v;
        }
#pragma unroll
        for (int o = 16; o; o >>= 1) {
            s1 += __shfl_xor_sync(0xffffffffu, s1, o);
            s2 += __shfl_xor_sync(0xffffffffu, s2, o);
        }
        if (lane == 0) {
            float mu = s1 * (1.f / 128.f);
            smu[r] = mu;
            srs[r] = rsqrtf(s2 * (1.f / 128.f) - mu * mu + LN_EPS);
        }
    }
    __syncthreads();
#pragma unroll
    for (int r = 0; r < 16; r++) {
        float o = (yv[r] - smu[r]) * srs[r] * gg + bb;
        out[(size_t)(r0 + r) * OUT_CH + tid] = o;
    }
}

// ---------------- launch ----------------
extern "C" void kernel_launch(void* const* d_in, const int* in_sizes, int n_in,
                              void* d_out, int out_size) {
    const float* x        = (const float*)d_in[0];
    const void*  ei       = d_in[1];
    const float* lin_w    = (const float*)d_in[2];
    const float* att_src  = (const float*)d_in[3];
    const float* att_dst  = (const float*)d_in[4];
    const float* gat_bias = (const float*)d_in[5];
    const float* proj_w   = (const float*)d_in[6];
    const float* proj_b   = (const float*)d_in[7];
    const float* ln_g     = (const float*)d_in[8];
    const float* ln_b     = (const float*)d_in[9];
    float* out = (float*)d_out;

    detect_k<<<1, 32>>>(ei);
    convert_k<<<(N_EDGES + 255) / 256, 256>>>(ei);
    init_cnt_k<<<(N_NODES + 255) / 256, 256>>>();
    hist_k<<<(N_EDGES + 255) / 256, 256>>>();
    scan_k<<<1, 1024>>>();
    selfloop_k<<<(N_NODES + 255) / 256, 256>>>();
    scatter_k<<<(N_EDGES + 255) / 256, 256>>>();

    gemm1_k<<<dim3(HID / 64, (N_NODES + 63) / 64), 256>>>(x, lin_w);
    attn_k<<<N_NODES, 128>>>(att_src, att_dst);
    agg_k<<<N_NODES, 128>>>(gat_bias);
    gemm2_ln_k<<<N_NODES / 16, 128>>>(proj_w, proj_b, x, ln_g, ln_b, out);
}

// round 5
// speedup vs baseline: 1.0730x; 1.0730x over previous
#include <cuda_runtime.h>
#include <cuda_fp16.h>
#include <cstdint>

#define N_NODES 50000
#define N_EDGES 800000
#define TOT_ADJ (N_EDGES + N_NODES)
#define HID 512           // HEADS*OUT_CH
#define IN_CH 128
#define OUT_CH 128
#define HEADS 4
#define NEG_SLOPE 0.2f
#define LN_EPS 1e-5f
#define CAP 256           // smem edge cache per node (deg ~Poisson(17); fallback path covers >CAP)

// ---------------- device scratch (static, no allocation) ----------------
__device__ __half g_h16[(size_t)N_NODES * HID];  // h = x @ lin_w  (fp16, L2-resident 51MB)
__device__ float g_act[(size_t)N_NODES * HID];   // relu(agg + gat_bias)
__device__ float g_asrc[N_NODES * HEADS];
__device__ float g_adst[N_NODES * HEADS];
__device__ int   g_src[N_EDGES];
__device__ int   g_dst[N_EDGES];
__device__ int   g_cnt[N_NODES];
__device__ int   g_cur[N_NODES];
__device__ int   g_off[N_NODES + 1];
__device__ int   g_adj[TOT_ADJ];
__device__ int   g_is64;

// ---------------- dtype probe: edge_index int32 vs int64 ----------------
__global__ void detect_k(const void* ei) {
    if (threadIdx.x != 0) return;
    const long long* p = (const long long*)ei;
    int ok = 1;
    for (int i = 0; i < 4096; i += 7) {
        long long v = p[i];
        if (v < 0 || v >= N_NODES) { ok = 0; break; }
    }
    g_is64 = ok;
}

__global__ void init_cnt_k() {
    int i = blockIdx.x * blockDim.x + threadIdx.x;
    if (i < N_NODES) g_cnt[i] = 1;   // self loop
}

// convert + dst histogram fused (saves one 800k pass)
__global__ void convert_hist_k(const void* ei) {
    int i = blockIdx.x * blockDim.x + threadIdx.x;
    if (i >= N_EDGES) return;
    int s, d;
    if (g_is64) {
        const long long* p = (const long long*)ei;
        s = (int)p[i];
        d = (int)p[N_EDGES + i];
    } else {
        const int* p = (const int*)ei;
        s = p[i];
        d = p[N_EDGES + i];
    }
    g_src[i] = s;
    g_dst[i] = d;
    atomicAdd(&g_cnt[d], 1);
}

__global__ void scan_k() {
    __shared__ int part[1024];
    const int T = 1024;
    const int CH = (N_NODES + T - 1) / T;   // 49
    int tid = threadIdx.x;
    int base = tid * CH;
    int s = 0;
    for (int j = 0; j < CH; j++) {
        int i = base + j;
        if (i < N_NODES) s += g_cnt[i];
    }
    part[tid] = s;
    __syncthreads();
    for (int st = 1; st < T; st <<= 1) {
        int v = (tid >= st) ? part[tid - st] : 0;
        __syncthreads();
        part[tid] += v;
        __syncthreads();
    }
    int run = (tid == 0) ? 0 : part[tid - 1];
    for (int j = 0; j < CH; j++) {
        int i = base + j;
        if (i < N_NODES) { g_off[i] = run; run += g_cnt[i]; }
    }
    if (base < N_NODES && base + CH >= N_NODES) g_off[N_NODES] = run;
}

__global__ void selfloop_k() {
    int i = blockIdx.x * blockDim.x + threadIdx.x;
    if (i < N_NODES) {
        g_adj[g_off[i]] = i;   // self loop first
        g_cur[i] = 1;
    }
}

__global__ void scatter_k() {
    int i = blockIdx.x * blockDim.x + threadIdx.x;
    if (i >= N_EDGES) return;
    int d = g_dst[i];
    int pos = g_off[d] + atomicAdd(&g_cur[d], 1);
    g_adj[pos] = g_src[i];
}

// ---------------- GEMM1: h = x @ lin_w  [N,128]x[128,512], fp16 out ------
// Static smem: sA 32 KB (full K) + sB 16 KB (64-wide K-chunk) = 48 KB.
__global__ __launch_bounds__(256) void gemm1_k(const float* __restrict__ x,
                                               const float* __restrict__ w) {
    __shared__ float sA[64 * 128];   // [m][k]   32 KB
    __shared__ float sB[64 * 64];    // [k][n]   16 KB (one K-chunk)
    int tid = threadIdx.x;
    int m0 = blockIdx.y * 64;
    int n0 = blockIdx.x * 64;

#pragma unroll
    for (int p = 0; p < 8; p++) {
        int idx = tid + p * 256;
        int row = idx >> 5, c4 = idx & 31;
        int gr = m0 + row;
        float4 v = (gr < N_NODES) ? *(const float4*)&x[(size_t)gr * 128 + c4 * 4]
                                  : make_float4(0.f, 0.f, 0.f, 0.f);
        *(float4*)&sA[row * 128 + c4 * 4] = v;
    }

    int tx = tid & 15, ty = tid >> 4;
    float4 acc[4];
#pragma unroll
    for (int j = 0; j < 4; j++) acc[j] = make_float4(0.f, 0.f, 0.f, 0.f);

    for (int kc = 0; kc < 128; kc += 64) {
        __syncthreads();
#pragma unroll
        for (int p = 0; p < 4; p++) {
            int idx = tid + p * 256;
            int k = idx >> 4, n4 = idx & 15;
            *(float4*)&sB[k * 64 + n4 * 4] =
                *(const float4*)&w[(size_t)(kc + k) * HID + n0 + n4 * 4];
        }
        __syncthreads();

        for (int kk = 0; kk < 64; kk += 4) {
            float4 a[4], b[4];
#pragma unroll
            for (int j = 0; j < 4; j++)
                a[j] = *(const float4*)&sA[(ty * 4 + j) * 128 + kc + kk];
#pragma unroll
            for (int u = 0; u < 4; u++)
                b[u] = *(const float4*)&sB[(kk + u) * 64 + tx * 4];
#pragma unroll
            for (int j = 0; j < 4; j++) {
                acc[j].x += a[j].x * b[0].x + a[j].y * b[1].x + a[j].z * b[2].x + a[j].w * b[3].x;
                acc[j].y += a[j].x * b[0].y + a[j].y * b[1].y + a[j].z * b[2].y + a[j].w * b[3].y;
                acc[j].z += a[j].x * b[0].z + a[j].y * b[1].z + a[j].z * b[2].z + a[j].w * b[3].z;
                acc[j].w += a[j].x * b[0].w + a[j].y * b[1].w + a[j].z * b[2].w + a[j].w * b[3].w;
            }
        }
    }
#pragma unroll
    for (int j = 0; j < 4; j++) {
        int gr = m0 + ty * 4 + j;
        if (gr < N_NODES) {
            __half2 h0 = __floats2half2_rn(acc[j].x, acc[j].y);
            __half2 h1 = __floats2half2_rn(acc[j].z, acc[j].w);
            __half2* dst = (__half2*)&g_h16[(size_t)gr * HID + n0 + tx * 4];
            dst[0] = h0;
            dst[1] = h1;
        }
    }
}

// ---------------- attention coefficients (fp16 h, fp32 math) -------------
__global__ __launch_bounds__(128) void attn_k(const float* __restrict__ att_src,
                                              const float* __restrict__ att_dst) {
    int node = blockIdx.x;
    int w = threadIdx.x >> 5;   // = head
    int lane = threadIdx.x & 31;
    const __half2* hp = (const __half2*)&g_h16[(size_t)node * HID + w * 128 + lane * 4];
    __half2 p0 = hp[0], p1 = hp[1];
    float2 v0 = __half22float2(p0), v1 = __half22float2(p1);
    float4 a = *(const float4*)&att_src[w * 128 + lane * 4];
    float4 b = *(const float4*)&att_dst[w * 128 + lane * 4];
    float ds = v0.x * a.x + v0.y * a.y + v1.x * a.z + v1.y * a.w;
    float dd = v0.x * b.x + v0.y * b.y + v1.x * b.z + v1.y * b.w;
#pragma unroll
    for (int o = 16; o; o >>= 1) {
        ds += __shfl_xor_sync(0xffffffffu, ds, o);
        dd += __shfl_xor_sync(0xffffffffu, dd, o);
    }
    if (lane == 0) {
        g_asrc[node * HEADS + w] = ds;
        g_adst[node * HEADS + w] = dd;
    }
}

// ---------------- per-node softmax + weighted aggregation ----------------
__device__ __forceinline__ float leaky(float e) { return e > 0.f ? e : NEG_SLOPE * e; }

__global__ __launch_bounds__(128) void agg_k(const float* __restrict__ gat_bias) {
    __shared__ int   sadj[CAP];
    __shared__ float se[HEADS][CAP];
    int d = blockIdx.x;
    int tid = threadIdx.x;
    int w = tid >> 5;            // warp = head
    int lane = tid & 31;
    int beg = g_off[d];
    int deg = g_off[d + 1] - beg;
    float adh = g_adst[d * HEADS + w];

    float mx = -1e30f, sum = 0.f, inv;
    bool cached = (deg <= CAP);

    if (cached) {
        for (int i = lane; i < deg; i += 32) {
            int s = g_adj[beg + i];
            if (w == 0) sadj[i] = s;
            float e = leaky(g_asrc[s * HEADS + w] + adh);
            se[w][i] = e;
            mx = fmaxf(mx, e);
        }
#pragma unroll
        for (int o = 16; o; o >>= 1) mx = fmaxf(mx, __shfl_xor_sync(0xffffffffu, mx, o));
        for (int i = lane; i < deg; i += 32) {
            float a = __expf(se[w][i] - mx);
            se[w][i] = a;
            sum += a;
        }
#pragma unroll
        for (int o = 16; o; o >>= 1) sum += __shfl_xor_sync(0xffffffffu, sum, o);
        inv = 1.f / (sum + 1e-16f);
        __syncthreads();           // sadj (warp0) + se visible to gather
    } else {
        for (int i = lane; i < deg; i += 32) {
            int s = g_adj[beg + i];
            mx = fmaxf(mx, leaky(g_asrc[s * HEADS + w] + adh));
        }
#pragma unroll
        for (int o = 16; o; o >>= 1) mx = fmaxf(mx, __shfl_xor_sync(0xffffffffu, mx, o));
        for (int i = lane; i < deg; i += 32) {
            int s = g_adj[beg + i];
            sum += __expf(leaky(g_asrc[s * HEADS + w] + adh) - mx);
        }
#pragma unroll
        for (int o = 16; o; o >>= 1) sum += __shfl_xor_sync(0xffffffffu, sum, o);
        inv = 1.f / (sum + 1e-16f);
        __syncthreads();
    }

    // gather: thread tid covers channels [4*tid, 4*tid+4) of (head w)'s 128
    float4 acc = make_float4(0.f, 0.f, 0.f, 0.f);
    float4 acc2 = make_float4(0.f, 0.f, 0.f, 0.f);
    if (cached) {
        int i = 0;
        for (; i + 1 < deg; i += 2) {
            float al0 = se[w][i] * inv;
            float al1 = se[w][i + 1] * inv;
            const __half2* r0 = (const __half2*)&g_h16[(size_t)sadj[i] * HID + 4 * tid];
            const __half2* r1 = (const __half2*)&g_h16[(size_t)sadj[i + 1] * HID + 4 * tid];
            __half2 a0 = r0[0], a1 = r0[1];
            __half2 b0 = r1[0], b1 = r1[1];
            float2 f0 = __half22float2(a0), f1 = __half22float2(a1);
            float2 q0 = __half22float2(b0), q1 = __half22float2(b1);
            acc.x += f0.x * al0;  acc.y += f0.y * al0;
            acc.z += f1.x * al0;  acc.w += f1.y * al0;
            acc2.x += q0.x * al1; acc2.y += q0.y * al1;
            acc2.z += q1.x * al1; acc2.w += q1.y * al1;
        }
        if (i < deg) {
            float al = se[w][i] * inv;
            const __half2* r = (const __half2*)&g_h16[(size_t)sadj[i] * HID + 4 * tid];
            float2 f0 = __half22float2(r[0]), f1 = __half22float2(r[1]);
            acc.x += f0.x * al; acc.y += f0.y * al;
            acc.z += f1.x * al; acc.w += f1.y * al;
        }
    } else {
        for (int i = 0; i < deg; i++) {
            int s = g_adj[beg + i];
            float e = leaky(g_asrc[s * HEADS + w] + adh);
            float al = __expf(e - mx) * inv;
            const __half2* r = (const __half2*)&g_h16[(size_t)s * HID + 4 * tid];
            float2 f0 = __half22float2(r[0]), f1 = __half22float2(r[1]);
            acc.x += f0.x * al; acc.y += f0.y * al;
            acc.z += f1.x * al; acc.w += f1.y * al;
        }
    }
    acc.x += acc2.x; acc.y += acc2.y; acc.z += acc2.z; acc.w += acc2.w;

    float4 b = ((const float4*)gat_bias)[tid];
    acc.x = fmaxf(acc.x + b.x, 0.f);
    acc.y = fmaxf(acc.y + b.y, 0.f);
    acc.z = fmaxf(acc.z + b.z, 0.f);
    acc.w = fmaxf(acc.w + b.w, 0.f);
    ((float4*)g_act)[(size_t)d * 128 + tid] = acc;
}

// ---------------- GEMM2 + bias + residual + LayerNorm ----------------
__global__ __launch_bounds__(128) void gemm2_ln_k(const float* __restrict__ proj_w,
                                                  const float* __restrict__ proj_b,
                                                  const float* __restrict__ x,
                                                  const float* __restrict__ lng,
                                                  const float* __restrict__ lnb,
                                                  float* __restrict__ out) {
    __shared__ float sAct[16 * HID];     // 32 KB
    __shared__ float smu[16], srs[16];
    int tid = threadIdx.x;               // 128; tid = output column
    int r0 = blockIdx.x * 16;

#pragma unroll
    for (int p = 0; p < 16; p++) {
        int idx = tid + p * 128;         // float4 index
        *(float4*)&sAct[idx * 4] = *(const float4*)&g_act[(size_t)r0 * HID + idx * 4];
    }
    __syncthreads();

    float acc[16];
#pragma unroll
    for (int r = 0; r < 16; r++) acc[r] = 0.f;

#pragma unroll 2
    for (int k = 0; k < HID; k += 4) {
        float w0 = proj_w[(k + 0) * OUT_CH + tid];
        float w1 = proj_w[(k + 1) * OUT_CH + tid];
        float w2 = proj_w[(k + 2) * OUT_CH + tid];
        float w3 = proj_w[(k + 3) * OUT_CH + tid];
#pragma unroll
        for (int r = 0; r < 16; r++) {
            float4 a = *(const float4*)&sAct[r * HID + k];
            acc[r] += a.x * w0 + a.y * w1 + a.z * w2 + a.w * w3;
        }
    }

    float pb = proj_b[tid], gg = lng[tid], bb = lnb[tid];
    float yv[16];
#pragma unroll
    for (int r = 0; r < 16; r++)
        yv[r] = acc[r] + pb + x[(size_t)(r0 + r) * OUT_CH + tid];

    __syncthreads();
#pragma unroll
    for (int r = 0; r < 16; r++) sAct[r * 128 + tid] = yv[r];
    __syncthreads();

    int warp = tid >> 5, lane = tid & 31;
    for (int q = 0; q < 4; q++) {
        int r = warp * 4 + q;
        float s1 = 0.f, s2 = 0.f;
        for (int j = lane; j < 128; j += 32) {
            float v = sAct[r * 128 + j];
            s1 += v; s2 += v * v;
        }
#pragma unroll
        for (int o = 16; o; o >>= 1) {
            s1 += __shfl_xor_sync(0xffffffffu, s1, o);
            s2 += __shfl_xor_sync(0xffffffffu, s2, o);
        }
        if (lane == 0) {
            float mu = s1 * (1.f / 128.f);
            smu[r] = mu;
            srs[r] = rsqrtf(s2 * (1.f / 128.f) - mu * mu + LN_EPS);
        }
    }
    __syncthreads();
#pragma unroll
    for (int r = 0; r < 16; r++) {
        float o = (yv[r] - smu[r]) * srs[r] * gg + bb;
        out[(size_t)(r0 + r) * OUT_CH + tid] = o;
    }
}

// ---------------- launch ----------------
extern "C" void kernel_launch(void* const* d_in, const int* in_sizes, int n_in,
                              void* d_out, int out_size) {
    const float* x        = (const float*)d_in[0];
    const void*  ei       = d_in[1];
    const float* lin_w    = (const float*)d_in[2];
    const float* att_src  = (const float*)d_in[3];
    const float* att_dst  = (const float*)d_in[4];
    const float* gat_bias = (const float*)d_in[5];
    const float* proj_w   = (const float*)d_in[6];
    const float* proj_b   = (const float*)d_in[7];
    const float* ln_g     = (const float*)d_in[8];
    const float* ln_b     = (const float*)d_in[9];
    float* out = (float*)d_out;

    detect_k<<<1, 32>>>(ei);
    init_cnt_k<<<(N_NODES + 255) / 256, 256>>>();
    convert_hist_k<<<(N_EDGES + 255) / 256, 256>>>(ei);
    scan_k<<<1, 1024>>>();
    selfloop_k<<<(N_NODES + 255) / 256, 256>>>();
    scatter_k<<<(N_EDGES + 255) / 256, 256>>>();

    gemm1_k<<<dim3(HID / 64, (N_NODES + 63) / 64), 256>>>(x, lin_w);
    attn_k<<<N_NODES, 128>>>(att_src, att_dst);
    agg_k<<<N_NODES, 128>>>(gat_bias);
    gemm2_ln_k<<<N_NODES / 16, 128>>>(proj_w, proj_b, x, ln_g, ln_b, out);
}

// round 6
// speedup vs baseline: 1.3843x; 1.2901x over previous
#include <cuda_runtime.h>
#include <cuda_fp16.h>
#include <cstdint>

#define N_NODES 50000
#define N_EDGES 800000
#define TOT_ADJ (N_EDGES + N_NODES)
#define HID 512           // HEADS*OUT_CH
#define IN_CH 128
#define OUT_CH 128
#define HEADS 4
#define NEG_SLOPE 0.2f
#define LN_EPS 1e-5f
#define CAP 256
#define SCAN_BLK 256
#define NPART ((N_NODES + SCAN_BLK - 1) / SCAN_BLK)   // 196

// ---------------- device scratch (static, no allocation) ----------------
__device__ __half g_h16[(size_t)N_NODES * HID];    // h  (fp16, 51 MB, ~L2-resident)
__device__ __half g_act16[(size_t)N_NODES * HID];  // relu(agg + gat_bias) fp16
__device__ float g_asrc[N_NODES * HEADS];
__device__ float g_adst[N_NODES * HEADS];
__device__ int   g_src[N_EDGES];
__device__ int   g_dst[N_EDGES];
__device__ int   g_cnt[N_NODES];
__device__ int   g_cur[N_NODES];
__device__ int   g_off[N_NODES + 1];
__device__ int   g_adj[TOT_ADJ];
__device__ int   g_part[NPART];
__device__ int   g_is64;

__device__ __forceinline__ uint32_t f2tf32(float f) {
    uint32_t r;
    asm("cvt.rna.tf32.f32 %0, %1;" : "=r"(r) : "f"(f));
    return r;
}

// ---------------- dtype probe: edge_index int32 vs int64 ----------------
__global__ void detect_k(const void* ei) {
    if (threadIdx.x != 0) return;
    const long long* p = (const long long*)ei;
    int ok = 1;
    for (int i = 0; i < 4096; i += 7) {
        long long v = p[i];
        if (v < 0 || v >= N_NODES) { ok = 0; break; }
    }
    g_is64 = ok;
}

__global__ void init_cnt_k() {
    int i = blockIdx.x * blockDim.x + threadIdx.x;
    if (i < N_NODES) g_cnt[i] = 1;   // self loop
}

__global__ void convert_hist_k(const void* ei) {
    int i = blockIdx.x * blockDim.x + threadIdx.x;
    if (i >= N_EDGES) return;
    int s, d;
    if (g_is64) {
        const long long* p = (const long long*)ei;
        s = (int)p[i];
        d = (int)p[N_EDGES + i];
    } else {
        const int* p = (const int*)ei;
        s = p[i];
        d = p[N_EDGES + i];
    }
    g_src[i] = s;
    g_dst[i] = d;
    atomicAdd(&g_cnt[d], 1);
}

// ---------------- multi-block exclusive scan of g_cnt -> g_off ----------
__global__ void partial_k() {
    __shared__ int sd[SCAN_BLK];
    int i = blockIdx.x * SCAN_BLK + threadIdx.x;
    sd[threadIdx.x] = (i < N_NODES) ? g_cnt[i] : 0;
    __syncthreads();
    for (int st = SCAN_BLK / 2; st; st >>= 1) {
        if (threadIdx.x < st) sd[threadIdx.x] += sd[threadIdx.x + st];
        __syncthreads();
    }
    if (threadIdx.x == 0) g_part[blockIdx.x] = sd[0];
}

__global__ void scanpart_k() {
    __shared__ int sp[256];
    int t = threadIdx.x;
    int own = (t < NPART) ? g_part[t] : 0;
    sp[t] = own;
    __syncthreads();
    for (int st = 1; st < 256; st <<= 1) {
        int v = (t >= st) ? sp[t - st] : 0;
        __syncthreads();
        sp[t] += v;
        __syncthreads();
    }
    if (t < NPART) g_part[t] = sp[t] - own;     // exclusive
    if (t == 255) g_off[N_NODES] = sp[255];     // total (padding is zero)
}

__global__ void offsets_k() {
    __shared__ int sd[SCAN_BLK];
    int i = blockIdx.x * SCAN_BLK + threadIdx.x;
    int own = (i < N_NODES) ? g_cnt[i] : 0;
    sd[threadIdx.x] = own;
    __syncthreads();
    for (int st = 1; st < SCAN_BLK; st <<= 1) {
        int v = (threadIdx.x >= st) ? sd[threadIdx.x - st] : 0;
        __syncthreads();
        sd[threadIdx.x] += v;
        __syncthreads();
    }
    if (i < N_NODES) g_off[i] = g_part[blockIdx.x] + sd[threadIdx.x] - own;
}

__global__ void selfloop_k() {
    int i = blockIdx.x * blockDim.x + threadIdx.x;
    if (i < N_NODES) {
        g_adj[g_off[i]] = i;   // self loop first
        g_cur[i] = 1;
    }
}

__global__ void scatter_k() {
    int i = blockIdx.x * blockDim.x + threadIdx.x;
    if (i >= N_EDGES) return;
    int d = g_dst[i];
    int pos = g_off[d] + atomicAdd(&g_cur[d], 1);
    g_adj[pos] = g_src[i];
}

// ---------------- GEMM1: h = x @ lin_w, tf32 mma, fp16 out --------------
// block 256 thr = 8 warps (warp_m 0..3 x warp_n 0..1), 64x64 output tile.
// sA stride 132, sB stride 72: conflict-free under m16n8k8 fragment pattern.
__global__ __launch_bounds__(256) void gemm1_k(const float* __restrict__ x,
                                               const float* __restrict__ w) {
    __shared__ uint32_t sA[64 * 132];   // 33 KB, full K=128
    __shared__ uint32_t sB[32 * 72];    // 9 KB, one 32-row K chunk
    int tid = threadIdx.x;
    int lane = tid & 31, wid = tid >> 5;
    int warp_m = wid & 3, warp_n = wid >> 2;
    int m0 = blockIdx.y * 64;
    int n0 = blockIdx.x * 64;

#pragma unroll
    for (int p = 0; p < 8; p++) {
        int idx = tid + p * 256;              // 2048 float4
        int row = idx >> 5, c4 = (idx & 31) * 4;
        int gr = m0 + row;
        float4 v = (gr < N_NODES) ? *(const float4*)&x[(size_t)gr * 128 + c4]
                                  : make_float4(0.f, 0.f, 0.f, 0.f);
        uint32_t* d = &sA[row * 132 + c4];
        d[0] = f2tf32(v.x); d[1] = f2tf32(v.y);
        d[2] = f2tf32(v.z); d[3] = f2tf32(v.w);
    }

    float c[4][4];
#pragma unroll
    for (int nt = 0; nt < 4; nt++)
#pragma unroll
        for (int r = 0; r < 4; r++) c[nt][r] = 0.f;

    int aRow = warp_m * 16 + (lane >> 2);
    int kq = lane & 3;

    for (int kc = 0; kc < 128; kc += 32) {
        __syncthreads();
#pragma unroll
        for (int p = 0; p < 2; p++) {
            int idx = tid + p * 256;          // 512 float4
            int kr = idx >> 4, c4 = (idx & 15) * 4;
            float4 v = *(const float4*)&w[(size_t)(kc + kr) * HID + n0 + c4];
            uint32_t* d = &sB[kr * 72 + c4];
            d[0] = f2tf32(v.x); d[1] = f2tf32(v.y);
            d[2] = f2tf32(v.z); d[3] = f2tf32(v.w);
        }
        __syncthreads();

#pragma unroll
        for (int ks = 0; ks < 32; ks += 8) {
            uint32_t a0 = sA[aRow * 132 + kc + ks + kq];
            uint32_t a1 = sA[(aRow + 8) * 132 + kc + ks + kq];
            uint32_t a2 = sA[aRow * 132 + kc + ks + kq + 4];
            uint32_t a3 = sA[(aRow + 8) * 132 + kc + ks + kq + 4];
#pragma unroll
            for (int nt = 0; nt < 4; nt++) {
                int nb = warp_n * 32 + nt * 8 + (lane >> 2);
                uint32_t b0 = sB[(ks + kq) * 72 + nb];
                uint32_t b1 = sB[(ks + kq + 4) * 72 + nb];
                asm volatile(
                    "mma.sync.aligned.m16n8k8.row.col.f32.tf32.tf32.f32 "
                    "{%0,%1,%2,%3}, {%4,%5,%6,%7}, {%8,%9}, {%0,%1,%2,%3};"
                    : "+f"(c[nt][0]), "+f"(c[nt][1]), "+f"(c[nt][2]), "+f"(c[nt][3])
                    : "r"(a0), "r"(a1), "r"(a2), "r"(a3), "r"(b0), "r"(b1));
            }
        }
    }

    int rowA = m0 + warp_m * 16 + (lane >> 2);
    int colB = n0 + warp_n * 32 + (lane & 3) * 2;
#pragma unroll
    for (int nt = 0; nt < 4; nt++) {
        int col = colB + nt * 8;
        if (rowA < N_NODES)
            *(__half2*)&g_h16[(size_t)rowA * HID + col] =
                __floats2half2_rn(c[nt][0], c[nt][1]);
        if (rowA + 8 < N_NODES)
            *(__half2*)&g_h16[(size_t)(rowA + 8) * HID + col] =
                __floats2half2_rn(c[nt][2], c[nt][3]);
    }
}

// ---------------- attention coefficients (fp16 h, fp32 math) -------------
__global__ __launch_bounds__(128) void attn_k(const float* __restrict__ att_src,
                                              const float* __restrict__ att_dst) {
    int node = blockIdx.x;
    int w = threadIdx.x >> 5;   // = head
    int lane = threadIdx.x & 31;
    const __half2* hp = (const __half2*)&g_h16[(size_t)node * HID + w * 128 + lane * 4];
    __half2 p0 = hp[0], p1 = hp[1];
    float2 v0 = __half22float2(p0), v1 = __half22float2(p1);
    float4 a = *(const float4*)&att_src[w * 128 + lane * 4];
    float4 b = *(const float4*)&att_dst[w * 128 + lane * 4];
    float ds = v0.x * a.x + v0.y * a.y + v1.x * a.z + v1.y * a.w;
    float dd = v0.x * b.x + v0.y * b.y + v1.x * b.z + v1.y * b.w;
#pragma unroll
    for (int o = 16; o; o >>= 1) {
        ds += __shfl_xor_sync(0xffffffffu, ds, o);
        dd += __shfl_xor_sync(0xffffffffu, dd, o);
    }
    if (lane == 0) {
        g_asrc[node * HEADS + w] = ds;
        g_adst[node * HEADS + w] = dd;
    }
}

// ---------------- per-node softmax + weighted aggregation ----------------
__device__ __forceinline__ float leaky(float e) { return e > 0.f ? e : NEG_SLOPE * e; }

__global__ __launch_bounds__(128) void agg_k(const float* __restrict__ gat_bias) {
    __shared__ int   sadj[CAP];
    __shared__ float se[HEADS][CAP];
    int d = blockIdx.x;
    int tid = threadIdx.x;
    int w = tid >> 5;            // warp = head
    int lane = tid & 31;
    int beg = g_off[d];
    int deg = g_off[d + 1] - beg;
    float adh = g_adst[d * HEADS + w];

    float mx = -1e30f, sum = 0.f, inv;
    bool cached = (deg <= CAP);

    if (cached) {
        for (int i = lane; i < deg; i += 32) {
            int s = g_adj[beg + i];
            if (w == 0) sadj[i] = s;
            float e = leaky(g_asrc[s * HEADS + w] + adh);
            se[w][i] = e;
            mx = fmaxf(mx, e);
        }
#pragma unroll
        for (int o = 16; o; o >>= 1) mx = fmaxf(mx, __shfl_xor_sync(0xffffffffu, mx, o));
        for (int i = lane; i < deg; i += 32) {
            float a = __expf(se[w][i] - mx);
            se[w][i] = a;
            sum += a;
        }
#pragma unroll
        for (int o = 16; o; o >>= 1) sum += __shfl_xor_sync(0xffffffffu, sum, o);
        inv = 1.f / (sum + 1e-16f);
        __syncthreads();
    } else {
        for (int i = lane; i < deg; i += 32) {
            int s = g_adj[beg + i];
            mx = fmaxf(mx, leaky(g_asrc[s * HEADS + w] + adh));
        }
#pragma unroll
        for (int o = 16; o; o >>= 1) mx = fmaxf(mx, __shfl_xor_sync(0xffffffffu, mx, o));
        for (int i = lane; i < deg; i += 32) {
            int s = g_adj[beg + i];
            sum += __expf(leaky(g_asrc[s * HEADS + w] + adh) - mx);
        }
#pragma unroll
        for (int o = 16; o; o >>= 1) sum += __shfl_xor_sync(0xffffffffu, sum, o);
        inv = 1.f / (sum + 1e-16f);
        __syncthreads();
    }

    // gather: thread tid covers channels [4*tid, 4*tid+4)  (4-wide MLP unroll)
    float4 acc = make_float4(0.f, 0.f, 0.f, 0.f);
    float4 acc2 = make_float4(0.f, 0.f, 0.f, 0.f);
    if (cached) {
        int i = 0;
        for (; i + 3 < deg; i += 4) {
            float al0 = se[w][i] * inv,     al1 = se[w][i + 1] * inv;
            float al2 = se[w][i + 2] * inv, al3 = se[w][i + 3] * inv;
            uint2 v0 = *(const uint2*)&g_h16[(size_t)sadj[i]     * HID + 4 * tid];
            uint2 v1 = *(const uint2*)&g_h16[(size_t)sadj[i + 1] * HID + 4 * tid];
            uint2 v2 = *(const uint2*)&g_h16[(size_t)sadj[i + 2] * HID + 4 * tid];
            uint2 v3 = *(const uint2*)&g_h16[(size_t)sadj[i + 3] * HID + 4 * tid];
            float2 f0a = __half22float2(*(__half2*)&v0.x), f0b = __half22float2(*(__half2*)&v0.y);
            float2 f1a = __half22float2(*(__half2*)&v1.x), f1b = __half22float2(*(__half2*)&v1.y);
            float2 f2a = __half22float2(*(__half2*)&v2.x), f2b = __half22float2(*(__half2*)&v2.y);
            float2 f3a = __half22float2(*(__half2*)&v3.x), f3b = __half22float2(*(__half2*)&v3.y);
            acc.x  += f0a.x * al0; acc.y  += f0a.y * al0; acc.z  += f0b.x * al0; acc.w  += f0b.y * al0;
            acc2.x += f1a.x * al1; acc2.y += f1a.y * al1; acc2.z += f1b.x * al1; acc2.w += f1b.y * al1;
            acc.x  += f2a.x * al2; acc.y  += f2a.y * al2; acc.z  += f2b.x * al2; acc.w  += f2b.y * al2;
            acc2.x += f3a.x * al3; acc2.y += f3a.y * al3; acc2.z += f3b.x * al3; acc2.w += f3b.y * al3;
        }
        for (; i < deg; i++) {
            float al = se[w][i] * inv;
            uint2 v = *(const uint2*)&g_h16[(size_t)sadj[i] * HID + 4 * tid];
            float2 fa = __half22float2(*(__half2*)&v.x), fb = __half22float2(*(__half2*)&v.y);
            acc.x += fa.x * al; acc.y += fa.y * al;
            acc.z += fb.x * al; acc.w += fb.y * al;
        }
    } else {
        for (int i = 0; i < deg; i++) {
            int s = g_adj[beg + i];
            float e = leaky(g_asrc[s * HEADS + w] + adh);
            float al = __expf(e - mx) * inv;
            uint2 v = *(const uint2*)&g_h16[(size_t)s * HID + 4 * tid];
            float2 fa = __half22float2(*(__half2*)&v.x), fb = __half22float2(*(__half2*)&v.y);
            acc.x += fa.x * al; acc.y += fa.y * al;
            acc.z += fb.x * al; acc.w += fb.y * al;
        }
    }
    acc.x += acc2.x; acc.y += acc2.y; acc.z += acc2.z; acc.w += acc2.w;

    float4 b = ((const float4*)gat_bias)[tid];
    acc.x = fmaxf(acc.x + b.x, 0.f);
    acc.y = fmaxf(acc.y + b.y, 0.f);
    acc.z = fmaxf(acc.z + b.z, 0.f);
    acc.w = fmaxf(acc.w + b.w, 0.f);
    uint2 st;
    *(__half2*)&st.x = __floats2half2_rn(acc.x, acc.y);
    *(__half2*)&st.y = __floats2half2_rn(acc.z, acc.w);
    *(uint2*)&g_act16[(size_t)d * HID + 4 * tid] = st;
}

// ---------------- GEMM2 + bias + residual + LayerNorm ----------------
__global__ __launch_bounds__(128) void gemm2_ln_k(const float* __restrict__ proj_w,
                                                  const float* __restrict__ proj_b,
                                                  const float* __restrict__ x,
                                                  const float* __restrict__ lng,
                                                  const float* __restrict__ lnb,
                                                  float* __restrict__ out) {
    __shared__ float sAct[16 * HID];     // 32 KB
    __shared__ float smu[16], srs[16];
    int tid = threadIdx.x;               // 128; tid = output column
    int r0 = blockIdx.x * 16;

    const uint4* actp = (const uint4*)&g_act16[(size_t)r0 * HID];
#pragma unroll
    for (int p = 0; p < 8; p++) {
        int idx = tid + p * 128;         // 1024 x (8 halves)
        uint4 v = actp[idx];
        float* d = &sAct[idx * 8];
        float2 f0 = __half22float2(*(__half2*)&v.x);
        float2 f1 = __half22float2(*(__half2*)&v.y);
        float2 f2 = __half22float2(*(__half2*)&v.z);
        float2 f3 = __half22float2(*(__half2*)&v.w);
        d[0] = f0.x; d[1] = f0.y; d[2] = f1.x; d[3] = f1.y;
        d[4] = f2.x; d[5] = f2.y; d[6] = f3.x; d[7] = f3.y;
    }
    __syncthreads();

    float acc[16];
#pragma unroll
    for (int r = 0; r < 16; r++) acc[r] = 0.f;

#pragma unroll 2
    for (int k = 0; k < HID; k += 4) {
        float w0 = proj_w[(k + 0) * OUT_CH + tid];
        float w1 = proj_w[(k + 1) * OUT_CH + tid];
        float w2 = proj_w[(k + 2) * OUT_CH + tid];
        float w3 = proj_w[(k + 3) * OUT_CH + tid];
#pragma unroll
        for (int r = 0; r < 16; r++) {
            float4 a = *(const float4*)&sAct[r * HID + k];
            acc[r] += a.x * w0 + a.y * w1 + a.z * w2 + a.w * w3;
        }
    }

    float pb = proj_b[tid], gg = lng[tid], bb = lnb[tid];
    float yv[16];
#pragma unroll
    for (int r = 0; r < 16; r++)
        yv[r] = acc[r] + pb + x[(size_t)(r0 + r) * OUT_CH + tid];

    __syncthreads();
#pragma unroll
    for (int r = 0; r < 16; r++) sAct[r * 128 + tid] = yv[r];
    __syncthreads();

    int warp = tid >> 5, lane = tid & 31;
    for (int q = 0; q < 4; q++) {
        int r = warp * 4 + q;
        float s1 = 0.f, s2 = 0.f;
        for (int j = lane; j < 128; j += 32) {
            float v = sAct[r * 128 + j];
            s1 += v; s2 += v * v;
        }
#pragma unroll
        for (int o = 16; o; o >>= 1) {
            s1 += __shfl_xor_sync(0xffffffffu, s1, o);
            s2 += __shfl_xor_sync(0xffffffffu, s2, o);
        }
        if (lane == 0) {
            float mu = s1 * (1.f / 128.f);
            smu[r] = mu;
            srs[r] = rsqrtf(s2 * (1.f / 128.f) - mu * mu + LN_EPS);
        }
    }
    __syncthreads();
#pragma unroll
    for (int r = 0; r < 16; r++) {
        float o = (yv[r] - smu[r]) * srs[r] * gg + bb;
        out[(size_t)(r0 + r) * OUT_CH + tid] = o;
    }
}

// ---------------- launch ----------------
extern "C" void kernel_launch(void* const* d_in, const int* in_sizes, int n_in,
                              void* d_out, int out_size) {
    const float* x        = (const float*)d_in[0];
    const void*  ei       = d_in[1];
    const float* lin_w    = (const float*)d_in[2];
    const float* att_src  = (const float*)d_in[3];
    const float* att_dst  = (const float*)d_in[4];
    const float* gat_bias = (const float*)d_in[5];
    const float* proj_w   = (const float*)d_in[6];
    const float* proj_b   = (const float*)d_in[7];
    const float* ln_g     = (const float*)d_in[8];
    const float* ln_b     = (const float*)d_in[9];
    float* out = (float*)d_out;

    detect_k<<<1, 32>>>(ei);
    init_cnt_k<<<(N_NODES + 255) / 256, 256>>>();
    convert_hist_k<<<(N_EDGES + 255) / 256, 256>>>(ei);
    partial_k<<<NPART, SCAN_BLK>>>();
    scanpart_k<<<1, 256>>>();
    offsets_k<<<NPART, SCAN_BLK>>>();
    selfloop_k<<<(N_NODES + 255) / 256, 256>>>();
    scatter_k<<<(N_EDGES + 255) / 256, 256>>>();

    gemm1_k<<<dim3(HID / 64, (N_NODES + 63) / 64), 256>>>(x, lin_w);
    attn_k<<<N_NODES, 128>>>(att_src, att_dst);
    agg_k<<<N_NODES, 128>>>(gat_bias);
    gemm2_ln_k<<<N_NODES / 16, 128>>>(proj_w, proj_b, x, ln_g, ln_b, out);
}

// round 7
// speedup vs baseline: 2.0513x; 1.4818x over previous
#include <cuda_runtime.h>
#include <cuda_fp16.h>
#include <cstdint>

#define N_NODES 50000
#define N_EDGES 800000
#define TOT_ADJ (N_EDGES + N_NODES)
#define HID 512           // HEADS*OUT_CH
#define IN_CH 128
#define OUT_CH 128
#define HEADS 4
#define NEG_SLOPE 0.2f
#define LN_EPS 1e-5f
#define CAP 256
#define SCAN_BLK 256
#define NPART ((N_NODES + SCAN_BLK - 1) / SCAN_BLK)   // 196

// ---------------- device scratch (static, no allocation) ----------------
__device__ __half g_h16[(size_t)N_NODES * HID];    // h  (fp16, 51 MB, ~L2-resident)
__device__ __half g_act16[(size_t)N_NODES * HID];  // relu(agg + gat_bias) fp16
__device__ float g_asrc[N_NODES * HEADS];
__device__ float g_adst[N_NODES * HEADS];
__device__ int   g_src[N_EDGES];
__device__ int   g_dst[N_EDGES];
__device__ int   g_cnt[N_NODES];
__device__ int   g_cur[N_NODES];
__device__ int   g_off[N_NODES + 1];
__device__ int   g_adj[TOT_ADJ];
__device__ int   g_part[NPART];
__device__ int   g_is64;

__device__ __forceinline__ uint32_t f2tf32(float f) {
    uint32_t r;
    asm("cvt.rna.tf32.f32 %0, %1;" : "=r"(r) : "f"(f));
    return r;
}

// ---------------- dtype probe: edge_index int32 vs int64 ----------------
__global__ void detect_k(const void* ei) {
    if (threadIdx.x != 0) return;
    const long long* p = (const long long*)ei;
    int ok = 1;
    for (int i = 0; i < 4096; i += 7) {
        long long v = p[i];
        if (v < 0 || v >= N_NODES) { ok = 0; break; }
    }
    g_is64 = ok;
}

__global__ void init_cnt_k() {
    int i = blockIdx.x * blockDim.x + threadIdx.x;
    if (i < N_NODES) g_cnt[i] = 1;   // self loop
}

__global__ void convert_hist_k(const void* ei) {
    int i = blockIdx.x * blockDim.x + threadIdx.x;
    if (i >= N_EDGES) return;
    int s, d;
    if (g_is64) {
        const long long* p = (const long long*)ei;
        s = (int)p[i];
        d = (int)p[N_EDGES + i];
    } else {
        const int* p = (const int*)ei;
        s = p[i];
        d = p[N_EDGES + i];
    }
    g_src[i] = s;
    g_dst[i] = d;
    atomicAdd(&g_cnt[d], 1);
}

// ---------------- multi-block exclusive scan of g_cnt -> g_off ----------
__global__ void partial_k() {
    __shared__ int sd[SCAN_BLK];
    int i = blockIdx.x * SCAN_BLK + threadIdx.x;
    sd[threadIdx.x] = (i < N_NODES) ? g_cnt[i] : 0;
    __syncthreads();
    for (int st = SCAN_BLK / 2; st; st >>= 1) {
        if (threadIdx.x < st) sd[threadIdx.x] += sd[threadIdx.x + st];
        __syncthreads();
    }
    if (threadIdx.x == 0) g_part[blockIdx.x] = sd[0];
}

__global__ void scanpart_k() {
    __shared__ int sp[256];
    int t = threadIdx.x;
    int own = (t < NPART) ? g_part[t] : 0;
    sp[t] = own;
    __syncthreads();
    for (int st = 1; st < 256; st <<= 1) {
        int v = (t >= st) ? sp[t - st] : 0;
        __syncthreads();
        sp[t] += v;
        __syncthreads();
    }
    if (t < NPART) g_part[t] = sp[t] - own;     // exclusive
    if (t == 255) g_off[N_NODES] = sp[255];     // total
}

// offsets + self-loop seed fused
__global__ void offsets_k() {
    __shared__ int sd[SCAN_BLK];
    int i = blockIdx.x * SCAN_BLK + threadIdx.x;
    int own = (i < N_NODES) ? g_cnt[i] : 0;
    sd[threadIdx.x] = own;
    __syncthreads();
    for (int st = 1; st < SCAN_BLK; st <<= 1) {
        int v = (threadIdx.x >= st) ? sd[threadIdx.x - st] : 0;
        __syncthreads();
        sd[threadIdx.x] += v;
        __syncthreads();
    }
    if (i < N_NODES) {
        int off = g_part[blockIdx.x] + sd[threadIdx.x] - own;
        g_off[i] = off;
        g_adj[off] = i;     // self loop first
        g_cur[i] = 1;
    }
}

__global__ void scatter_k() {
    int i = blockIdx.x * blockDim.x + threadIdx.x;
    if (i >= N_EDGES) return;
    int d = g_dst[i];
    int pos = g_off[d] + atomicAdd(&g_cur[d], 1);
    g_adj[pos] = g_src[i];
}

// ---------------- GEMM1: h = x @ lin_w, tf32 mma, fp16 out --------------
__global__ __launch_bounds__(256) void gemm1_k(const float* __restrict__ x,
                                               const float* __restrict__ w) {
    __shared__ uint32_t sA[64 * 132];   // 33 KB, full K=128
    __shared__ uint32_t sB[32 * 72];    // 9 KB, one 32-row K chunk
    int tid = threadIdx.x;
    int lane = tid & 31, wid = tid >> 5;
    int warp_m = wid & 3, warp_n = wid >> 2;
    int m0 = blockIdx.y * 64;
    int n0 = blockIdx.x * 64;

#pragma unroll
    for (int p = 0; p < 8; p++) {
        int idx = tid + p * 256;
        int row = idx >> 5, c4 = (idx & 31) * 4;
        int gr = m0 + row;
        float4 v = (gr < N_NODES) ? *(const float4*)&x[(size_t)gr * 128 + c4]
                                  : make_float4(0.f, 0.f, 0.f, 0.f);
        uint32_t* d = &sA[row * 132 + c4];
        d[0] = f2tf32(v.x); d[1] = f2tf32(v.y);
        d[2] = f2tf32(v.z); d[3] = f2tf32(v.w);
    }

    float c[4][4];
#pragma unroll
    for (int nt = 0; nt < 4; nt++)
#pragma unroll
        for (int r = 0; r < 4; r++) c[nt][r] = 0.f;

    int aRow = warp_m * 16 + (lane >> 2);
    int kq = lane & 3;

    for (int kc = 0; kc < 128; kc += 32) {
        __syncthreads();
#pragma unroll
        for (int p = 0; p < 2; p++) {
            int idx = tid + p * 256;
            int kr = idx >> 4, c4 = (idx & 15) * 4;
            float4 v = *(const float4*)&w[(size_t)(kc + kr) * HID + n0 + c4];
            uint32_t* d = &sB[kr * 72 + c4];
            d[0] = f2tf32(v.x); d[1] = f2tf32(v.y);
            d[2] = f2tf32(v.z); d[3] = f2tf32(v.w);
        }
        __syncthreads();

#pragma unroll
        for (int ks = 0; ks < 32; ks += 8) {
            uint32_t a0 = sA[aRow * 132 + kc + ks + kq];
            uint32_t a1 = sA[(aRow + 8) * 132 + kc + ks + kq];
            uint32_t a2 = sA[aRow * 132 + kc + ks + kq + 4];
            uint32_t a3 = sA[(aRow + 8) * 132 + kc + ks + kq + 4];
#pragma unroll
            for (int nt = 0; nt < 4; nt++) {
                int nb = warp_n * 32 + nt * 8 + (lane >> 2);
                uint32_t b0 = sB[(ks + kq) * 72 + nb];
                uint32_t b1 = sB[(ks + kq + 4) * 72 + nb];
                asm volatile(
                    "mma.sync.aligned.m16n8k8.row.col.f32.tf32.tf32.f32 "
                    "{%0,%1,%2,%3}, {%4,%5,%6,%7}, {%8,%9}, {%0,%1,%2,%3};"
                    : "+f"(c[nt][0]), "+f"(c[nt][1]), "+f"(c[nt][2]), "+f"(c[nt][3])
                    : "r"(a0), "r"(a1), "r"(a2), "r"(a3), "r"(b0), "r"(b1));
            }
        }
    }

    int rowA = m0 + warp_m * 16 + (lane >> 2);
    int colB = n0 + warp_n * 32 + (lane & 3) * 2;
#pragma unroll
    for (int nt = 0; nt < 4; nt++) {
        int col = colB + nt * 8;
        if (rowA < N_NODES)
            *(__half2*)&g_h16[(size_t)rowA * HID + col] =
                __floats2half2_rn(c[nt][0], c[nt][1]);
        if (rowA + 8 < N_NODES)
            *(__half2*)&g_h16[(size_t)(rowA + 8) * HID + col] =
                __floats2half2_rn(c[nt][2], c[nt][3]);
    }
}

// ---------------- attention coefficients (fp16 h, fp32 math) -------------
__global__ __launch_bounds__(128) void attn_k(const float* __restrict__ att_src,
                                              const float* __restrict__ att_dst) {
    int node = blockIdx.x;
    int w = threadIdx.x >> 5;   // = head
    int lane = threadIdx.x & 31;
    const __half2* hp = (const __half2*)&g_h16[(size_t)node * HID + w * 128 + lane * 4];
    __half2 p0 = hp[0], p1 = hp[1];
    float2 v0 = __half22float2(p0), v1 = __half22float2(p1);
    float4 a = *(const float4*)&att_src[w * 128 + lane * 4];
    float4 b = *(const float4*)&att_dst[w * 128 + lane * 4];
    float ds = v0.x * a.x + v0.y * a.y + v1.x * a.z + v1.y * a.w;
    float dd = v0.x * b.x + v0.y * b.y + v1.x * b.z + v1.y * b.w;
#pragma unroll
    for (int o = 16; o; o >>= 1) {
        ds += __shfl_xor_sync(0xffffffffu, ds, o);
        dd += __shfl_xor_sync(0xffffffffu, dd, o);
    }
    if (lane == 0) {
        g_asrc[node * HEADS + w] = ds;
        g_adst[node * HEADS + w] = dd;
    }
}

// ---------------- per-node softmax + weighted aggregation ----------------
__device__ __forceinline__ float leaky(float e) { return e > 0.f ? e : NEG_SLOPE * e; }

__global__ __launch_bounds__(128) void agg_k(const float* __restrict__ gat_bias) {
    __shared__ int   sadj[CAP];
    __shared__ float se[HEADS][CAP];
    int d = blockIdx.x;
    int tid = threadIdx.x;
    int w = tid >> 5;            // warp = head
    int lane = tid & 31;
    int beg = g_off[d];
    int deg = g_off[d + 1] - beg;
    float adh = g_adst[d * HEADS + w];

    float mx = -1e30f, sum = 0.f, inv;
    bool cached = (deg <= CAP);

    if (cached) {
        for (int i = lane; i < deg; i += 32) {
            int s = g_adj[beg + i];
            if (w == 0) sadj[i] = s;
            float e = leaky(g_asrc[s * HEADS + w] + adh);
            se[w][i] = e;
            mx = fmaxf(mx, e);
        }
#pragma unroll
        for (int o = 16; o; o >>= 1) mx = fmaxf(mx, __shfl_xor_sync(0xffffffffu, mx, o));
        for (int i = lane; i < deg; i += 32) {
            float a = __expf(se[w][i] - mx);
            se[w][i] = a;
            sum += a;
        }
#pragma unroll
        for (int o = 16; o; o >>= 1) sum += __shfl_xor_sync(0xffffffffu, sum, o);
        inv = 1.f / (sum + 1e-16f);
        __syncthreads();
    } else {
        for (int i = lane; i < deg; i += 32) {
            int s = g_adj[beg + i];
            mx = fmaxf(mx, leaky(g_asrc[s * HEADS + w] + adh));
        }
#pragma unroll
        for (int o = 16; o; o >>= 1) mx = fmaxf(mx, __shfl_xor_sync(0xffffffffu, mx, o));
        for (int i = lane; i < deg; i += 32) {
            int s = g_adj[beg + i];
            sum += __expf(leaky(g_asrc[s * HEADS + w] + adh) - mx);
        }
#pragma unroll
        for (int o = 16; o; o >>= 1) sum += __shfl_xor_sync(0xffffffffu, sum, o);
        inv = 1.f / (sum + 1e-16f);
        __syncthreads();
    }

    float4 acc = make_float4(0.f, 0.f, 0.f, 0.f);
    float4 acc2 = make_float4(0.f, 0.f, 0.f, 0.f);
    if (cached) {
        int i = 0;
        for (; i + 3 < deg; i += 4) {
            float al0 = se[w][i] * inv,     al1 = se[w][i + 1] * inv;
            float al2 = se[w][i + 2] * inv, al3 = se[w][i + 3] * inv;
            uint2 v0 = *(const uint2*)&g_h16[(size_t)sadj[i]     * HID + 4 * tid];
            uint2 v1 = *(const uint2*)&g_h16[(size_t)sadj[i + 1] * HID + 4 * tid];
            uint2 v2 = *(const uint2*)&g_h16[(size_t)sadj[i + 2] * HID + 4 * tid];
            uint2 v3 = *(const uint2*)&g_h16[(size_t)sadj[i + 3] * HID + 4 * tid];
            float2 f0a = __half22float2(*(__half2*)&v0.x), f0b = __half22float2(*(__half2*)&v0.y);
            float2 f1a = __half22float2(*(__half2*)&v1.x), f1b = __half22float2(*(__half2*)&v1.y);
            float2 f2a = __half22float2(*(__half2*)&v2.x), f2b = __half22float2(*(__half2*)&v2.y);
            float2 f3a = __half22float2(*(__half2*)&v3.x), f3b = __half22float2(*(__half2*)&v3.y);
            acc.x  += f0a.x * al0; acc.y  += f0a.y * al0; acc.z  += f0b.x * al0; acc.w  += f0b.y * al0;
            acc2.x += f1a.x * al1; acc2.y += f1a.y * al1; acc2.z += f1b.x * al1; acc2.w += f1b.y * al1;
            acc.x  += f2a.x * al2; acc.y  += f2a.y * al2; acc.z  += f2b.x * al2; acc.w  += f2b.y * al2;
            acc2.x += f3a.x * al3; acc2.y += f3a.y * al3; acc2.z += f3b.x * al3; acc2.w += f3b.y * al3;
        }
        for (; i < deg; i++) {
            float al = se[w][i] * inv;
            uint2 v = *(const uint2*)&g_h16[(size_t)sadj[i] * HID + 4 * tid];
            float2 fa = __half22float2(*(__half2*)&v.x), fb = __half22float2(*(__half2*)&v.y);
            acc.x += fa.x * al; acc.y += fa.y * al;
            acc.z += fb.x * al; acc.w += fb.y * al;
        }
    } else {
        for (int i = 0; i < deg; i++) {
            int s = g_adj[beg + i];
            float e = leaky(g_asrc[s * HEADS + w] + adh);
            float al = __expf(e - mx) * inv;
            uint2 v = *(const uint2*)&g_h16[(size_t)s * HID + 4 * tid];
            float2 fa = __half22float2(*(__half2*)&v.x), fb = __half22float2(*(__half2*)&v.y);
            acc.x += fa.x * al; acc.y += fa.y * al;
            acc.z += fb.x * al; acc.w += fb.y * al;
        }
    }
    acc.x += acc2.x; acc.y += acc2.y; acc.z += acc2.z; acc.w += acc2.w;

    float4 b = ((const float4*)gat_bias)[tid];
    acc.x = fmaxf(acc.x + b.x, 0.f);
    acc.y = fmaxf(acc.y + b.y, 0.f);
    acc.z = fmaxf(acc.z + b.z, 0.f);
    acc.w = fmaxf(acc.w + b.w, 0.f);
    uint2 st;
    *(__half2*)&st.x = __floats2half2_rn(acc.x, acc.y);
    *(__half2*)&st.y = __floats2half2_rn(acc.z, acc.w);
    *(uint2*)&g_act16[(size_t)d * HID + 4 * tid] = st;
}

// ------- GEMM2 (tf32 mma) + bias + residual + LayerNorm, fused ----------
// 64x128 output tile / block, 256 thr = 8 warps (4 M x 2 N). K=512 in 32-chunks.
// smem: mainloop sA(64x36)+sB(32x136) = 26 KB; epilogue sY(64x132) = 33 KB aliased.
__global__ __launch_bounds__(256) void gemm2_ln_k(const float* __restrict__ proj_w,
                                                  const float* __restrict__ proj_b,
                                                  const float* __restrict__ x,
                                                  const float* __restrict__ lng,
                                                  const float* __restrict__ lnb,
                                                  float* __restrict__ out) {
    __shared__ uint32_t buf[64 * 132];      // 33 KB, aliased
    uint32_t* sA = buf;                     // 64 x 36
    uint32_t* sB = buf + 64 * 36;           // 32 x 136
    float* sY = (float*)buf;                // 64 x 132 (epilogue)
    int tid = threadIdx.x;
    int lane = tid & 31, wid = tid >> 5;
    int warp_m = wid & 3, warp_n = wid >> 2;
    int m0 = blockIdx.x * 64;

    float c[8][4];
#pragma unroll
    for (int nt = 0; nt < 8; nt++)
#pragma unroll
        for (int r = 0; r < 4; r++) c[nt][r] = 0.f;

    int aRow = warp_m * 16 + (lane >> 2);
    int kq = lane & 3;

    for (int kc = 0; kc < HID; kc += 32) {
        __syncthreads();
        // sA: 64 rows x 32 halves of g_act16 -> tf32
#pragma unroll
        for (int p = 0; p < 2; p++) {
            int idx = tid + p * 256;          // 512 uint2
            int row = idx >> 3, c4 = (idx & 7) * 4;
            int gr = m0 + row;
            uint2 v = (gr < N_NODES)
                ? *(const uint2*)&g_act16[(size_t)gr * HID + kc + c4]
                : make_uint2(0u, 0u);
            float2 f0 = __half22float2(*(__half2*)&v.x);
            float2 f1 = __half22float2(*(__half2*)&v.y);
            uint32_t* dd = &sA[row * 36 + c4];
            dd[0] = f2tf32(f0.x); dd[1] = f2tf32(f0.y);
            dd[2] = f2tf32(f1.x); dd[3] = f2tf32(f1.y);
        }
        // sB: 32 k x 128 n of proj_w -> tf32
#pragma unroll
        for (int p = 0; p < 4; p++) {
            int idx = tid + p * 256;          // 1024 float4
            int kr = idx >> 5, c4 = (idx & 31) * 4;
            float4 v = *(const float4*)&proj_w[(size_t)(kc + kr) * OUT_CH + c4];
            uint32_t* dd = &sB[kr * 136 + c4];
            dd[0] = f2tf32(v.x); dd[1] = f2tf32(v.y);
            dd[2] = f2tf32(v.z); dd[3] = f2tf32(v.w);
        }
        __syncthreads();

#pragma unroll
        for (int ks = 0; ks < 32; ks += 8) {
            uint32_t a0 = sA[aRow * 36 + ks + kq];
            uint32_t a1 = sA[(aRow + 8) * 36 + ks + kq];
            uint32_t a2 = sA[aRow * 36 + ks + kq + 4];
            uint32_t a3 = sA[(aRow + 8) * 36 + ks + kq + 4];
#pragma unroll
            for (int nt = 0; nt < 8; nt++) {
                int nb = warp_n * 64 + nt * 8 + (lane >> 2);
                uint32_t b0 = sB[(ks + kq) * 136 + nb];
                uint32_t b1 = sB[(ks + kq + 4) * 136 + nb];
                asm volatile(
                    "mma.sync.aligned.m16n8k8.row.col.f32.tf32.tf32.f32 "
                    "{%0,%1,%2,%3}, {%4,%5,%6,%7}, {%8,%9}, {%0,%1,%2,%3};"
                    : "+f"(c[nt][0]), "+f"(c[nt][1]), "+f"(c[nt][2]), "+f"(c[nt][3])
                    : "r"(a0), "r"(a1), "r"(a2), "r"(a3), "r"(b0), "r"(b1));
            }
        }
    }
    __syncthreads();   // mainloop buffers dead; reuse as sY

    // epilogue: y = c + proj_b + x  -> sY
    int lr = warp_m * 16 + (lane >> 2);
#pragma unroll
    for (int nt = 0; nt < 8; nt++) {
        int col = warp_n * 64 + nt * 8 + (lane & 3) * 2;
        int gr0 = m0 + lr, gr1 = gr0 + 8;
        float pb0 = proj_b[col], pb1 = proj_b[col + 1];
        float x00 = 0.f, x01 = 0.f, x10 = 0.f, x11 = 0.f;
        if (gr0 < N_NODES) {
            x00 = x[(size_t)gr0 * OUT_CH + col];
            x01 = x[(size_t)gr0 * OUT_CH + col + 1];
        }
        if (gr1 < N_NODES) {
            x10 = x[(size_t)gr1 * OUT_CH + col];
            x11 = x[(size_t)gr1 * OUT_CH + col + 1];
        }
        sY[lr * 132 + col]           = c[nt][0] + pb0 + x00;
        sY[lr * 132 + col + 1]       = c[nt][1] + pb1 + x01;
        sY[(lr + 8) * 132 + col]     = c[nt][2] + pb0 + x10;
        sY[(lr + 8) * 132 + col + 1] = c[nt][3] + pb1 + x11;
    }
    __syncthreads();

    // LayerNorm: warp wid handles local rows [wid*8, wid*8+8)
    float gg[4], bb[4];
#pragma unroll
    for (int q = 0; q < 4; q++) {
        gg[q] = lng[lane + q * 32];
        bb[q] = lnb[lane + q * 32];
    }
#pragma unroll
    for (int q = 0; q < 8; q++) {
        int r = wid * 8 + q;
        int gr = m0 + r;
        float v0 = sY[r * 132 + lane];
        float v1 = sY[r * 132 + lane + 32];
        float v2 = sY[r * 132 + lane + 64];
        float v3 = sY[r * 132 + lane + 96];
        float s1 = v0 + v1 + v2 + v3;
        float s2 = v0 * v0 + v1 * v1 + v2 * v2 + v3 * v3;
#pragma unroll
        for (int o = 16; o; o >>= 1) {
            s1 += __shfl_xor_sync(0xffffffffu, s1, o);
            s2 += __shfl_xor_sync(0xffffffffu, s2, o);
        }
        float mu = s1 * (1.f / 128.f);
        float rs = rsqrtf(s2 * (1.f / 128.f) - mu * mu + LN_EPS);
        if (gr < N_NODES) {
            out[(size_t)gr * OUT_CH + lane]      = (v0 - mu) * rs * gg[0] + bb[0];
            out[(size_t)gr * OUT_CH + lane + 32] = (v1 - mu) * rs * gg[1] + bb[1];
            out[(size_t)gr * OUT_CH + lane + 64] = (v2 - mu) * rs * gg[2] + bb[2];
            out[(size_t)gr * OUT_CH + lane + 96] = (v3 - mu) * rs * gg[3] + bb[3];
        }
    }
}

// ---------------- launch ----------------
extern "C" void kernel_launch(void* const* d_in, const int* in_sizes, int n_in,
                              void* d_out, int out_size) {
    const float* x        = (const float*)d_in[0];
    const void*  ei       = d_in[1];
    const float* lin_w    = (const float*)d_in[2];
    const float* att_src  = (const float*)d_in[3];
    const float* att_dst  = (const float*)d_in[4];
    const float* gat_bias = (const float*)d_in[5];
    const float* proj_w   = (const float*)d_in[6];
    const float* proj_b   = (const float*)d_in[7];
    const float* ln_g     = (const float*)d_in[8];
    const float* ln_b     = (const float*)d_in[9];
    float* out = (float*)d_out;

    detect_k<<<1, 32>>>(ei);
    init_cnt_k<<<(N_NODES + 255) / 256, 256>>>();
    convert_hist_k<<<(N_EDGES + 255) / 256, 256>>>(ei);
    partial_k<<<NPART, SCAN_BLK>>>();
    scanpart_k<<<1, 256>>>();
    offsets_k<<<NPART, SCAN_BLK>>>();
    scatter_k<<<(N_EDGES + 255) / 256, 256>>>();

    gemm1_k<<<dim3(HID / 64, (N_NODES + 63) / 64), 256>>>(x, lin_w);
    attn_k<<<N_NODES, 128>>>(att_src, att_dst);
    agg_k<<<N_NODES, 128>>>(gat_bias);
    gemm2_ln_k<<<(N_NODES + 63) / 64, 256>>>(proj_w, proj_b, x, ln_g, ln_b, out);
}

// round 8
// speedup vs baseline: 2.0524x; 1.0005x over previous
#include <cuda_runtime.h>
#include <cuda_fp16.h>
#include <cstdint>

#define N_NODES 50000
#define N_EDGES 800000
#define TOT_ADJ (N_EDGES + N_NODES)
#define HID 512           // HEADS*OUT_CH
#define IN_CH 128
#define OUT_CH 128
#define HEADS 4
#define NEG_SLOPE 0.2f
#define LN_EPS 1e-5f
#define CAP 256
#define SCAN_BLK 256
#define NPART ((N_NODES + SCAN_BLK - 1) / SCAN_BLK)   // 196

// ---------------- device scratch (static, no allocation) ----------------
__device__ __half g_h16[(size_t)N_NODES * HID];    // h  (fp16, 51 MB, ~L2-resident)
__device__ __half g_act16[(size_t)N_NODES * HID];  // relu(agg + gat_bias) fp16
__device__ float g_asrc[N_NODES * HEADS];
__device__ float g_adst[N_NODES * HEADS];
__device__ int   g_src[N_EDGES];
__device__ int   g_dst[N_EDGES];
__device__ int   g_cnt[N_NODES];
__device__ int   g_cur[N_NODES];
__device__ int   g_off[N_NODES + 1];
__device__ int   g_adj[TOT_ADJ];
__device__ int   g_part[NPART];
__device__ int   g_is64;

__device__ __forceinline__ uint32_t f2tf32(float f) {
    uint32_t r;
    asm("cvt.rna.tf32.f32 %0, %1;" : "=r"(r) : "f"(f));
    return r;
}

// ---------------- dtype probe: edge_index int32 vs int64 ----------------
__global__ void detect_k(const void* ei) {
    if (threadIdx.x != 0) return;
    const long long* p = (const long long*)ei;
    int ok = 1;
    for (int i = 0; i < 4096; i += 7) {
        long long v = p[i];
        if (v < 0 || v >= N_NODES) { ok = 0; break; }
    }
    g_is64 = ok;
}

__global__ void init_cnt_k() {
    int i = blockIdx.x * blockDim.x + threadIdx.x;
    if (i < N_NODES) g_cnt[i] = 1;   // self loop
}

__global__ void convert_hist_k(const void* ei) {
    int i = blockIdx.x * blockDim.x + threadIdx.x;
    if (i >= N_EDGES) return;
    int s, d;
    if (g_is64) {
        const long long* p = (const long long*)ei;
        s = (int)p[i];
        d = (int)p[N_EDGES + i];
    } else {
        const int* p = (const int*)ei;
        s = p[i];
        d = p[N_EDGES + i];
    }
    g_src[i] = s;
    g_dst[i] = d;
    atomicAdd(&g_cnt[d], 1);
}

// ---------------- multi-block exclusive scan of g_cnt -> g_off ----------
__global__ void partial_k() {
    __shared__ int sd[SCAN_BLK];
    int i = blockIdx.x * SCAN_BLK + threadIdx.x;
    sd[threadIdx.x] = (i < N_NODES) ? g_cnt[i] : 0;
    __syncthreads();
    for (int st = SCAN_BLK / 2; st; st >>= 1) {
        if (threadIdx.x < st) sd[threadIdx.x] += sd[threadIdx.x + st];
        __syncthreads();
    }
    if (threadIdx.x == 0) g_part[blockIdx.x] = sd[0];
}

__global__ void scanpart_k() {
    __shared__ int sp[256];
    int t = threadIdx.x;
    int own = (t < NPART) ? g_part[t] : 0;
    sp[t] = own;
    __syncthreads();
    for (int st = 1; st < 256; st <<= 1) {
        int v = (t >= st) ? sp[t - st] : 0;
        __syncthreads();
        sp[t] += v;
        __syncthreads();
    }
    if (t < NPART) g_part[t] = sp[t] - own;     // exclusive
    if (t == 255) g_off[N_NODES] = sp[255];     // total
}

// offsets + self-loop seed fused
__global__ void offsets_k() {
    __shared__ int sd[SCAN_BLK];
    int i = blockIdx.x * SCAN_BLK + threadIdx.x;
    int own = (i < N_NODES) ? g_cnt[i] : 0;
    sd[threadIdx.x] = own;
    __syncthreads();
    for (int st = 1; st < SCAN_BLK; st <<= 1) {
        int v = (threadIdx.x >= st) ? sd[threadIdx.x - st] : 0;
        __syncthreads();
        sd[threadIdx.x] += v;
        __syncthreads();
    }
    if (i < N_NODES) {
        int off = g_part[blockIdx.x] + sd[threadIdx.x] - own;
        g_off[i] = off;
        g_adj[off] = i;     // self loop first
        g_cur[i] = 1;
    }
}

__global__ void scatter_k() {
    int i = blockIdx.x * blockDim.x + threadIdx.x;
    if (i >= N_EDGES) return;
    int d = g_dst[i];
    int pos = g_off[d] + atomicAdd(&g_cur[d], 1);
    g_adj[pos] = g_src[i];
}

// ---------------- GEMM1: h = x @ lin_w, tf32 mma, fp16 out --------------
__global__ __launch_bounds__(256) void gemm1_k(const float* __restrict__ x,
                                               const float* __restrict__ w) {
    __shared__ uint32_t sA[64 * 132];   // 33 KB, full K=128
    __shared__ uint32_t sB[32 * 72];    // 9 KB, one 32-row K chunk
    int tid = threadIdx.x;
    int lane = tid & 31, wid = tid >> 5;
    int warp_m = wid & 3, warp_n = wid >> 2;
    int m0 = blockIdx.y * 64;
    int n0 = blockIdx.x * 64;

#pragma unroll
    for (int p = 0; p < 8; p++) {
        int idx = tid + p * 256;
        int row = idx >> 5, c4 = (idx & 31) * 4;
        int gr = m0 + row;
        float4 v = (gr < N_NODES) ? *(const float4*)&x[(size_t)gr * 128 + c4]
                                  : make_float4(0.f, 0.f, 0.f, 0.f);
        uint32_t* d = &sA[row * 132 + c4];
        d[0] = f2tf32(v.x); d[1] = f2tf32(v.y);
        d[2] = f2tf32(v.z); d[3] = f2tf32(v.w);
    }

    float c[4][4];
#pragma unroll
    for (int nt = 0; nt < 4; nt++)
#pragma unroll
        for (int r = 0; r < 4; r++) c[nt][r] = 0.f;

    int aRow = warp_m * 16 + (lane >> 2);
    int kq = lane & 3;

    for (int kc = 0; kc < 128; kc += 32) {
        __syncthreads();
#pragma unroll
        for (int p = 0; p < 2; p++) {
            int idx = tid + p * 256;
            int kr = idx >> 4, c4 = (idx & 15) * 4;
            float4 v = *(const float4*)&w[(size_t)(kc + kr) * HID + n0 + c4];
            uint32_t* d = &sB[kr * 72 + c4];
            d[0] = f2tf32(v.x); d[1] = f2tf32(v.y);
            d[2] = f2tf32(v.z); d[3] = f2tf32(v.w);
        }
        __syncthreads();

#pragma unroll
        for (int ks = 0; ks < 32; ks += 8) {
            uint32_t a0 = sA[aRow * 132 + kc + ks + kq];
            uint32_t a1 = sA[(aRow + 8) * 132 + kc + ks + kq];
            uint32_t a2 = sA[aRow * 132 + kc + ks + kq + 4];
            uint32_t a3 = sA[(aRow + 8) * 132 + kc + ks + kq + 4];
#pragma unroll
            for (int nt = 0; nt < 4; nt++) {
                int nb = warp_n * 32 + nt * 8 + (lane >> 2);
                uint32_t b0 = sB[(ks + kq) * 72 + nb];
                uint32_t b1 = sB[(ks + kq + 4) * 72 + nb];
                asm volatile(
                    "mma.sync.aligned.m16n8k8.row.col.f32.tf32.tf32.f32 "
                    "{%0,%1,%2,%3}, {%4,%5,%6,%7}, {%8,%9}, {%0,%1,%2,%3};"
                    : "+f"(c[nt][0]), "+f"(c[nt][1]), "+f"(c[nt][2]), "+f"(c[nt][3])
                    : "r"(a0), "r"(a1), "r"(a2), "r"(a3), "r"(b0), "r"(b1));
            }
        }
    }

    int rowA = m0 + warp_m * 16 + (lane >> 2);
    int colB = n0 + warp_n * 32 + (lane & 3) * 2;
#pragma unroll
    for (int nt = 0; nt < 4; nt++) {
        int col = colB + nt * 8;
        if (rowA < N_NODES)
            *(__half2*)&g_h16[(size_t)rowA * HID + col] =
                __floats2half2_rn(c[nt][0], c[nt][1]);
        if (rowA + 8 < N_NODES)
            *(__half2*)&g_h16[(size_t)(rowA + 8) * HID + col] =
                __floats2half2_rn(c[nt][2], c[nt][3]);
    }
}

// ---------------- attention coefficients (fp16 h, fp32 math) -------------
__global__ __launch_bounds__(128) void attn_k(const float* __restrict__ att_src,
                                              const float* __restrict__ att_dst) {
    int node = blockIdx.x;
    int w = threadIdx.x >> 5;   // = head
    int lane = threadIdx.x & 31;
    const __half2* hp = (const __half2*)&g_h16[(size_t)node * HID + w * 128 + lane * 4];
    __half2 p0 = hp[0], p1 = hp[1];
    float2 v0 = __half22float2(p0), v1 = __half22float2(p1);
    float4 a = *(const float4*)&att_src[w * 128 + lane * 4];
    float4 b = *(const float4*)&att_dst[w * 128 + lane * 4];
    float ds = v0.x * a.x + v0.y * a.y + v1.x * a.z + v1.y * a.w;
    float dd = v0.x * b.x + v0.y * b.y + v1.x * b.z + v1.y * b.w;
#pragma unroll
    for (int o = 16; o; o >>= 1) {
        ds += __shfl_xor_sync(0xffffffffu, ds, o);
        dd += __shfl_xor_sync(0xffffffffu, dd, o);
    }
    if (lane == 0) {
        g_asrc[node * HEADS + w] = ds;
        g_adst[node * HEADS + w] = dd;
    }
}

// ---------------- per-node softmax + weighted aggregation ----------------
// Softmax: warp-per-head. Gather: 2 edge-groups x 64 threads, 8 ch (16B) per
// thread per edge, combined through smem at the end.
__device__ __forceinline__ float leaky(float e) { return e > 0.f ? e : NEG_SLOPE * e; }

__device__ __forceinline__ void acc8(float* acc, uint4 v, float al) {
    float2 f0 = __half22float2(*(__half2*)&v.x);
    float2 f1 = __half22float2(*(__half2*)&v.y);
    float2 f2 = __half22float2(*(__half2*)&v.z);
    float2 f3 = __half22float2(*(__half2*)&v.w);
    acc[0] += f0.x * al; acc[1] += f0.y * al;
    acc[2] += f1.x * al; acc[3] += f1.y * al;
    acc[4] += f2.x * al; acc[5] += f2.y * al;
    acc[6] += f3.x * al; acc[7] += f3.y * al;
}

__global__ __launch_bounds__(128) void agg_k(const float* __restrict__ gat_bias) {
    __shared__ int   sadj[CAP];
    __shared__ float se[HEADS][CAP];
    __shared__ float sinv[HEADS], smx[HEADS], sadh[HEADS];
    __shared__ float sacc[64][9];     // group-1 partials, pad 9 (odd) = conflict-free
    int d = blockIdx.x;
    int tid = threadIdx.x;
    int w = tid >> 5;            // warp = head (softmax phase)
    int lane = tid & 31;
    int beg = g_off[d];
    int deg = g_off[d + 1] - beg;
    float adh = g_adst[d * HEADS + w];
    bool cached = (deg <= CAP);

    float mx = -1e30f, sum = 0.f;
    if (cached) {
        for (int i = lane; i < deg; i += 32) {
            int s = g_adj[beg + i];
            if (w == 0) sadj[i] = s;
            float e = leaky(g_asrc[s * HEADS + w] + adh);
            se[w][i] = e;
            mx = fmaxf(mx, e);
        }
#pragma unroll
        for (int o = 16; o; o >>= 1) mx = fmaxf(mx, __shfl_xor_sync(0xffffffffu, mx, o));
        for (int i = lane; i < deg; i += 32) {
            float a = __expf(se[w][i] - mx);
            se[w][i] = a;
            sum += a;
        }
#pragma unroll
        for (int o = 16; o; o >>= 1) sum += __shfl_xor_sync(0xffffffffu, sum, o);
    } else {
        for (int i = lane; i < deg; i += 32) {
            int s = g_adj[beg + i];
            mx = fmaxf(mx, leaky(g_asrc[s * HEADS + w] + adh));
        }
#pragma unroll
        for (int o = 16; o; o >>= 1) mx = fmaxf(mx, __shfl_xor_sync(0xffffffffu, mx, o));
        for (int i = lane; i < deg; i += 32) {
            int s = g_adj[beg + i];
            sum += __expf(leaky(g_asrc[s * HEADS + w] + adh) - mx);
        }
#pragma unroll
        for (int o = 16; o; o >>= 1) sum += __shfl_xor_sync(0xffffffffu, sum, o);
    }
    if (lane == 0) {
        sinv[w] = 1.f / (sum + 1e-16f);
        smx[w] = mx;
        sadh[w] = adh;
    }
    __syncthreads();

    // ---- gather phase: remap to 2 groups x 64 threads, 8 ch / thread ----
    int g = tid >> 6;            // edge-parity group
    int t6 = tid & 63;
    int ch = t6 * 8;
    int head = t6 >> 4;
    float inv = sinv[head];
    float acc[8] = {0.f, 0.f, 0.f, 0.f, 0.f, 0.f, 0.f, 0.f};
    const __half* hbase = g_h16;

    if (cached) {
        int i = g;
        for (; i + 6 < deg; i += 8) {
            float al0 = se[head][i] * inv;
            float al1 = se[head][i + 2] * inv;
            float al2 = se[head][i + 4] * inv;
            float al3 = se[head][i + 6] * inv;
            uint4 v0 = *(const uint4*)&hbase[(size_t)sadj[i]     * HID + ch];
            uint4 v1 = *(const uint4*)&hbase[(size_t)sadj[i + 2] * HID + ch];
            uint4 v2 = *(const uint4*)&hbase[(size_t)sadj[i + 4] * HID + ch];
            uint4 v3 = *(const uint4*)&hbase[(size_t)sadj[i + 6] * HID + ch];
            acc8(acc, v0, al0);
            acc8(acc, v1, al1);
            acc8(acc, v2, al2);
            acc8(acc, v3, al3);
        }
        for (; i < deg; i += 2) {
            float al = se[head][i] * inv;
            uint4 v = *(const uint4*)&hbase[(size_t)sadj[i] * HID + ch];
            acc8(acc, v, al);
        }
    } else {
        float mxh = smx[head], adhh = sadh[head];
        for (int i = g; i < deg; i += 2) {
            int s = g_adj[beg + i];
            float al = __expf(leaky(g_asrc[s * HEADS + head] + adhh) - mxh) * inv;
            uint4 v = *(const uint4*)&hbase[(size_t)s * HID + ch];
            acc8(acc, v, al);
        }
    }

    if (g == 1) {
#pragma unroll
        for (int j = 0; j < 8; j++) sacc[t6][j] = acc[j];
    }
    __syncthreads();
    if (g == 0) {
        float4 b0 = *(const float4*)&gat_bias[ch];
        float4 b1 = *(const float4*)&gat_bias[ch + 4];
        float r0 = fmaxf(acc[0] + sacc[t6][0] + b0.x, 0.f);
        float r1 = fmaxf(acc[1] + sacc[t6][1] + b0.y, 0.f);
        float r2 = fmaxf(acc[2] + sacc[t6][2] + b0.z, 0.f);
        float r3 = fmaxf(acc[3] + sacc[t6][3] + b0.w, 0.f);
        float r4 = fmaxf(acc[4] + sacc[t6][4] + b1.x, 0.f);
        float r5 = fmaxf(acc[5] + sacc[t6][5] + b1.y, 0.f);
        float r6 = fmaxf(acc[6] + sacc[t6][6] + b1.z, 0.f);
        float r7 = fmaxf(acc[7] + sacc[t6][7] + b1.w, 0.f);
        uint4 st;
        *(__half2*)&st.x = __floats2half2_rn(r0, r1);
        *(__half2*)&st.y = __floats2half2_rn(r2, r3);
        *(__half2*)&st.z = __floats2half2_rn(r4, r5);
        *(__half2*)&st.w = __floats2half2_rn(r6, r7);
        *(uint4*)&g_act16[(size_t)d * HID + ch] = st;
    }
}

// ------- GEMM2 (tf32 mma) + bias + residual + LayerNorm, fused ----------
__global__ __launch_bounds__(256) void gemm2_ln_k(const float* __restrict__ proj_w,
                                                  const float* __restrict__ proj_b,
                                                  const float* __restrict__ x,
                                                  const float* __restrict__ lng,
                                                  const float* __restrict__ lnb,
                                                  float* __restrict__ out) {
    __shared__ uint32_t buf[64 * 132];      // 33 KB, aliased
    uint32_t* sA = buf;                     // 64 x 36
    uint32_t* sB = buf + 64 * 36;           // 32 x 136
    float* sY = (float*)buf;                // 64 x 132 (epilogue)
    int tid = threadIdx.x;
    int lane = tid & 31, wid = tid >> 5;
    int warp_m = wid & 3, warp_n = wid >> 2;
    int m0 = blockIdx.x * 64;

    float c[8][4];
#pragma unroll
    for (int nt = 0; nt < 8; nt++)
#pragma unroll
        for (int r = 0; r < 4; r++) c[nt][r] = 0.f;

    int aRow = warp_m * 16 + (lane >> 2);
    int kq = lane & 3;

    for (int kc = 0; kc < HID; kc += 32) {
        __syncthreads();
#pragma unroll
        for (int p = 0; p < 2; p++) {
            int idx = tid + p * 256;          // 512 uint2
            int row = idx >> 3, c4 = (idx & 7) * 4;
            int gr = m0 + row;
            uint2 v = (gr < N_NODES)
                ? *(const uint2*)&g_act16[(size_t)gr * HID + kc + c4]
                : make_uint2(0u, 0u);
            float2 f0 = __half22float2(*(__half2*)&v.x);
            float2 f1 = __half22float2(*(__half2*)&v.y);
            uint32_t* dd = &sA[row * 36 + c4];
            dd[0] = f2tf32(f0.x); dd[1] = f2tf32(f0.y);
            dd[2] = f2tf32(f1.x); dd[3] = f2tf32(f1.y);
        }
#pragma unroll
        for (int p = 0; p < 4; p++) {
            int idx = tid + p * 256;          // 1024 float4
            int kr = idx >> 5, c4 = (idx & 31) * 4;
            float4 v = *(const float4*)&proj_w[(size_t)(kc + kr) * OUT_CH + c4];
            uint32_t* dd = &sB[kr * 136 + c4];
            dd[0] = f2tf32(v.x); dd[1] = f2tf32(v.y);
            dd[2] = f2tf32(v.z); dd[3] = f2tf32(v.w);
        }
        __syncthreads();

#pragma unroll
        for (int ks = 0; ks < 32; ks += 8) {
            uint32_t a0 = sA[aRow * 36 + ks + kq];
            uint32_t a1 = sA[(aRow + 8) * 36 + ks + kq];
            uint32_t a2 = sA[aRow * 36 + ks + kq + 4];
            uint32_t a3 = sA[(aRow + 8) * 36 + ks + kq + 4];
#pragma unroll
            for (int nt = 0; nt < 8; nt++) {
                int nb = warp_n * 64 + nt * 8 + (lane >> 2);
                uint32_t b0 = sB[(ks + kq) * 136 + nb];
                uint32_t b1 = sB[(ks + kq + 4) * 136 + nb];
                asm volatile(
                    "mma.sync.aligned.m16n8k8.row.col.f32.tf32.tf32.f32 "
                    "{%0,%1,%2,%3}, {%4,%5,%6,%7}, {%8,%9}, {%0,%1,%2,%3};"
                    : "+f"(c[nt][0]), "+f"(c[nt][1]), "+f"(c[nt][2]), "+f"(c[nt][3])
                    : "r"(a0), "r"(a1), "r"(a2), "r"(a3), "r"(b0), "r"(b1));
            }
        }
    }
    __syncthreads();   // mainloop buffers dead; reuse as sY

    int lr = warp_m * 16 + (lane >> 2);
#pragma unroll
    for (int nt = 0; nt < 8; nt++) {
        int col = warp_n * 64 + nt * 8 + (lane & 3) * 2;
        int gr0 = m0 + lr, gr1 = gr0 + 8;
        float pb0 = proj_b[col], pb1 = proj_b[col + 1];
        float x00 = 0.f, x01 = 0.f, x10 = 0.f, x11 = 0.f;
        if (gr0 < N_NODES) {
            x00 = x[(size_t)gr0 * OUT_CH + col];
            x01 = x[(size_t)gr0 * OUT_CH + col + 1];
        }
        if (gr1 < N_NODES) {
            x10 = x[(size_t)gr1 * OUT_CH + col];
            x11 = x[(size_t)gr1 * OUT_CH + col + 1];
        }
        sY[lr * 132 + col]           = c[nt][0] + pb0 + x00;
        sY[lr * 132 + col + 1]       = c[nt][1] + pb1 + x01;
        sY[(lr + 8) * 132 + col]     = c[nt][2] + pb0 + x10;
        sY[(lr + 8) * 132 + col + 1] = c[nt][3] + pb1 + x11;
    }
    __syncthreads();

    float gg[4], bb[4];
#pragma unroll
    for (int q = 0; q < 4; q++) {
        gg[q] = lng[lane + q * 32];
        bb[q] = lnb[lane + q * 32];
    }
#pragma unroll
    for (int q = 0; q < 8; q++) {
        int r = wid * 8 + q;
        int gr = m0 + r;
        float v0 = sY[r * 132 + lane];
        float v1 = sY[r * 132 + lane + 32];
        float v2 = sY[r * 132 + lane + 64];
        float v3 = sY[r * 132 + lane + 96];
        float s1 = v0 + v1 + v2 + v3;
        float s2 = v0 * v0 + v1 * v1 + v2 * v2 + v3 * v3;
#pragma unroll
        for (int o = 16; o; o >>= 1) {
            s1 += __shfl_xor_sync(0xffffffffu, s1, o);
            s2 += __shfl_xor_sync(0xffffffffu, s2, o);
        }
        float mu = s1 * (1.f / 128.f);
        float rs = rsqrtf(s2 * (1.f / 128.f) - mu * mu + LN_EPS);
        if (gr < N_NODES) {
            out[(size_t)gr * OUT_CH + lane]      = (v0 - mu) * rs * gg[0] + bb[0];
            out[(size_t)gr * OUT_CH + lane + 32] = (v1 - mu) * rs * gg[1] + bb[1];
            out[(size_t)gr * OUT_CH + lane + 64] = (v2 - mu) * rs * gg[2] + bb[2];
            out[(size_t)gr * OUT_CH + lane + 96] = (v3 - mu) * rs * gg[3] + bb[3];
        }
    }
}

// ---------------- launch ----------------
extern "C" void kernel_launch(void* const* d_in, const int* in_sizes, int n_in,
                              void* d_out, int out_size) {
    const float* x        = (const float*)d_in[0];
    const void*  ei       = d_in[1];
    const float* lin_w    = (const float*)d_in[2];
    const float* att_src  = (const float*)d_in[3];
    const float* att_dst  = (const float*)d_in[4];
    const float* gat_bias = (const float*)d_in[5];
    const float* proj_w   = (const float*)d_in[6];
    const float* proj_b   = (const float*)d_in[7];
    const float* ln_g     = (const float*)d_in[8];
    const float* ln_b     = (const float*)d_in[9];
    float* out = (float*)d_out;

    detect_k<<<1, 32>>>(ei);
    init_cnt_k<<<(N_NODES + 255) / 256, 256>>>();
    convert_hist_k<<<(N_EDGES + 255) / 256, 256>>>(ei);
    partial_k<<<NPART, SCAN_BLK>>>();
    scanpart_k<<<1, 256>>>();
    offsets_k<<<NPART, SCAN_BLK>>>();
    scatter_k<<<(N_EDGES + 255) / 256, 256>>>();

    gemm1_k<<<dim3(HID / 64, (N_NODES + 63) / 64), 256>>>(x, lin_w);
    attn_k<<<N_NODES, 128>>>(att_src, att_dst);
    agg_k<<<N_NODES, 128>>>(gat_bias);
    gemm2_ln_k<<<(N_NODES + 63) / 64, 256>>>(proj_w, proj_b, x, ln_g, ln_b, out);
}

// round 9
// speedup vs baseline: 2.0997x; 1.0230x over previous
#include <cuda_runtime.h>
#include <cuda_fp16.h>
#include <cstdint>

#define N_NODES 50000
#define N_EDGES 800000
#define TOT_ADJ (N_EDGES + N_NODES)
#define HID 512           // HEADS*OUT_CH
#define IN_CH 128
#define OUT_CH 128
#define HEADS 4
#define NEG_SLOPE 0.2f
#define LN_EPS 1e-5f
#define CAP 256
#define SCAN_BLK 256
#define NPART ((N_NODES + SCAN_BLK - 1) / SCAN_BLK)   // 196

// ---------------- device scratch (static, no allocation) ----------------
__device__ __half g_h16[(size_t)N_NODES * HID];    // h  (fp16, 51 MB, ~L2-resident)
__device__ __half g_act16[(size_t)N_NODES * HID];  // relu(agg + gat_bias) fp16
__device__ float g_asrc[N_NODES * HEADS];
__device__ float g_adst[N_NODES * HEADS];
__device__ int   g_cnt[N_NODES];
__device__ int   g_cur[N_NODES];
__device__ int   g_off[N_NODES + 1];
__device__ int   g_adj[TOT_ADJ];
__device__ int   g_part[NPART];
__device__ int   g_is64;

__device__ __forceinline__ uint32_t f2tf32(float f) {
    uint32_t r;
    asm("cvt.rna.tf32.f32 %0, %1;" : "=r"(r) : "f"(f));
    return r;
}

// ---------------- init counts + parallel dtype probe ---------------------
// int64 indices: every 8-byte word < N_NODES. int32 data read as int64
// combines two indices -> >= 2^32 almost surely.
__global__ void initdet_k(const void* ei) {
    int i = blockIdx.x * blockDim.x + threadIdx.x;
    if (i < N_NODES) g_cnt[i] = 1;   // self loop
    if (blockIdx.x == 0 && threadIdx.x < 32) {
        const long long* p = (const long long*)ei;
        int ok = 1;
        for (int j = (int)threadIdx.x; j < 1024; j += 32) {
            long long v = p[j * 3];
            if (v < 0 || v >= N_NODES) ok = 0;
        }
        ok = __all_sync(0xffffffffu, ok);
        if (threadIdx.x == 0) g_is64 = ok;
    }
}

__device__ __forceinline__ int load_idx(const void* ei, size_t pos, int is64) {
    if (is64) return (int)((const long long*)ei)[pos];
    return ((const int*)ei)[pos];
}

__global__ void hist_k(const void* ei) {
    int i = blockIdx.x * blockDim.x + threadIdx.x;
    if (i >= N_EDGES) return;
    int d = load_idx(ei, (size_t)N_EDGES + i, g_is64);
    atomicAdd(&g_cnt[d], 1);
}

// ---------------- multi-block exclusive scan of g_cnt -> g_off ----------
__global__ void partial_k() {
    __shared__ int sd[SCAN_BLK];
    int i = blockIdx.x * SCAN_BLK + threadIdx.x;
    sd[threadIdx.x] = (i < N_NODES) ? g_cnt[i] : 0;
    __syncthreads();
    for (int st = SCAN_BLK / 2; st; st >>= 1) {
        if (threadIdx.x < st) sd[threadIdx.x] += sd[threadIdx.x + st];
        __syncthreads();
    }
    if (threadIdx.x == 0) g_part[blockIdx.x] = sd[0];
}

__global__ void scanpart_k() {
    __shared__ int sp[256];
    int t = threadIdx.x;
    int own = (t < NPART) ? g_part[t] : 0;
    sp[t] = own;
    __syncthreads();
    for (int st = 1; st < 256; st <<= 1) {
        int v = (t >= st) ? sp[t - st] : 0;
        __syncthreads();
        sp[t] += v;
        __syncthreads();
    }
    if (t < NPART) g_part[t] = sp[t] - own;     // exclusive
    if (t == 255) g_off[N_NODES] = sp[255];     // total
}

// offsets + self-loop seed fused
__global__ void offsets_k() {
    __shared__ int sd[SCAN_BLK];
    int i = blockIdx.x * SCAN_BLK + threadIdx.x;
    int own = (i < N_NODES) ? g_cnt[i] : 0;
    sd[threadIdx.x] = own;
    __syncthreads();
    for (int st = 1; st < SCAN_BLK; st <<= 1) {
        int v = (threadIdx.x >= st) ? sd[threadIdx.x - st] : 0;
        __syncthreads();
        sd[threadIdx.x] += v;
        __syncthreads();
    }
    if (i < N_NODES) {
        int off = g_part[blockIdx.x] + sd[threadIdx.x] - own;
        g_off[i] = off;
        g_adj[off] = i;     // self loop first
        g_cur[i] = 1;
    }
}

__global__ void scatter_k(const void* ei) {
    int i = blockIdx.x * blockDim.x + threadIdx.x;
    if (i >= N_EDGES) return;
    int is64 = g_is64;
    int s = load_idx(ei, (size_t)i, is64);
    int d = load_idx(ei, (size_t)N_EDGES + i, is64);
    int pos = g_off[d] + atomicAdd(&g_cur[d], 1);
    g_adj[pos] = s;
}

// ---------------- GEMM1: h = x @ lin_w, tf32 mma, fp16 out --------------
__global__ __launch_bounds__(256) void gemm1_k(const float* __restrict__ x,
                                               const float* __restrict__ w) {
    __shared__ uint32_t sA[64 * 132];   // 33 KB, full K=128
    __shared__ uint32_t sB[32 * 72];    // 9 KB, one 32-row K chunk
    int tid = threadIdx.x;
    int lane = tid & 31, wid = tid >> 5;
    int warp_m = wid & 3, warp_n = wid >> 2;
    int m0 = blockIdx.y * 64;
    int n0 = blockIdx.x * 64;

#pragma unroll
    for (int p = 0; p < 8; p++) {
        int idx = tid + p * 256;
        int row = idx >> 5, c4 = (idx & 31) * 4;
        int gr = m0 + row;
        float4 v = (gr < N_NODES) ? *(const float4*)&x[(size_t)gr * 128 + c4]
                                  : make_float4(0.f, 0.f, 0.f, 0.f);
        uint32_t* d = &sA[row * 132 + c4];
        d[0] = f2tf32(v.x); d[1] = f2tf32(v.y);
        d[2] = f2tf32(v.z); d[3] = f2tf32(v.w);
    }

    float c[4][4];
#pragma unroll
    for (int nt = 0; nt < 4; nt++)
#pragma unroll
        for (int r = 0; r < 4; r++) c[nt][r] = 0.f;

    int aRow = warp_m * 16 + (lane >> 2);
    int kq = lane & 3;

    for (int kc = 0; kc < 128; kc += 32) {
        __syncthreads();
#pragma unroll
        for (int p = 0; p < 2; p++) {
            int idx = tid + p * 256;
            int kr = idx >> 4, c4 = (idx & 15) * 4;
            float4 v = *(const float4*)&w[(size_t)(kc + kr) * HID + n0 + c4];
            uint32_t* d = &sB[kr * 72 + c4];
            d[0] = f2tf32(v.x); d[1] = f2tf32(v.y);
            d[2] = f2tf32(v.z); d[3] = f2tf32(v.w);
        }
        __syncthreads();

#pragma unroll
        for (int ks = 0; ks < 32; ks += 8) {
            uint32_t a0 = sA[aRow * 132 + kc + ks + kq];
            uint32_t a1 = sA[(aRow + 8) * 132 + kc + ks + kq];
            uint32_t a2 = sA[aRow * 132 + kc + ks + kq + 4];
            uint32_t a3 = sA[(aRow + 8) * 132 + kc + ks + kq + 4];
#pragma unroll
            for (int nt = 0; nt < 4; nt++) {
                int nb = warp_n * 32 + nt * 8 + (lane >> 2);
                uint32_t b0 = sB[(ks + kq) * 72 + nb];
                uint32_t b1 = sB[(ks + kq + 4) * 72 + nb];
                asm volatile(
                    "mma.sync.aligned.m16n8k8.row.col.f32.tf32.tf32.f32 "
                    "{%0,%1,%2,%3}, {%4,%5,%6,%7}, {%8,%9}, {%0,%1,%2,%3};"
                    : "+f"(c[nt][0]), "+f"(c[nt][1]), "+f"(c[nt][2]), "+f"(c[nt][3])
                    : "r"(a0), "r"(a1), "r"(a2), "r"(a3), "r"(b0), "r"(b1));
            }
        }
    }

    int rowA = m0 + warp_m * 16 + (lane >> 2);
    int colB = n0 + warp_n * 32 + (lane & 3) * 2;
#pragma unroll
    for (int nt = 0; nt < 4; nt++) {
        int col = colB + nt * 8;
        if (rowA < N_NODES)
            *(__half2*)&g_h16[(size_t)rowA * HID + col] =
                __floats2half2_rn(c[nt][0], c[nt][1]);
        if (rowA + 8 < N_NODES)
            *(__half2*)&g_h16[(size_t)(rowA + 8) * HID + col] =
                __floats2half2_rn(c[nt][2], c[nt][3]);
    }
}

// ---------------- attention coefficients (fp16 h, fp32 math) -------------
__global__ __launch_bounds__(128) void attn_k(const float* __restrict__ att_src,
                                              const float* __restrict__ att_dst) {
    int node = blockIdx.x;
    int w = threadIdx.x >> 5;   // = head
    int lane = threadIdx.x & 31;
    const __half2* hp = (const __half2*)&g_h16[(size_t)node * HID + w * 128 + lane * 4];
    __half2 p0 = hp[0], p1 = hp[1];
    float2 v0 = __half22float2(p0), v1 = __half22float2(p1);
    float4 a = *(const float4*)&att_src[w * 128 + lane * 4];
    float4 b = *(const float4*)&att_dst[w * 128 + lane * 4];
    float ds = v0.x * a.x + v0.y * a.y + v1.x * a.z + v1.y * a.w;
    float dd = v0.x * b.x + v0.y * b.y + v1.x * b.z + v1.y * b.w;
#pragma unroll
    for (int o = 16; o; o >>= 1) {
        ds += __shfl_xor_sync(0xffffffffu, ds, o);
        dd += __shfl_xor_sync(0xffffffffu, dd, o);
    }
    if (lane == 0) {
        g_asrc[node * HEADS + w] = ds;
        g_adst[node * HEADS + w] = dd;
    }
}

// ---------------- per-node softmax + weighted aggregation ----------------
__device__ __forceinline__ float leaky(float e) { return e > 0.f ? e : NEG_SLOPE * e; }

__device__ __forceinline__ void acc8(float* acc, uint4 v, float al) {
    float2 f0 = __half22float2(*(__half2*)&v.x);
    float2 f1 = __half22float2(*(__half2*)&v.y);
    float2 f2 = __half22float2(*(__half2*)&v.z);
    float2 f3 = __half22float2(*(__half2*)&v.w);
    acc[0] += f0.x * al; acc[1] += f0.y * al;
    acc[2] += f1.x * al; acc[3] += f1.y * al;
    acc[4] += f2.x * al; acc[5] += f2.y * al;
    acc[6] += f3.x * al; acc[7] += f3.y * al;
}

__global__ __launch_bounds__(128) void agg_k(const float* __restrict__ gat_bias) {
    __shared__ int   sadj[CAP];
    __shared__ float se[HEADS][CAP];
    __shared__ float sinv[HEADS], smx[HEADS], sadh[HEADS];
    __shared__ float sacc[64][9];
    int d = blockIdx.x;
    int tid = threadIdx.x;
    int w = tid >> 5;            // warp = head (softmax phase)
    int lane = tid & 31;
    int beg = g_off[d];
    int deg = g_off[d + 1] - beg;
    float adh = g_adst[d * HEADS + w];
    bool cached = (deg <= CAP);

    float mx = -1e30f, sum = 0.f;
    if (cached) {
        for (int i = lane; i < deg; i += 32) {
            int s = g_adj[beg + i];
            if (w == 0) sadj[i] = s;
            float e = leaky(g_asrc[s * HEADS + w] + adh);
            se[w][i] = e;
            mx = fmaxf(mx, e);
        }
#pragma unroll
        for (int o = 16; o; o >>= 1) mx = fmaxf(mx, __shfl_xor_sync(0xffffffffu, mx, o));
        for (int i = lane; i < deg; i += 32) {
            float a = __expf(se[w][i] - mx);
            se[w][i] = a;
            sum += a;
        }
#pragma unroll
        for (int o = 16; o; o >>= 1) sum += __shfl_xor_sync(0xffffffffu, sum, o);
    } else {
        for (int i = lane; i < deg; i += 32) {
            int s = g_adj[beg + i];
            mx = fmaxf(mx, leaky(g_asrc[s * HEADS + w] + adh));
        }
#pragma unroll
        for (int o = 16; o; o >>= 1) mx = fmaxf(mx, __shfl_xor_sync(0xffffffffu, mx, o));
        for (int i = lane; i < deg; i += 32) {
            int s = g_adj[beg + i];
            sum += __expf(leaky(g_asrc[s * HEADS + w] + adh) - mx);
        }
#pragma unroll
        for (int o = 16; o; o >>= 1) sum += __shfl_xor_sync(0xffffffffu, sum, o);
    }
    if (lane == 0) {
        sinv[w] = 1.f / (sum + 1e-16f);
        smx[w] = mx;
        sadh[w] = adh;
    }
    __syncthreads();

    int g = tid >> 6;            // edge-parity group
    int t6 = tid & 63;
    int ch = t6 * 8;
    int head = t6 >> 4;
    float inv = sinv[head];
    float acc[8] = {0.f, 0.f, 0.f, 0.f, 0.f, 0.f, 0.f, 0.f};
    const __half* hbase = g_h16;

    if (cached) {
        int i = g;
        for (; i + 6 < deg; i += 8) {
            float al0 = se[head][i] * inv;
            float al1 = se[head][i + 2] * inv;
            float al2 = se[head][i + 4] * inv;
            float al3 = se[head][i + 6] * inv;
            uint4 v0 = *(const uint4*)&hbase[(size_t)sadj[i]     * HID + ch];
            uint4 v1 = *(const uint4*)&hbase[(size_t)sadj[i + 2] * HID + ch];
            uint4 v2 = *(const uint4*)&hbase[(size_t)sadj[i + 4] * HID + ch];
            uint4 v3 = *(const uint4*)&hbase[(size_t)sadj[i + 6] * HID + ch];
            acc8(acc, v0, al0);
            acc8(acc, v1, al1);
            acc8(acc, v2, al2);
            acc8(acc, v3, al3);
        }
        for (; i < deg; i += 2) {
            float al = se[head][i] * inv;
            uint4 v = *(const uint4*)&hbase[(size_t)sadj[i] * HID + ch];
            acc8(acc, v, al);
        }
    } else {
        float mxh = smx[head], adhh = sadh[head];
        for (int i = g; i < deg; i += 2) {
            int s = g_adj[beg + i];
            float al = __expf(leaky(g_asrc[s * HEADS + head] + adhh) - mxh) * inv;
            uint4 v = *(const uint4*)&hbase[(size_t)s * HID + ch];
            acc8(acc, v, al);
        }
    }

    if (g == 1) {
#pragma unroll
        for (int j = 0; j < 8; j++) sacc[t6][j] = acc[j];
    }
    __syncthreads();
    if (g == 0) {
        float4 b0 = *(const float4*)&gat_bias[ch];
        float4 b1 = *(const float4*)&gat_bias[ch + 4];
        float r0 = fmaxf(acc[0] + sacc[t6][0] + b0.x, 0.f);
        float r1 = fmaxf(acc[1] + sacc[t6][1] + b0.y, 0.f);
        float r2 = fmaxf(acc[2] + sacc[t6][2] + b0.z, 0.f);
        float r3 = fmaxf(acc[3] + sacc[t6][3] + b0.w, 0.f);
        float r4 = fmaxf(acc[4] + sacc[t6][4] + b1.x, 0.f);
        float r5 = fmaxf(acc[5] + sacc[t6][5] + b1.y, 0.f);
        float r6 = fmaxf(acc[6] + sacc[t6][6] + b1.z, 0.f);
        float r7 = fmaxf(acc[7] + sacc[t6][7] + b1.w, 0.f);
        uint4 st;
        *(__half2*)&st.x = __floats2half2_rn(r0, r1);
        *(__half2*)&st.y = __floats2half2_rn(r2, r3);
        *(__half2*)&st.z = __floats2half2_rn(r4, r5);
        *(__half2*)&st.w = __floats2half2_rn(r6, r7);
        *(uint4*)&g_act16[(size_t)d * HID + ch] = st;
    }
}

// ------- GEMM2 (tf32 mma) + bias + residual + LayerNorm, fused ----------
__global__ __launch_bounds__(256) void gemm2_ln_k(const float* __restrict__ proj_w,
                                                  const float* __restrict__ proj_b,
                                                  const float* __restrict__ x,
                                                  const float* __restrict__ lng,
                                                  const float* __restrict__ lnb,
                                                  float* __restrict__ out) {
    __shared__ uint32_t buf[64 * 132];      // 33 KB, aliased
    uint32_t* sA = buf;                     // 64 x 36
    uint32_t* sB = buf + 64 * 36;           // 32 x 136
    float* sY = (float*)buf;                // 64 x 132 (epilogue)
    int tid = threadIdx.x;
    int lane = tid & 31, wid = tid >> 5;
    int warp_m = wid & 3, warp_n = wid >> 2;
    int m0 = blockIdx.x * 64;

    float c[8][4];
#pragma unroll
    for (int nt = 0; nt < 8; nt++)
#pragma unroll
        for (int r = 0; r < 4; r++) c[nt][r] = 0.f;

    int aRow = warp_m * 16 + (lane >> 2);
    int kq = lane & 3;

    for (int kc = 0; kc < HID; kc += 32) {
        __syncthreads();
#pragma unroll
        for (int p = 0; p < 2; p++) {
            int idx = tid + p * 256;          // 512 uint2
            int row = idx >> 3, c4 = (idx & 7) * 4;
            int gr = m0 + row;
            uint2 v = (gr < N_NODES)
                ? *(const uint2*)&g_act16[(size_t)gr * HID + kc + c4]
                : make_uint2(0u, 0u);
            float2 f0 = __half22float2(*(__half2*)&v.x);
            float2 f1 = __half22float2(*(__half2*)&v.y);
            uint32_t* dd = &sA[row * 36 + c4];
            dd[0] = f2tf32(f0.x); dd[1] = f2tf32(f0.y);
            dd[2] = f2tf32(f1.x); dd[3] = f2tf32(f1.y);
        }
#pragma unroll
        for (int p = 0; p < 4; p++) {
            int idx = tid + p * 256;          // 1024 float4
            int kr = idx >> 5, c4 = (idx & 31) * 4;
            float4 v = *(const float4*)&proj_w[(size_t)(kc + kr) * OUT_CH + c4];
            uint32_t* dd = &sB[kr * 136 + c4];
            dd[0] = f2tf32(v.x); dd[1] = f2tf32(v.y);
            dd[2] = f2tf32(v.z); dd[3] = f2tf32(v.w);
        }
        __syncthreads();

#pragma unroll
        for (int ks = 0; ks < 32; ks += 8) {
            uint32_t a0 = sA[aRow * 36 + ks + kq];
            uint32_t a1 = sA[(aRow + 8) * 36 + ks + kq];
            uint32_t a2 = sA[aRow * 36 + ks + kq + 4];
            uint32_t a3 = sA[(aRow + 8) * 36 + ks + kq + 4];
#pragma unroll
            for (int nt = 0; nt < 8; nt++) {
                int nb = warp_n * 64 + nt * 8 + (lane >> 2);
                uint32_t b0 = sB[(ks + kq) * 136 + nb];
                uint32_t b1 = sB[(ks + kq + 4) * 136 + nb];
                asm volatile(
                    "mma.sync.aligned.m16n8k8.row.col.f32.tf32.tf32.f32 "
                    "{%0,%1,%2,%3}, {%4,%5,%6,%7}, {%8,%9}, {%0,%1,%2,%3};"
                    : "+f"(c[nt][0]), "+f"(c[nt][1]), "+f"(c[nt][2]), "+f"(c[nt][3])
                    : "r"(a0), "r"(a1), "r"(a2), "r"(a3), "r"(b0), "r"(b1));
            }
        }
    }
    __syncthreads();   // mainloop buffers dead; reuse as sY

    int lr = warp_m * 16 + (lane >> 2);
#pragma unroll
    for (int nt = 0; nt < 8; nt++) {
        int col = warp_n * 64 + nt * 8 + (lane & 3) * 2;
        int gr0 = m0 + lr, gr1 = gr0 + 8;
        float pb0 = proj_b[col], pb1 = proj_b[col + 1];
        float x00 = 0.f, x01 = 0.f, x10 = 0.f, x11 = 0.f;
        if (gr0 < N_NODES) {
            x00 = x[(size_t)gr0 * OUT_CH + col];
            x01 = x[(size_t)gr0 * OUT_CH + col + 1];
        }
        if (gr1 < N_NODES) {
            x10 = x[(size_t)gr1 * OUT_CH + col];
            x11 = x[(size_t)gr1 * OUT_CH + col + 1];
        }
        sY[lr * 132 + col]           = c[nt][0] + pb0 + x00;
        sY[lr * 132 + col + 1]       = c[nt][1] + pb1 + x01;
        sY[(lr + 8) * 132 + col]     = c[nt][2] + pb0 + x10;
        sY[(lr + 8) * 132 + col + 1] = c[nt][3] + pb1 + x11;
    }
    __syncthreads();

    float gg[4], bb[4];
#pragma unroll
    for (int q = 0; q < 4; q++) {
        gg[q] = lng[lane + q * 32];
        bb[q] = lnb[lane + q * 32];
    }
#pragma unroll
    for (int q = 0; q < 8; q++) {
        int r = wid * 8 + q;
        int gr = m0 + r;
        float v0 = sY[r * 132 + lane];
        float v1 = sY[r * 132 + lane + 32];
        float v2 = sY[r * 132 + lane + 64];
        float v3 = sY[r * 132 + lane + 96];
        float s1 = v0 + v1 + v2 + v3;
        float s2 = v0 * v0 + v1 * v1 + v2 * v2 + v3 * v3;
#pragma unroll
        for (int o = 16; o; o >>= 1) {
            s1 += __shfl_xor_sync(0xffffffffu, s1, o);
            s2 += __shfl_xor_sync(0xffffffffu, s2, o);
        }
        float mu = s1 * (1.f / 128.f);
        float rs = rsqrtf(s2 * (1.f / 128.f) - mu * mu + LN_EPS);
        if (gr < N_NODES) {
            out[(size_t)gr * OUT_CH + lane]      = (v0 - mu) * rs * gg[0] + bb[0];
            out[(size_t)gr * OUT_CH + lane + 32] = (v1 - mu) * rs * gg[1] + bb[1];
            out[(size_t)gr * OUT_CH + lane + 64] = (v2 - mu) * rs * gg[2] + bb[2];
            out[(size_t)gr * OUT_CH + lane + 96] = (v3 - mu) * rs * gg[3] + bb[3];
        }
    }
}

// ---------------- launch: CSR chain forked onto a side stream -----------
extern "C" void kernel_launch(void* const* d_in, const int* in_sizes, int n_in,
                              void* d_out, int out_size) {
    const float* x        = (const float*)d_in[0];
    const void*  ei       = d_in[1];
    const float* lin_w    = (const float*)d_in[2];
    const float* att_src  = (const float*)d_in[3];
    const float* att_dst  = (const float*)d_in[4];
    const float* gat_bias = (const float*)d_in[5];
    const float* proj_w   = (const float*)d_in[6];
    const float* proj_b   = (const float*)d_in[7];
    const float* ln_g     = (const float*)d_in[8];
    const float* ln_b     = (const float*)d_in[9];
    float* out = (float*)d_out;

    // fresh per call (called only a handful of times; replays use the graph)
    cudaStream_t sc;
    cudaEvent_t evF, evJ;
    cudaStreamCreateWithFlags(&sc, cudaStreamNonBlocking);
    cudaEventCreateWithFlags(&evF, cudaEventDisableTiming);
    cudaEventCreateWithFlags(&evJ, cudaEventDisableTiming);

    // fork: side stream depends on capture origin
    cudaEventRecord(evF, 0);
    cudaStreamWaitEvent(sc, evF, 0);

    // ---- side stream: CSR build ----
    initdet_k<<<(N_NODES + 255) / 256, 256, 0, sc>>>(ei);
    hist_k<<<(N_EDGES + 255) / 256, 256, 0, sc>>>(ei);
    partial_k<<<NPART, SCAN_BLK, 0, sc>>>();
    scanpart_k<<<1, 256, 0, sc>>>();
    offsets_k<<<NPART, SCAN_BLK, 0, sc>>>();
    scatter_k<<<(N_EDGES + 255) / 256, 256, 0, sc>>>(ei);
    cudaEventRecord(evJ, sc);

    // ---- main stream: feature path ----
    gemm1_k<<<dim3(HID / 64, (N_NODES + 63) / 64), 256>>>(x, lin_w);
    attn_k<<<N_NODES, 128>>>(att_src, att_dst);

    // join, then the dependent tail
    cudaStreamWaitEvent(0, evJ, 0);
    agg_k<<<N_NODES, 128>>>(gat_bias);
    gemm2_ln_k<<<(N_NODES + 63) / 64, 256>>>(proj_w, proj_b, x, ln_g, ln_b, out);
}

// round 10
// speedup vs baseline: 2.4335x; 1.1590x over previous
#include <cuda_runtime.h>
#include <cuda_fp16.h>
#include <cstdint>

#define N_NODES 50000
#define N_EDGES 800000
#define TOT_ADJ (N_EDGES + N_NODES)
#define HID 512           // HEADS*OUT_CH
#define IN_CH 128
#define OUT_CH 128
#define HEADS 4
#define NEG_SLOPE 0.2f
#define LN_EPS 1e-5f
#define CAP 256
#define SCAN_BLK 256
#define NPART ((N_NODES + SCAN_BLK - 1) / SCAN_BLK)   // 196

// ---------------- device scratch (static, no allocation) ----------------
__device__ __half g_h16[(size_t)N_NODES * HID];    // h  (fp16, 51 MB, ~L2-resident)
__device__ __half g_act16[(size_t)N_NODES * HID];  // relu(agg + gat_bias) fp16
__device__ __half2 g_w16[(HID / 2) * OUT_CH];      // proj_w, k-pair packed fp16
__device__ float g_asrc[N_NODES * HEADS];
__device__ float g_adst[N_NODES * HEADS];
__device__ int   g_cnt[N_NODES];
__device__ int   g_cur[N_NODES];
__device__ int   g_off[N_NODES + 1];
__device__ int   g_adj[TOT_ADJ];
__device__ int   g_part[NPART];
__device__ int   g_is64;

__device__ __forceinline__ uint32_t f2tf32(float f) {
    uint32_t r;
    asm("cvt.rna.tf32.f32 %0, %1;" : "=r"(r) : "f"(f));
    return r;
}

// ---------------- init counts + parallel dtype probe ---------------------
__global__ void initdet_k(const void* ei) {
    int i = blockIdx.x * blockDim.x + threadIdx.x;
    if (i < N_NODES) g_cnt[i] = 1;   // self loop
    if (blockIdx.x == 0 && threadIdx.x < 32) {
        const long long* p = (const long long*)ei;
        int ok = 1;
        for (int j = (int)threadIdx.x; j < 1024; j += 32) {
            long long v = p[j * 3];
            if (v < 0 || v >= N_NODES) ok = 0;
        }
        ok = __all_sync(0xffffffffu, ok);
        if (threadIdx.x == 0) g_is64 = ok;
    }
}

__device__ __forceinline__ int load_idx(const void* ei, size_t pos, int is64) {
    if (is64) return (int)((const long long*)ei)[pos];
    return ((const int*)ei)[pos];
}

__global__ void hist_k(const void* ei) {
    int i = blockIdx.x * blockDim.x + threadIdx.x;
    if (i >= N_EDGES) return;
    int d = load_idx(ei, (size_t)N_EDGES + i, g_is64);
    atomicAdd(&g_cnt[d], 1);
}

__global__ void partial_k() {
    __shared__ int sd[SCAN_BLK];
    int i = blockIdx.x * SCAN_BLK + threadIdx.x;
    sd[threadIdx.x] = (i < N_NODES) ? g_cnt[i] : 0;
    __syncthreads();
    for (int st = SCAN_BLK / 2; st; st >>= 1) {
        if (threadIdx.x < st) sd[threadIdx.x] += sd[threadIdx.x + st];
        __syncthreads();
    }
    if (threadIdx.x == 0) g_part[blockIdx.x] = sd[0];
}

__global__ void scanpart_k() {
    __shared__ int sp[256];
    int t = threadIdx.x;
    int own = (t < NPART) ? g_part[t] : 0;
    sp[t] = own;
    __syncthreads();
    for (int st = 1; st < 256; st <<= 1) {
        int v = (t >= st) ? sp[t - st] : 0;
        __syncthreads();
        sp[t] += v;
        __syncthreads();
    }
    if (t < NPART) g_part[t] = sp[t] - own;     // exclusive
    if (t == 255) g_off[N_NODES] = sp[255];     // total
}

__global__ void offsets_k() {
    __shared__ int sd[SCAN_BLK];
    int i = blockIdx.x * SCAN_BLK + threadIdx.x;
    int own = (i < N_NODES) ? g_cnt[i] : 0;
    sd[threadIdx.x] = own;
    __syncthreads();
    for (int st = 1; st < SCAN_BLK; st <<= 1) {
        int v = (threadIdx.x >= st) ? sd[threadIdx.x - st] : 0;
        __syncthreads();
        sd[threadIdx.x] += v;
        __syncthreads();
    }
    if (i < N_NODES) {
        int off = g_part[blockIdx.x] + sd[threadIdx.x] - own;
        g_off[i] = off;
        g_adj[off] = i;     // self loop first
        g_cur[i] = 1;
    }
}

__global__ void scatter_k(const void* ei) {
    int i = blockIdx.x * blockDim.x + threadIdx.x;
    if (i >= N_EDGES) return;
    int is64 = g_is64;
    int s = load_idx(ei, (size_t)i, is64);
    int d = load_idx(ei, (size_t)N_EDGES + i, is64);
    int pos = g_off[d] + atomicAdd(&g_cur[d], 1);
    g_adj[pos] = s;
}

// ---------------- zero attention accumulators ---------------------------
__global__ void zasrc_k() {
    int i = blockIdx.x * blockDim.x + threadIdx.x;
    if (i < N_NODES * HEADS) { g_asrc[i] = 0.f; g_adst[i] = 0.f; }
}

// ---------------- proj_w -> k-pair packed fp16 --------------------------
__global__ void wconv_k(const float* __restrict__ w) {
    int i = blockIdx.x * blockDim.x + threadIdx.x;   // kp*128 + n
    if (i >= (HID / 2) * OUT_CH) return;
    int kp = i >> 7, n = i & 127;
    g_w16[i] = __floats2half2_rn(w[(2 * kp) * OUT_CH + n],
                                 w[(2 * kp + 1) * OUT_CH + n]);
}

// ---- GEMM1: h = x @ lin_w, tf32 mma, fp16 out + fused attn dots --------
__global__ __launch_bounds__(256) void gemm1_k(const float* __restrict__ x,
                                               const float* __restrict__ w,
                                               const float* __restrict__ att_src,
                                               const float* __restrict__ att_dst) {
    __shared__ uint32_t sA[64 * 132];   // 33 KB, full K=128
    __shared__ uint32_t sB[32 * 72];    // 9 KB, one 32-row K chunk
    int tid = threadIdx.x;
    int lane = tid & 31, wid = tid >> 5;
    int warp_m = wid & 3, warp_n = wid >> 2;
    int m0 = blockIdx.y * 64;
    int n0 = blockIdx.x * 64;

#pragma unroll
    for (int p = 0; p < 8; p++) {
        int idx = tid + p * 256;
        int row = idx >> 5, c4 = (idx & 31) * 4;
        int gr = m0 + row;
        float4 v = (gr < N_NODES) ? *(const float4*)&x[(size_t)gr * 128 + c4]
                                  : make_float4(0.f, 0.f, 0.f, 0.f);
        uint32_t* d = &sA[row * 132 + c4];
        d[0] = f2tf32(v.x); d[1] = f2tf32(v.y);
        d[2] = f2tf32(v.z); d[3] = f2tf32(v.w);
    }

    float c[4][4];
#pragma unroll
    for (int nt = 0; nt < 4; nt++)
#pragma unroll
        for (int r = 0; r < 4; r++) c[nt][r] = 0.f;

    int aRow = warp_m * 16 + (lane >> 2);
    int kq = lane & 3;

    for (int kc = 0; kc < 128; kc += 32) {
        __syncthreads();
#pragma unroll
        for (int p = 0; p < 2; p++) {
            int idx = tid + p * 256;
            int kr = idx >> 4, c4 = (idx & 15) * 4;
            float4 v = *(const float4*)&w[(size_t)(kc + kr) * HID + n0 + c4];
            uint32_t* d = &sB[kr * 72 + c4];
            d[0] = f2tf32(v.x); d[1] = f2tf32(v.y);
            d[2] = f2tf32(v.z); d[3] = f2tf32(v.w);
        }
        __syncthreads();

#pragma unroll
        for (int ks = 0; ks < 32; ks += 8) {
            uint32_t a0 = sA[aRow * 132 + kc + ks + kq];
            uint32_t a1 = sA[(aRow + 8) * 132 + kc + ks + kq];
            uint32_t a2 = sA[aRow * 132 + kc + ks + kq + 4];
            uint32_t a3 = sA[(aRow + 8) * 132 + kc + ks + kq + 4];
#pragma unroll
            for (int nt = 0; nt < 4; nt++) {
                int nb = warp_n * 32 + nt * 8 + (lane >> 2);
                uint32_t b0 = sB[(ks + kq) * 72 + nb];
                uint32_t b1 = sB[(ks + kq + 4) * 72 + nb];
                asm volatile(
                    "mma.sync.aligned.m16n8k8.row.col.f32.tf32.tf32.f32 "
                    "{%0,%1,%2,%3}, {%4,%5,%6,%7}, {%8,%9}, {%0,%1,%2,%3};"
                    : "+f"(c[nt][0]), "+f"(c[nt][1]), "+f"(c[nt][2]), "+f"(c[nt][3])
                    : "r"(a0), "r"(a1), "r"(a2), "r"(a3), "r"(b0), "r"(b1));
            }
        }
    }

    int rowA = m0 + warp_m * 16 + (lane >> 2);
    int head = n0 >> 7;    // 64-col tile lies within one head
#pragma unroll
    for (int nt = 0; nt < 4; nt++) {
        int col = n0 + warp_n * 32 + nt * 8 + (lane & 3) * 2;
        if (rowA < N_NODES)
            *(__half2*)&g_h16[(size_t)rowA * HID + col] =
                __floats2half2_rn(c[nt][0], c[nt][1]);
        if (rowA + 8 < N_NODES)
            *(__half2*)&g_h16[(size_t)(rowA + 8) * HID + col] =
                __floats2half2_rn(c[nt][2], c[nt][3]);
    }

    // fused attention dot partials
    float ps0 = 0.f, ps1 = 0.f, pd0 = 0.f, pd1 = 0.f;
#pragma unroll
    for (int nt = 0; nt < 4; nt++) {
        int cc = (n0 + warp_n * 32 + nt * 8 + (lane & 3) * 2) & 127;
        float s0 = att_src[head * 128 + cc], s1 = att_src[head * 128 + cc + 1];
        float d0 = att_dst[head * 128 + cc], d1 = att_dst[head * 128 + cc + 1];
        ps0 += c[nt][0] * s0 + c[nt][1] * s1;
        pd0 += c[nt][0] * d0 + c[nt][1] * d1;
        ps1 += c[nt][2] * s0 + c[nt][3] * s1;
        pd1 += c[nt][2] * d0 + c[nt][3] * d1;
    }
#pragma unroll
    for (int o = 1; o < 4; o <<= 1) {
        ps0 += __shfl_xor_sync(0xffffffffu, ps0, o);
        ps1 += __shfl_xor_sync(0xffffffffu, ps1, o);
        pd0 += __shfl_xor_sync(0xffffffffu, pd0, o);
        pd1 += __shfl_xor_sync(0xffffffffu, pd1, o);
    }
    if ((lane & 3) == 0) {
        if (rowA < N_NODES) {
            atomicAdd(&g_asrc[rowA * HEADS + head], ps0);
            atomicAdd(&g_adst[rowA * HEADS + head], pd0);
        }
        if (rowA + 8 < N_NODES) {
            atomicAdd(&g_asrc[(rowA + 8) * HEADS + head], ps1);
            atomicAdd(&g_adst[(rowA + 8) * HEADS + head], pd1);
        }
    }
}

// ---------------- per-node softmax + weighted aggregation ----------------
__device__ __forceinline__ float leaky(float e) { return e > 0.f ? e : NEG_SLOPE * e; }

__device__ __forceinline__ void acc8(float* acc, uint4 v, float al) {
    float2 f0 = __half22float2(*(__half2*)&v.x);
    float2 f1 = __half22float2(*(__half2*)&v.y);
    float2 f2 = __half22float2(*(__half2*)&v.z);
    float2 f3 = __half22float2(*(__half2*)&v.w);
    acc[0] += f0.x * al; acc[1] += f0.y * al;
    acc[2] += f1.x * al; acc[3] += f1.y * al;
    acc[4] += f2.x * al; acc[5] += f2.y * al;
    acc[6] += f3.x * al; acc[7] += f3.y * al;
}

__global__ __launch_bounds__(128) void agg_k(const float* __restrict__ gat_bias) {
    __shared__ int   sadj[CAP];
    __shared__ float se[HEADS][CAP];
    __shared__ float sinv[HEADS], smx[HEADS], sadh[HEADS];
    __shared__ float sacc[64][9];
    int d = blockIdx.x;
    int tid = threadIdx.x;
    int w = tid >> 5;            // warp = head (softmax phase)
    int lane = tid & 31;
    int beg = g_off[d];
    int deg = g_off[d + 1] - beg;
    float adh = g_adst[d * HEADS + w];
    bool cached = (deg <= CAP);

    float mx = -1e30f, sum = 0.f;
    if (cached) {
        for (int i = lane; i < deg; i += 32) {
            int s = g_adj[beg + i];
            if (w == 0) sadj[i] = s;
            float e = leaky(g_asrc[s * HEADS + w] + adh);
            se[w][i] = e;
            mx = fmaxf(mx, e);
        }
#pragma unroll
        for (int o = 16; o; o >>= 1) mx = fmaxf(mx, __shfl_xor_sync(0xffffffffu, mx, o));
        for (int i = lane; i < deg; i += 32) {
            float a = __expf(se[w][i] - mx);
            se[w][i] = a;
            sum += a;
        }
#pragma unroll
        for (int o = 16; o; o >>= 1) sum += __shfl_xor_sync(0xffffffffu, sum, o);
    } else {
        for (int i = lane; i < deg; i += 32) {
            int s = g_adj[beg + i];
            mx = fmaxf(mx, leaky(g_asrc[s * HEADS + w] + adh));
        }
#pragma unroll
        for (int o = 16; o; o >>= 1) mx = fmaxf(mx, __shfl_xor_sync(0xffffffffu, mx, o));
        for (int i = lane; i < deg; i += 32) {
            int s = g_adj[beg + i];
            sum += __expf(leaky(g_asrc[s * HEADS + w] + adh) - mx);
        }
#pragma unroll
        for (int o = 16; o; o >>= 1) sum += __shfl_xor_sync(0xffffffffu, sum, o);
    }
    if (lane == 0) {
        sinv[w] = 1.f / (sum + 1e-16f);
        smx[w] = mx;
        sadh[w] = adh;
    }
    __syncthreads();

    int g = tid >> 6;
    int t6 = tid & 63;
    int ch = t6 * 8;
    int head = t6 >> 4;
    float inv = sinv[head];
    float acc[8] = {0.f, 0.f, 0.f, 0.f, 0.f, 0.f, 0.f, 0.f};
    const __half* hbase = g_h16;

    if (cached) {
        int i = g;
        for (; i + 6 < deg; i += 8) {
            float al0 = se[head][i] * inv;
            float al1 = se[head][i + 2] * inv;
            float al2 = se[head][i + 4] * inv;
            float al3 = se[head][i + 6] * inv;
            uint4 v0 = *(const uint4*)&hbase[(size_t)sadj[i]     * HID + ch];
            uint4 v1 = *(const uint4*)&hbase[(size_t)sadj[i + 2] * HID + ch];
            uint4 v2 = *(const uint4*)&hbase[(size_t)sadj[i + 4] * HID + ch];
            uint4 v3 = *(const uint4*)&hbase[(size_t)sadj[i + 6] * HID + ch];
            acc8(acc, v0, al0);
            acc8(acc, v1, al1);
            acc8(acc, v2, al2);
            acc8(acc, v3, al3);
        }
        for (; i < deg; i += 2) {
            float al = se[head][i] * inv;
            uint4 v = *(const uint4*)&hbase[(size_t)sadj[i] * HID + ch];
            acc8(acc, v, al);
        }
    } else {
        float mxh = smx[head], adhh = sadh[head];
        for (int i = g; i < deg; i += 2) {
            int s = g_adj[beg + i];
            float al = __expf(leaky(g_asrc[s * HEADS + head] + adhh) - mxh) * inv;
            uint4 v = *(const uint4*)&hbase[(size_t)s * HID + ch];
            acc8(acc, v, al);
        }
    }

    if (g == 1) {
#pragma unroll
        for (int j = 0; j < 8; j++) sacc[t6][j] = acc[j];
    }
    __syncthreads();
    if (g == 0) {
        float4 b0 = *(const float4*)&gat_bias[ch];
        float4 b1 = *(const float4*)&gat_bias[ch + 4];
        float r0 = fmaxf(acc[0] + sacc[t6][0] + b0.x, 0.f);
        float r1 = fmaxf(acc[1] + sacc[t6][1] + b0.y, 0.f);
        float r2 = fmaxf(acc[2] + sacc[t6][2] + b0.z, 0.f);
        float r3 = fmaxf(acc[3] + sacc[t6][3] + b0.w, 0.f);
        float r4 = fmaxf(acc[4] + sacc[t6][4] + b1.x, 0.f);
        float r5 = fmaxf(acc[5] + sacc[t6][5] + b1.y, 0.f);
        float r6 = fmaxf(acc[6] + sacc[t6][6] + b1.z, 0.f);
        float r7 = fmaxf(acc[7] + sacc[t6][7] + b1.w, 0.f);
        uint4 st;
        *(__half2*)&st.x = __floats2half2_rn(r0, r1);
        *(__half2*)&st.y = __floats2half2_rn(r2, r3);
        *(__half2*)&st.z = __floats2half2_rn(r4, r5);
        *(__half2*)&st.w = __floats2half2_rn(r6, r7);
        *(uint4*)&g_act16[(size_t)d * HID + ch] = st;
    }
}

// ------- GEMM2 (fp16 mma m16n8k16) + bias + residual + LayerNorm --------
// 64x128 tile / block, 256 thr (4 M-warps x 2 N-warps). K=512 in 32-chunks.
// smem: sA 64x20 u32 (fp16 pairs, stride 20 = conflict-free),
//       sB 16x136 u32 (k-pair packed fp16, stride 136), epilogue sY aliased.
__global__ __launch_bounds__(256) void gemm2_ln_k(const float* __restrict__ proj_b,
                                                  const float* __restrict__ x,
                                                  const float* __restrict__ lng,
                                                  const float* __restrict__ lnb,
                                                  float* __restrict__ out) {
    __shared__ uint32_t buf[64 * 132];      // 33 KB (epilogue size), aliased
    uint32_t* sA = buf;                     // 64 x 20
    uint32_t* sB = buf + 64 * 20;           // 16 x 136
    float* sY = (float*)buf;                // 64 x 132 (epilogue)
    int tid = threadIdx.x;
    int lane = tid & 31, wid = tid >> 5;
    int warp_m = wid & 3, warp_n = wid >> 2;
    int m0 = blockIdx.x * 64;

    float c[8][4];
#pragma unroll
    for (int nt = 0; nt < 8; nt++)
#pragma unroll
        for (int r = 0; r < 4; r++) c[nt][r] = 0.f;

    int aRow = warp_m * 16 + (lane >> 2);
    int kq = lane & 3;

    for (int kc = 0; kc < HID; kc += 32) {
        __syncthreads();
        // sA: 64 rows x 16 half2 (raw fp16 copies, no conversion)
#pragma unroll
        for (int p = 0; p < 2; p++) {
            int idx = tid + p * 256;          // 512
            int row = idx >> 3, h2 = (idx & 7) * 2;    // half2 col 0..15 step 2
            int gr = m0 + row;
            uint2 v = (gr < N_NODES)
                ? *(const uint2*)&g_act16[(size_t)gr * HID + kc + h2 * 2]
                : make_uint2(0u, 0u);
            sA[row * 20 + h2] = v.x;
            sA[row * 20 + h2 + 1] = v.y;
        }
        // sB: 16 k-pairs x 128 n (raw copies from pre-packed g_w16)
#pragma unroll
        for (int p = 0; p < 2; p++) {
            int idx = tid + p * 256;          // 512 uint4
            int row = idx >> 5, q = (idx & 31) * 4;
            uint4 v = *(const uint4*)&g_w16[(size_t)(kc / 2 + row) * OUT_CH + q];
            *(uint4*)&sB[row * 136 + q] = v;
        }
        __syncthreads();

#pragma unroll
        for (int ks = 0; ks < 32; ks += 16) {
            int ho = ks >> 1;                 // half2 / k-pair offset
            uint32_t a0 = sA[aRow * 20 + ho + kq];
            uint32_t a1 = sA[(aRow + 8) * 20 + ho + kq];
            uint32_t a2 = sA[aRow * 20 + ho + kq + 4];
            uint32_t a3 = sA[(aRow + 8) * 20 + ho + kq + 4];
#pragma unroll
            for (int nt = 0; nt < 8; nt++) {
                int nb = warp_n * 64 + nt * 8 + (lane >> 2);
                uint32_t b0 = sB[(ho + kq) * 136 + nb];
                uint32_t b1 = sB[(ho + kq + 4) * 136 + nb];
                asm volatile(
                    "mma.sync.aligned.m16n8k16.row.col.f32.f16.f16.f32 "
                    "{%0,%1,%2,%3}, {%4,%5,%6,%7}, {%8,%9}, {%0,%1,%2,%3};"
                    : "+f"(c[nt][0]), "+f"(c[nt][1]), "+f"(c[nt][2]), "+f"(c[nt][3])
                    : "r"(a0), "r"(a1), "r"(a2), "r"(a3), "r"(b0), "r"(b1));
            }
        }
    }
    __syncthreads();   // mainloop buffers dead; reuse as sY

    int lr = warp_m * 16 + (lane >> 2);
#pragma unroll
    for (int nt = 0; nt < 8; nt++) {
        int col = warp_n * 64 + nt * 8 + (lane & 3) * 2;
        int gr0 = m0 + lr, gr1 = gr0 + 8;
        float pb0 = proj_b[col], pb1 = proj_b[col + 1];
        float x00 = 0.f, x01 = 0.f, x10 = 0.f, x11 = 0.f;
        if (gr0 < N_NODES) {
            x00 = x[(size_t)gr0 * OUT_CH + col];
            x01 = x[(size_t)gr0 * OUT_CH + col + 1];
        }
        if (gr1 < N_NODES) {
            x10 = x[(size_t)gr1 * OUT_CH + col];
            x11 = x[(size_t)gr1 * OUT_CH + col + 1];
        }
        sY[lr * 132 + col]           = c[nt][0] + pb0 + x00;
        sY[lr * 132 + col + 1]       = c[nt][1] + pb1 + x01;
        sY[(lr + 8) * 132 + col]     = c[nt][2] + pb0 + x10;
        sY[(lr + 8) * 132 + col + 1] = c[nt][3] + pb1 + x11;
    }
    __syncthreads();

    float gg[4], bb[4];
#pragma unroll
    for (int q = 0; q < 4; q++) {
        gg[q] = lng[lane + q * 32];
        bb[q] = lnb[lane + q * 32];
    }
#pragma unroll
    for (int q = 0; q < 8; q++) {
        int r = wid * 8 + q;
        int gr = m0 + r;
        float v0 = sY[r * 132 + lane];
        float v1 = sY[r * 132 + lane + 32];
        float v2 = sY[r * 132 + lane + 64];
        float v3 = sY[r * 132 + lane + 96];
        float s1 = v0 + v1 + v2 + v3;
        float s2 = v0 * v0 + v1 * v1 + v2 * v2 + v3 * v3;
#pragma unroll
        for (int o = 16; o; o >>= 1) {
            s1 += __shfl_xor_sync(0xffffffffu, s1, o);
            s2 += __shfl_xor_sync(0xffffffffu, s2, o);
        }
        float mu = s1 * (1.f / 128.f);
        float rs = rsqrtf(s2 * (1.f / 128.f) - mu * mu + LN_EPS);
        if (gr < N_NODES) {
            out[(size_t)gr * OUT_CH + lane]      = (v0 - mu) * rs * gg[0] + bb[0];
            out[(size_t)gr * OUT_CH + lane + 32] = (v1 - mu) * rs * gg[1] + bb[1];
            out[(size_t)gr * OUT_CH + lane + 64] = (v2 - mu) * rs * gg[2] + bb[2];
            out[(size_t)gr * OUT_CH + lane + 96] = (v3 - mu) * rs * gg[3] + bb[3];
        }
    }
}

// ---------------- launch: CSR chain forked onto a side stream -----------
extern "C" void kernel_launch(void* const* d_in, const int* in_sizes, int n_in,
                              void* d_out, int out_size) {
    const float* x        = (const float*)d_in[0];
    const void*  ei       = d_in[1];
    const float* lin_w    = (const float*)d_in[2];
    const float* att_src  = (const float*)d_in[3];
    const float* att_dst  = (const float*)d_in[4];
    const float* gat_bias = (const float*)d_in[5];
    const float* proj_w   = (const float*)d_in[6];
    const float* proj_b   = (const float*)d_in[7];
    const float* ln_g     = (const float*)d_in[8];
    const float* ln_b     = (const float*)d_in[9];
    float* out = (float*)d_out;

    cudaStream_t sc;
    cudaEvent_t evF, evJ;
    cudaStreamCreateWithFlags(&sc, cudaStreamNonBlocking);
    cudaEventCreateWithFlags(&evF, cudaEventDisableTiming);
    cudaEventCreateWithFlags(&evJ, cudaEventDisableTiming);

    cudaEventRecord(evF, 0);
    cudaStreamWaitEvent(sc, evF, 0);

    // ---- side stream: proj_w pack + CSR build ----
    wconv_k<<<((HID / 2) * OUT_CH + 255) / 256, 256, 0, sc>>>(proj_w);
    initdet_k<<<(N_NODES + 255) / 256, 256, 0, sc>>>(ei);
    hist_k<<<(N_EDGES + 255) / 256, 256, 0, sc>>>(ei);
    partial_k<<<NPART, SCAN_BLK, 0, sc>>>();
    scanpart_k<<<1, 256, 0, sc>>>();
    offsets_k<<<NPART, SCAN_BLK, 0, sc>>>();
    scatter_k<<<(N_EDGES + 255) / 256, 256, 0, sc>>>(ei);
    cudaEventRecord(evJ, sc);

    // ---- main stream: feature path (attn fused into gemm1) ----
    zasrc_k<<<(N_NODES * HEADS + 255) / 256, 256>>>();
    gemm1_k<<<dim3(HID / 64, (N_NODES + 63) / 64), 256>>>(x, lin_w, att_src, att_dst);

    cudaStreamWaitEvent(0, evJ, 0);
    agg_k<<<N_NODES, 128>>>(gat_bias);
    gemm2_ln_k<<<(N_NODES + 63) / 64, 256>>>(proj_b, x, ln_g, ln_b, out);
}

// round 11
// speedup vs baseline: 2.6935x; 1.1068x over previous
#include <cuda_runtime.h>
#include <cuda_fp16.h>
#include <cstdint>

#define N_NODES 50000
#define N_EDGES 800000
#define TOT_ADJ (N_EDGES + N_NODES)
#define HID 512           // HEADS*OUT_CH
#define IN_CH 128
#define OUT_CH 128
#define HEADS 4
#define NEG_SLOPE 0.2f
#define LN_EPS 1e-5f
#define CAP 256
#define SCAN_BLK 256
#define NPART ((N_NODES + SCAN_BLK - 1) / SCAN_BLK)   // 196

// ---------------- device scratch (static, no allocation) ----------------
__device__ __half g_h16[(size_t)N_NODES * HID];    // h  (fp16, 51 MB, ~L2-resident)
__device__ __half g_act16[(size_t)N_NODES * HID];  // relu(agg + gat_bias) fp16
__device__ __half2 g_w16[(HID / 2) * OUT_CH];      // proj_w, k-pair packed fp16
__device__ __half2 g_lw16[(IN_CH / 2) * HID];      // lin_w, k-pair packed fp16
__device__ float g_asrc[N_NODES * HEADS];
__device__ float g_adst[N_NODES * HEADS];
__device__ int   g_cnt[N_NODES];
__device__ int   g_cur[N_NODES];
__device__ int   g_off[N_NODES + 1];
__device__ int   g_adj[TOT_ADJ];
__device__ int   g_part[NPART];
__device__ int   g_is64;

// ---------------- init counts + parallel dtype probe ---------------------
__global__ void initdet_k(const void* ei) {
    int i = blockIdx.x * blockDim.x + threadIdx.x;
    if (i < N_NODES) g_cnt[i] = 1;   // self loop
    if (blockIdx.x == 0 && threadIdx.x < 32) {
        const long long* p = (const long long*)ei;
        int ok = 1;
        for (int j = (int)threadIdx.x; j < 1024; j += 32) {
            long long v = p[j * 3];
            if (v < 0 || v >= N_NODES) ok = 0;
        }
        ok = __all_sync(0xffffffffu, ok);
        if (threadIdx.x == 0) g_is64 = ok;
    }
}

__device__ __forceinline__ int load_idx(const void* ei, size_t pos, int is64) {
    if (is64) return (int)((const long long*)ei)[pos];
    return ((const int*)ei)[pos];
}

__global__ void hist_k(const void* ei) {
    int i = blockIdx.x * blockDim.x + threadIdx.x;
    if (i >= N_EDGES) return;
    int d = load_idx(ei, (size_t)N_EDGES + i, g_is64);
    atomicAdd(&g_cnt[d], 1);
}

__global__ void partial_k() {
    __shared__ int sd[SCAN_BLK];
    int i = blockIdx.x * SCAN_BLK + threadIdx.x;
    sd[threadIdx.x] = (i < N_NODES) ? g_cnt[i] : 0;
    __syncthreads();
    for (int st = SCAN_BLK / 2; st; st >>= 1) {
        if (threadIdx.x < st) sd[threadIdx.x] += sd[threadIdx.x + st];
        __syncthreads();
    }
    if (threadIdx.x == 0) g_part[blockIdx.x] = sd[0];
}

__global__ void scanpart_k() {
    __shared__ int sp[256];
    int t = threadIdx.x;
    int own = (t < NPART) ? g_part[t] : 0;
    sp[t] = own;
    __syncthreads();
    for (int st = 1; st < 256; st <<= 1) {
        int v = (t >= st) ? sp[t - st] : 0;
        __syncthreads();
        sp[t] += v;
        __syncthreads();
    }
    if (t < NPART) g_part[t] = sp[t] - own;     // exclusive
    if (t == 255) g_off[N_NODES] = sp[255];     // total
}

__global__ void offsets_k() {
    __shared__ int sd[SCAN_BLK];
    int i = blockIdx.x * SCAN_BLK + threadIdx.x;
    int own = (i < N_NODES) ? g_cnt[i] : 0;
    sd[threadIdx.x] = own;
    __syncthreads();
    for (int st = 1; st < SCAN_BLK; st <<= 1) {
        int v = (threadIdx.x >= st) ? sd[threadIdx.x - st] : 0;
        __syncthreads();
        sd[threadIdx.x] += v;
        __syncthreads();
    }
    if (i < N_NODES) {
        int off = g_part[blockIdx.x] + sd[threadIdx.x] - own;
        g_off[i] = off;
        g_adj[off] = i;     // self loop first
        g_cur[i] = 1;
    }
}

__global__ void scatter_k(const void* ei) {
    int i = blockIdx.x * blockDim.x + threadIdx.x;
    if (i >= N_EDGES) return;
    int is64 = g_is64;
    int s = load_idx(ei, (size_t)i, is64);
    int d = load_idx(ei, (size_t)N_EDGES + i, is64);
    int pos = g_off[d] + atomicAdd(&g_cur[d], 1);
    g_adj[pos] = s;
}

// ---------------- zero attention accumulators ---------------------------
__global__ void zasrc_k() {
    int i = blockIdx.x * blockDim.x + threadIdx.x;
    if (i < N_NODES * HEADS) { g_asrc[i] = 0.f; g_adst[i] = 0.f; }
}

// ---------------- weight packs: k-pair fp16 ------------------------------
__global__ void wconv_k(const float* __restrict__ w) {
    int i = blockIdx.x * blockDim.x + threadIdx.x;   // kp*128 + n
    if (i >= (HID / 2) * OUT_CH) return;
    int kp = i >> 7, n = i & 127;
    g_w16[i] = __floats2half2_rn(w[(2 * kp) * OUT_CH + n],
                                 w[(2 * kp + 1) * OUT_CH + n]);
}

__global__ void lwconv_k(const float* __restrict__ w) {
    int i = blockIdx.x * blockDim.x + threadIdx.x;   // kp*512 + n
    if (i >= (IN_CH / 2) * HID) return;
    int kp = i >> 9, n = i & 511;
    g_lw16[i] = __floats2half2_rn(w[(2 * kp) * HID + n],
                                  w[(2 * kp + 1) * HID + n]);
}

// ---- GEMM1: h = x @ lin_w, fp16 mma m16n8k16, full-K resident ----------
// 64x64 tile, 256 thr (4 M-warps x 2 N-warps). smem: sA 64x68 + sB 64x72.
__global__ __launch_bounds__(256) void gemm1_k(const float* __restrict__ x,
                                               const float* __restrict__ att_src,
                                               const float* __restrict__ att_dst) {
    __shared__ uint32_t sA[64 * 68];    // 17 KB, 64 rows x 64 k-pairs (+4 pad)
    __shared__ uint32_t sB[64 * 72];    // 18 KB, 64 k-pairs x 64 n (+8 pad)
    int tid = threadIdx.x;
    int lane = tid & 31, wid = tid >> 5;
    int warp_m = wid & 3, warp_n = wid >> 2;
    int m0 = blockIdx.y * 64;
    int n0 = blockIdx.x * 64;

    // sA: x rows -> fp16 k-pairs
#pragma unroll
    for (int p = 0; p < 8; p++) {
        int idx = tid + p * 256;              // 2048 float4
        int row = idx >> 5, kp = (idx & 31) * 2;
        int gr = m0 + row;
        float4 v = (gr < N_NODES) ? *(const float4*)&x[(size_t)gr * 128 + kp * 2]
                                  : make_float4(0.f, 0.f, 0.f, 0.f);
        __half2 h0 = __floats2half2_rn(v.x, v.y);
        __half2 h1 = __floats2half2_rn(v.z, v.w);
        sA[row * 68 + kp]     = *(uint32_t*)&h0;
        sA[row * 68 + kp + 1] = *(uint32_t*)&h1;
    }
    // sB: raw copies from pre-packed g_lw16
#pragma unroll
    for (int p = 0; p < 4; p++) {
        int idx = tid + p * 256;              // 1024 uint4
        int kp = idx >> 4, q = (idx & 15) * 4;
        uint4 v = *(const uint4*)&g_lw16[(size_t)kp * HID + n0 + q];
        *(uint4*)&sB[kp * 72 + q] = v;
    }
    __syncthreads();

    float c[4][4];
#pragma unroll
    for (int nt = 0; nt < 4; nt++)
#pragma unroll
        for (int r = 0; r < 4; r++) c[nt][r] = 0.f;

    int aRow = warp_m * 16 + (lane >> 2);
    int kq = lane & 3;

#pragma unroll
    for (int ks = 0; ks < 8; ks++) {
        int o = ks * 8;                       // k-pair offset
        uint32_t a0 = sA[aRow * 68 + o + kq];
        uint32_t a1 = sA[(aRow + 8) * 68 + o + kq];
        uint32_t a2 = sA[aRow * 68 + o + kq + 4];
        uint32_t a3 = sA[(aRow + 8) * 68 + o + kq + 4];
#pragma unroll
        for (int nt = 0; nt < 4; nt++) {
            int nb = warp_n * 32 + nt * 8 + (lane >> 2);
            uint32_t b0 = sB[(o + kq) * 72 + nb];
            uint32_t b1 = sB[(o + kq + 4) * 72 + nb];
            asm volatile(
                "mma.sync.aligned.m16n8k16.row.col.f32.f16.f16.f32 "
                "{%0,%1,%2,%3}, {%4,%5,%6,%7}, {%8,%9}, {%0,%1,%2,%3};"
                : "+f"(c[nt][0]), "+f"(c[nt][1]), "+f"(c[nt][2]), "+f"(c[nt][3])
                : "r"(a0), "r"(a1), "r"(a2), "r"(a3), "r"(b0), "r"(b1));
        }
    }

    int rowA = m0 + warp_m * 16 + (lane >> 2);
    int head = n0 >> 7;    // 64-col tile lies within one head
#pragma unroll
    for (int nt = 0; nt < 4; nt++) {
        int col = n0 + warp_n * 32 + nt * 8 + (lane & 3) * 2;
        if (rowA < N_NODES)
            *(__half2*)&g_h16[(size_t)rowA * HID + col] =
                __floats2half2_rn(c[nt][0], c[nt][1]);
        if (rowA + 8 < N_NODES)
            *(__half2*)&g_h16[(size_t)(rowA + 8) * HID + col] =
                __floats2half2_rn(c[nt][2], c[nt][3]);
    }

    // fused attention dot partials
    float ps0 = 0.f, ps1 = 0.f, pd0 = 0.f, pd1 = 0.f;
#pragma unroll
    for (int nt = 0; nt < 4; nt++) {
        int cc = (n0 + warp_n * 32 + nt * 8 + (lane & 3) * 2) & 127;
        float s0 = att_src[head * 128 + cc], s1 = att_src[head * 128 + cc + 1];
        float d0 = att_dst[head * 128 + cc], d1 = att_dst[head * 128 + cc + 1];
        ps0 += c[nt][0] * s0 + c[nt][1] * s1;
        pd0 += c[nt][0] * d0 + c[nt][1] * d1;
        ps1 += c[nt][2] * s0 + c[nt][3] * s1;
        pd1 += c[nt][2] * d0 + c[nt][3] * d1;
    }
#pragma unroll
    for (int o = 1; o < 4; o <<= 1) {
        ps0 += __shfl_xor_sync(0xffffffffu, ps0, o);
        ps1 += __shfl_xor_sync(0xffffffffu, ps1, o);
        pd0 += __shfl_xor_sync(0xffffffffu, pd0, o);
        pd1 += __shfl_xor_sync(0xffffffffu, pd1, o);
    }
    if ((lane & 3) == 0) {
        if (rowA < N_NODES) {
            atomicAdd(&g_asrc[rowA * HEADS + head], ps0);
            atomicAdd(&g_adst[rowA * HEADS + head], pd0);
        }
        if (rowA + 8 < N_NODES) {
            atomicAdd(&g_asrc[(rowA + 8) * HEADS + head], ps1);
            atomicAdd(&g_adst[(rowA + 8) * HEADS + head], pd1);
        }
    }
}

// ---------------- per-node softmax + weighted aggregation ----------------
__device__ __forceinline__ float leaky(float e) { return e > 0.f ? e : NEG_SLOPE * e; }

__device__ __forceinline__ void acc8(float* acc, uint4 v, float al) {
    float2 f0 = __half22float2(*(__half2*)&v.x);
    float2 f1 = __half22float2(*(__half2*)&v.y);
    float2 f2 = __half22float2(*(__half2*)&v.z);
    float2 f3 = __half22float2(*(__half2*)&v.w);
    acc[0] += f0.x * al; acc[1] += f0.y * al;
    acc[2] += f1.x * al; acc[3] += f1.y * al;
    acc[4] += f2.x * al; acc[5] += f2.y * al;
    acc[6] += f3.x * al; acc[7] += f3.y * al;
}

__global__ __launch_bounds__(128) void agg_k(const float* __restrict__ gat_bias) {
    __shared__ int   sadj[CAP];
    __shared__ float se[HEADS][CAP];
    __shared__ float sinv[HEADS], smx[HEADS], sadh[HEADS];
    __shared__ float sacc[64][9];
    int d = blockIdx.x;
    int tid = threadIdx.x;
    int w = tid >> 5;            // warp = head (softmax phase)
    int lane = tid & 31;
    int beg = g_off[d];
    int deg = g_off[d + 1] - beg;
    float adh = g_adst[d * HEADS + w];
    bool cached = (deg <= CAP);

    float mx = -1e30f, sum = 0.f;
    if (cached) {
        for (int i = lane; i < deg; i += 32) {
            int s = g_adj[beg + i];
            if (w == 0) sadj[i] = s;
            float e = leaky(g_asrc[s * HEADS + w] + adh);
            se[w][i] = e;
            mx = fmaxf(mx, e);
        }
#pragma unroll
        for (int o = 16; o; o >>= 1) mx = fmaxf(mx, __shfl_xor_sync(0xffffffffu, mx, o));
        for (int i = lane; i < deg; i += 32) {
            float a = __expf(se[w][i] - mx);
            se[w][i] = a;
            sum += a;
        }
#pragma unroll
        for (int o = 16; o; o >>= 1) sum += __shfl_xor_sync(0xffffffffu, sum, o);
    } else {
        for (int i = lane; i < deg; i += 32) {
            int s = g_adj[beg + i];
            mx = fmaxf(mx, leaky(g_asrc[s * HEADS + w] + adh));
        }
#pragma unroll
        for (int o = 16; o; o >>= 1) mx = fmaxf(mx, __shfl_xor_sync(0xffffffffu, mx, o));
        for (int i = lane; i < deg; i += 32) {
            int s = g_adj[beg + i];
            sum += __expf(leaky(g_asrc[s * HEADS + w] + adh) - mx);
        }
#pragma unroll
        for (int o = 16; o; o >>= 1) sum += __shfl_xor_sync(0xffffffffu, sum, o);
    }
    if (lane == 0) {
        sinv[w] = 1.f / (sum + 1e-16f);
        smx[w] = mx;
        sadh[w] = adh;
    }
    __syncthreads();

    int g = tid >> 6;
    int t6 = tid & 63;
    int ch = t6 * 8;
    int head = t6 >> 4;
    float inv = sinv[head];
    float acc[8] = {0.f, 0.f, 0.f, 0.f, 0.f, 0.f, 0.f, 0.f};
    const __half* hbase = g_h16;

    if (cached) {
        int i = g;
        for (; i + 6 < deg; i += 8) {
            float al0 = se[head][i] * inv;
            float al1 = se[head][i + 2] * inv;
            float al2 = se[head][i + 4] * inv;
            float al3 = se[head][i + 6] * inv;
            uint4 v0 = *(const uint4*)&hbase[(size_t)sadj[i]     * HID + ch];
            uint4 v1 = *(const uint4*)&hbase[(size_t)sadj[i + 2] * HID + ch];
            uint4 v2 = *(const uint4*)&hbase[(size_t)sadj[i + 4] * HID + ch];
            uint4 v3 = *(const uint4*)&hbase[(size_t)sadj[i + 6] * HID + ch];
            acc8(acc, v0, al0);
            acc8(acc, v1, al1);
            acc8(acc, v2, al2);
            acc8(acc, v3, al3);
        }
        for (; i < deg; i += 2) {
            float al = se[head][i] * inv;
            uint4 v = *(const uint4*)&hbase[(size_t)sadj[i] * HID + ch];
            acc8(acc, v, al);
        }
    } else {
        float mxh = smx[head], adhh = sadh[head];
        for (int i = g; i < deg; i += 2) {
            int s = g_adj[beg + i];
            float al = __expf(leaky(g_asrc[s * HEADS + head] + adhh) - mxh) * inv;
            uint4 v = *(const uint4*)&hbase[(size_t)s * HID + ch];
            acc8(acc, v, al);
        }
    }

    if (g == 1) {
#pragma unroll
        for (int j = 0; j < 8; j++) sacc[t6][j] = acc[j];
    }
    __syncthreads();
    if (g == 0) {
        float4 b0 = *(const float4*)&gat_bias[ch];
        float4 b1 = *(const float4*)&gat_bias[ch + 4];
        float r0 = fmaxf(acc[0] + sacc[t6][0] + b0.x, 0.f);
        float r1 = fmaxf(acc[1] + sacc[t6][1] + b0.y, 0.f);
        float r2 = fmaxf(acc[2] + sacc[t6][2] + b0.z, 0.f);
        float r3 = fmaxf(acc[3] + sacc[t6][3] + b0.w, 0.f);
        float r4 = fmaxf(acc[4] + sacc[t6][4] + b1.x, 0.f);
        float r5 = fmaxf(acc[5] + sacc[t6][5] + b1.y, 0.f);
        float r6 = fmaxf(acc[6] + sacc[t6][6] + b1.z, 0.f);
        float r7 = fmaxf(acc[7] + sacc[t6][7] + b1.w, 0.f);
        uint4 st;
        *(__half2*)&st.x = __floats2half2_rn(r0, r1);
        *(__half2*)&st.y = __floats2half2_rn(r2, r3);
        *(__half2*)&st.z = __floats2half2_rn(r4, r5);
        *(__half2*)&st.w = __floats2half2_rn(r6, r7);
        *(uint4*)&g_act16[(size_t)d * HID + ch] = st;
    }
}

// ------- GEMM2 (fp16 mma m16n8k16) + bias + residual + LayerNorm --------
__global__ __launch_bounds__(256) void gemm2_ln_k(const float* __restrict__ proj_b,
                                                  const float* __restrict__ x,
                                                  const float* __restrict__ lng,
                                                  const float* __restrict__ lnb,
                                                  float* __restrict__ out) {
    __shared__ uint32_t buf[64 * 132];      // 33 KB (epilogue size), aliased
    uint32_t* sA = buf;                     // 64 x 20
    uint32_t* sB = buf + 64 * 20;           // 16 x 136
    float* sY = (float*)buf;                // 64 x 132 (epilogue)
    int tid = threadIdx.x;
    int lane = tid & 31, wid = tid >> 5;
    int warp_m = wid & 3, warp_n = wid >> 2;
    int m0 = blockIdx.x * 64;

    float c[8][4];
#pragma unroll
    for (int nt = 0; nt < 8; nt++)
#pragma unroll
        for (int r = 0; r < 4; r++) c[nt][r] = 0.f;

    int aRow = warp_m * 16 + (lane >> 2);
    int kq = lane & 3;

    for (int kc = 0; kc < HID; kc += 32) {
        __syncthreads();
#pragma unroll
        for (int p = 0; p < 2; p++) {
            int idx = tid + p * 256;          // 512
            int row = idx >> 3, h2 = (idx & 7) * 2;
            int gr = m0 + row;
            uint2 v = (gr < N_NODES)
                ? *(const uint2*)&g_act16[(size_t)gr * HID + kc + h2 * 2]
                : make_uint2(0u, 0u);
            sA[row * 20 + h2] = v.x;
            sA[row * 20 + h2 + 1] = v.y;
        }
#pragma unroll
        for (int p = 0; p < 2; p++) {
            int idx = tid + p * 256;          // 512 uint4
            int row = idx >> 5, q = (idx & 31) * 4;
            uint4 v = *(const uint4*)&g_w16[(size_t)(kc / 2 + row) * OUT_CH + q];
            *(uint4*)&sB[row * 136 + q] = v;
        }
        __syncthreads();

#pragma unroll
        for (int ks = 0; ks < 32; ks += 16) {
            int ho = ks >> 1;
            uint32_t a0 = sA[aRow * 20 + ho + kq];
            uint32_t a1 = sA[(aRow + 8) * 20 + ho + kq];
            uint32_t a2 = sA[aRow * 20 + ho + kq + 4];
            uint32_t a3 = sA[(aRow + 8) * 20 + ho + kq + 4];
#pragma unroll
            for (int nt = 0; nt < 8; nt++) {
                int nb = warp_n * 64 + nt * 8 + (lane >> 2);
                uint32_t b0 = sB[(ho + kq) * 136 + nb];
                uint32_t b1 = sB[(ho + kq + 4) * 136 + nb];
                asm volatile(
                    "mma.sync.aligned.m16n8k16.row.col.f32.f16.f16.f32 "
                    "{%0,%1,%2,%3}, {%4,%5,%6,%7}, {%8,%9}, {%0,%1,%2,%3};"
                    : "+f"(c[nt][0]), "+f"(c[nt][1]), "+f"(c[nt][2]), "+f"(c[nt][3])
                    : "r"(a0), "r"(a1), "r"(a2), "r"(a3), "r"(b0), "r"(b1));
            }
        }
    }
    __syncthreads();   // mainloop buffers dead; reuse as sY

    int lr = warp_m * 16 + (lane >> 2);
#pragma unroll
    for (int nt = 0; nt < 8; nt++) {
        int col = warp_n * 64 + nt * 8 + (lane & 3) * 2;
        int gr0 = m0 + lr, gr1 = gr0 + 8;
        float pb0 = proj_b[col], pb1 = proj_b[col + 1];
        float x00 = 0.f, x01 = 0.f, x10 = 0.f, x11 = 0.f;
        if (gr0 < N_NODES) {
            x00 = x[(size_t)gr0 * OUT_CH + col];
            x01 = x[(size_t)gr0 * OUT_CH + col + 1];
        }
        if (gr1 < N_NODES) {
            x10 = x[(size_t)gr1 * OUT_CH + col];
            x11 = x[(size_t)gr1 * OUT_CH + col + 1];
        }
        sY[lr * 132 + col]           = c[nt][0] + pb0 + x00;
        sY[lr * 132 + col + 1]       = c[nt][1] + pb1 + x01;
        sY[(lr + 8) * 132 + col]     = c[nt][2] + pb0 + x10;
        sY[(lr + 8) * 132 + col + 1] = c[nt][3] + pb1 + x11;
    }
    __syncthreads();

    float gg[4], bb[4];
#pragma unroll
    for (int q = 0; q < 4; q++) {
        gg[q] = lng[lane + q * 32];
        bb[q] = lnb[lane + q * 32];
    }
#pragma unroll
    for (int q = 0; q < 8; q++) {
        int r = wid * 8 + q;
        int gr = m0 + r;
        float v0 = sY[r * 132 + lane];
        float v1 = sY[r * 132 + lane + 32];
        float v2 = sY[r * 132 + lane + 64];
        float v3 = sY[r * 132 + lane + 96];
        float s1 = v0 + v1 + v2 + v3;
        float s2 = v0 * v0 + v1 * v1 + v2 * v2 + v3 * v3;
#pragma unroll
        for (int o = 16; o; o >>= 1) {
            s1 += __shfl_xor_sync(0xffffffffu, s1, o);
            s2 += __shfl_xor_sync(0xffffffffu, s2, o);
        }
        float mu = s1 * (1.f / 128.f);
        float rs = rsqrtf(s2 * (1.f / 128.f) - mu * mu + LN_EPS);
        if (gr < N_NODES) {
            out[(size_t)gr * OUT_CH + lane]      = (v0 - mu) * rs * gg[0] + bb[0];
            out[(size_t)gr * OUT_CH + lane + 32] = (v1 - mu) * rs * gg[1] + bb[1];
            out[(size_t)gr * OUT_CH + lane + 64] = (v2 - mu) * rs * gg[2] + bb[2];
            out[(size_t)gr * OUT_CH + lane + 96] = (v3 - mu) * rs * gg[3] + bb[3];
        }
    }
}

// ---------------- launch: CSR chain forked onto a side stream -----------
extern "C" void kernel_launch(void* const* d_in, const int* in_sizes, int n_in,
                              void* d_out, int out_size) {
    const float* x        = (const float*)d_in[0];
    const void*  ei       = d_in[1];
    const float* lin_w    = (const float*)d_in[2];
    const float* att_src  = (const float*)d_in[3];
    const float* att_dst  = (const float*)d_in[4];
    const float* gat_bias = (const float*)d_in[5];
    const float* proj_w   = (const float*)d_in[6];
    const float* proj_b   = (const float*)d_in[7];
    const float* ln_g     = (const float*)d_in[8];
    const float* ln_b     = (const float*)d_in[9];
    float* out = (float*)d_out;

    cudaStream_t sc;
    cudaEvent_t evF, evJ;
    cudaStreamCreateWithFlags(&sc, cudaStreamNonBlocking);
    cudaEventCreateWithFlags(&evF, cudaEventDisableTiming);
    cudaEventCreateWithFlags(&evJ, cudaEventDisableTiming);

    cudaEventRecord(evF, 0);
    cudaStreamWaitEvent(sc, evF, 0);

    // ---- side stream: proj_w pack + CSR build ----
    wconv_k<<<((HID / 2) * OUT_CH + 255) / 256, 256, 0, sc>>>(proj_w);
    initdet_k<<<(N_NODES + 255) / 256, 256, 0, sc>>>(ei);
    hist_k<<<(N_EDGES + 255) / 256, 256, 0, sc>>>(ei);
    partial_k<<<NPART, SCAN_BLK, 0, sc>>>();
    scanpart_k<<<1, 256, 0, sc>>>();
    offsets_k<<<NPART, SCAN_BLK, 0, sc>>>();
    scatter_k<<<(N_EDGES + 255) / 256, 256, 0, sc>>>(ei);
    cudaEventRecord(evJ, sc);

    // ---- main stream: feature path (attn fused into gemm1) ----
    lwconv_k<<<((IN_CH / 2) * HID + 255) / 256, 256>>>(lin_w);
    zasrc_k<<<(N_NODES * HEADS + 255) / 256, 256>>>();
    gemm1_k<<<dim3(HID / 64, (N_NODES + 63) / 64), 256>>>(x, att_src, att_dst);

    cudaStreamWaitEvent(0, evJ, 0);
    agg_k<<<N_NODES, 128>>>(gat_bias);
    gemm2_ln_k<<<(N_NODES + 63) / 64, 256>>>(proj_b, x, ln_g, ln_b, out);
}

// round 12
// speedup vs baseline: 2.9160x; 1.0826x over previous
#include <cuda_runtime.h>
#include <cuda_fp16.h>
#include <cstdint>

#define N_NODES 50000
#define N_EDGES 800000
#define TOT_ADJ (N_EDGES + N_NODES)
#define HID 512           // HEADS*OUT_CH
#define IN_CH 128
#define OUT_CH 128
#define HEADS 4
#define NEG_SLOPE 0.2f
#define LN_EPS 1e-5f
#define CAP 256
#define SCAN_BLK 256
#define NPART ((N_NODES + SCAN_BLK - 1) / SCAN_BLK)   // 196

// ---------------- device scratch (static, no allocation) ----------------
__device__ __half g_h16[(size_t)N_NODES * HID];    // h  (fp16, 51 MB, ~L2-resident)
__device__ __half g_act16[(size_t)N_NODES * HID];  // relu(agg + gat_bias) fp16
__device__ __half2 g_w16[(HID / 2) * OUT_CH];      // proj_w, k-pair packed fp16
__device__ __half2 g_lw16[(IN_CH / 2) * HID];      // lin_w, k-pair packed fp16
__device__ float g_asrc[N_NODES * HEADS];
__device__ float g_adst[N_NODES * HEADS];
__device__ int   g_cnt[N_NODES];
__device__ int   g_cur[N_NODES];
__device__ int   g_off[N_NODES + 1];
__device__ int   g_adj[TOT_ADJ];
__device__ int   g_part[NPART];
__device__ int   g_is64;

// ---------------- init counts + parallel dtype probe ---------------------
__global__ void initdet_k(const void* ei) {
    int i = blockIdx.x * blockDim.x + threadIdx.x;
    if (i < N_NODES) g_cnt[i] = 1;   // self loop
    if (blockIdx.x == 0 && threadIdx.x < 32) {
        const long long* p = (const long long*)ei;
        int ok = 1;
        for (int j = (int)threadIdx.x; j < 1024; j += 32) {
            long long v = p[j * 3];
            if (v < 0 || v >= N_NODES) ok = 0;
        }
        ok = __all_sync(0xffffffffu, ok);
        if (threadIdx.x == 0) g_is64 = ok;
    }
}

__device__ __forceinline__ int load_idx(const void* ei, size_t pos, int is64) {
    if (is64) return (int)((const long long*)ei)[pos];
    return ((const int*)ei)[pos];
}

__global__ void hist_k(const void* ei) {
    int i = blockIdx.x * blockDim.x + threadIdx.x;
    if (i >= N_EDGES) return;
    int d = load_idx(ei, (size_t)N_EDGES + i, g_is64);
    atomicAdd(&g_cnt[d], 1);
}

__global__ void partial_k() {
    __shared__ int sd[SCAN_BLK];
    int i = blockIdx.x * SCAN_BLK + threadIdx.x;
    sd[threadIdx.x] = (i < N_NODES) ? g_cnt[i] : 0;
    __syncthreads();
    for (int st = SCAN_BLK / 2; st; st >>= 1) {
        if (threadIdx.x < st) sd[threadIdx.x] += sd[threadIdx.x + st];
        __syncthreads();
    }
    if (threadIdx.x == 0) g_part[blockIdx.x] = sd[0];
}

__global__ void scanpart_k() {
    __shared__ int sp[256];
    int t = threadIdx.x;
    int own = (t < NPART) ? g_part[t] : 0;
    sp[t] = own;
    __syncthreads();
    for (int st = 1; st < 256; st <<= 1) {
        int v = (t >= st) ? sp[t - st] : 0;
        __syncthreads();
        sp[t] += v;
        __syncthreads();
    }
    if (t < NPART) g_part[t] = sp[t] - own;     // exclusive
    if (t == 255) g_off[N_NODES] = sp[255];     // total
}

__global__ void offsets_k() {
    __shared__ int sd[SCAN_BLK];
    int i = blockIdx.x * SCAN_BLK + threadIdx.x;
    int own = (i < N_NODES) ? g_cnt[i] : 0;
    sd[threadIdx.x] = own;
    __syncthreads();
    for (int st = 1; st < SCAN_BLK; st <<= 1) {
        int v = (threadIdx.x >= st) ? sd[threadIdx.x - st] : 0;
        __syncthreads();
        sd[threadIdx.x] += v;
        __syncthreads();
    }
    if (i < N_NODES) {
        int off = g_part[blockIdx.x] + sd[threadIdx.x] - own;
        g_off[i] = off;
        g_adj[off] = i;     // self loop first
        g_cur[i] = 1;
    }
}

__global__ void scatter_k(const void* ei) {
    int i = blockIdx.x * blockDim.x + threadIdx.x;
    if (i >= N_EDGES) return;
    int is64 = g_is64;
    int s = load_idx(ei, (size_t)i, is64);
    int d = load_idx(ei, (size_t)N_EDGES + i, is64);
    int pos = g_off[d] + atomicAdd(&g_cur[d], 1);
    g_adj[pos] = s;
}

// ---------------- weight packs: k-pair fp16 ------------------------------
__global__ void wconv_k(const float* __restrict__ w) {
    int i = blockIdx.x * blockDim.x + threadIdx.x;   // kp*128 + n
    if (i >= (HID / 2) * OUT_CH) return;
    int kp = i >> 7, n = i & 127;
    g_w16[i] = __floats2half2_rn(w[(2 * kp) * OUT_CH + n],
                                 w[(2 * kp + 1) * OUT_CH + n]);
}

__global__ void lwconv_k(const float* __restrict__ w) {
    int i = blockIdx.x * blockDim.x + threadIdx.x;   // kp*512 + n
    if (i >= (IN_CH / 2) * HID) return;
    int kp = i >> 9, n = i & 511;
    g_lw16[i] = __floats2half2_rn(w[(2 * kp) * HID + n],
                                  w[(2 * kp + 1) * HID + n]);
}

// ---- GEMM1: one block per 64 rows, loops all 8 N-tiles, sA resident ----
// attn dots complete in-block (all 4 heads visible) -> plain stores.
__global__ __launch_bounds__(256) void gemm1_k(const float* __restrict__ x,
                                               const float* __restrict__ att_src,
                                               const float* __restrict__ att_dst) {
    __shared__ uint32_t sA[64 * 68];    // 17 KB, 64 rows x 64 k-pairs (+4 pad)
    __shared__ uint32_t sB[64 * 72];    // 18 KB, 64 k-pairs x 64 n (+8 pad)
    __shared__ float sRs[64][4], sRd[64][4];   // 2 KB cross-warp_n combine
    int tid = threadIdx.x;
    int lane = tid & 31, wid = tid >> 5;
    int warp_m = wid & 3, warp_n = wid >> 2;
    int m0 = blockIdx.x * 64;

    // sA: x rows -> fp16 k-pairs (staged ONCE)
#pragma unroll
    for (int p = 0; p < 8; p++) {
        int idx = tid + p * 256;              // 2048 float4
        int row = idx >> 5, kp = (idx & 31) * 2;
        int gr = m0 + row;
        float4 v = (gr < N_NODES) ? *(const float4*)&x[(size_t)gr * 128 + kp * 2]
                                  : make_float4(0.f, 0.f, 0.f, 0.f);
        __half2 h0 = __floats2half2_rn(v.x, v.y);
        __half2 h1 = __floats2half2_rn(v.z, v.w);
        sA[row * 68 + kp]     = *(uint32_t*)&h0;
        sA[row * 68 + kp + 1] = *(uint32_t*)&h1;
    }

    int aRow = warp_m * 16 + (lane >> 2);
    int kq = lane & 3;
    int rowA = m0 + aRow;

    float psA[4] = {0.f, 0.f, 0.f, 0.f}, psB[4] = {0.f, 0.f, 0.f, 0.f};
    float pdA[4] = {0.f, 0.f, 0.f, 0.f}, pdB[4] = {0.f, 0.f, 0.f, 0.f};

#pragma unroll
    for (int t = 0; t < 8; t++) {
        int n0 = t * 64;
        int head = t >> 1;                   // compile-time via unroll
        __syncthreads();
#pragma unroll
        for (int p = 0; p < 4; p++) {
            int idx = tid + p * 256;          // 1024 uint4
            int kp = idx >> 4, q = (idx & 15) * 4;
            uint4 v = *(const uint4*)&g_lw16[(size_t)kp * HID + n0 + q];
            *(uint4*)&sB[kp * 72 + q] = v;
        }
        __syncthreads();

        float c[4][4];
#pragma unroll
        for (int nt = 0; nt < 4; nt++)
#pragma unroll
            for (int r = 0; r < 4; r++) c[nt][r] = 0.f;

#pragma unroll
        for (int ks = 0; ks < 8; ks++) {
            int o = ks * 8;
            uint32_t a0 = sA[aRow * 68 + o + kq];
            uint32_t a1 = sA[(aRow + 8) * 68 + o + kq];
            uint32_t a2 = sA[aRow * 68 + o + kq + 4];
            uint32_t a3 = sA[(aRow + 8) * 68 + o + kq + 4];
#pragma unroll
            for (int nt = 0; nt < 4; nt++) {
                int nb = warp_n * 32 + nt * 8 + (lane >> 2);
                uint32_t b0 = sB[(o + kq) * 72 + nb];
                uint32_t b1 = sB[(o + kq + 4) * 72 + nb];
                asm volatile(
                    "mma.sync.aligned.m16n8k16.row.col.f32.f16.f16.f32 "
                    "{%0,%1,%2,%3}, {%4,%5,%6,%7}, {%8,%9}, {%0,%1,%2,%3};"
                    : "+f"(c[nt][0]), "+f"(c[nt][1]), "+f"(c[nt][2]), "+f"(c[nt][3])
                    : "r"(a0), "r"(a1), "r"(a2), "r"(a3), "r"(b0), "r"(b1));
            }
        }

        // epilogue: store h tile + accumulate attn dot partials
#pragma unroll
        for (int nt = 0; nt < 4; nt++) {
            int col = n0 + warp_n * 32 + nt * 8 + (lane & 3) * 2;
            if (rowA < N_NODES)
                *(__half2*)&g_h16[(size_t)rowA * HID + col] =
                    __floats2half2_rn(c[nt][0], c[nt][1]);
            if (rowA + 8 < N_NODES)
                *(__half2*)&g_h16[(size_t)(rowA + 8) * HID + col] =
                    __floats2half2_rn(c[nt][2], c[nt][3]);
            int cc = col & 127;
            float s0 = att_src[head * 128 + cc], s1 = att_src[head * 128 + cc + 1];
            float d0 = att_dst[head * 128 + cc], d1 = att_dst[head * 128 + cc + 1];
            psA[head] += c[nt][0] * s0 + c[nt][1] * s1;
            pdA[head] += c[nt][0] * d0 + c[nt][1] * d1;
            psB[head] += c[nt][2] * s0 + c[nt][3] * s1;
            pdB[head] += c[nt][2] * d0 + c[nt][3] * d1;
        }
    }

    // quarter-warp reduce (4 lanes share a row)
#pragma unroll
    for (int h = 0; h < 4; h++) {
#pragma unroll
        for (int o = 1; o < 4; o <<= 1) {
            psA[h] += __shfl_xor_sync(0xffffffffu, psA[h], o);
            psB[h] += __shfl_xor_sync(0xffffffffu, psB[h], o);
            pdA[h] += __shfl_xor_sync(0xffffffffu, pdA[h], o);
            pdB[h] += __shfl_xor_sync(0xffffffffu, pdB[h], o);
        }
    }
    // combine warp_n=0 + warp_n=1 partials via smem, then plain stores
    int lr = warp_m * 16 + (lane >> 2);
    __syncthreads();
    if (warp_n == 1 && (lane & 3) == 0) {
#pragma unroll
        for (int h = 0; h < 4; h++) {
            sRs[lr][h] = psA[h];     sRd[lr][h] = pdA[h];
            sRs[lr + 8][h] = psB[h]; sRd[lr + 8][h] = pdB[h];
        }
    }
    __syncthreads();
    if (warp_n == 0 && (lane & 3) == 0) {
        if (rowA < N_NODES) {
#pragma unroll
            for (int h = 0; h < 4; h++) {
                g_asrc[rowA * HEADS + h] = psA[h] + sRs[lr][h];
                g_adst[rowA * HEADS + h] = pdA[h] + sRd[lr][h];
            }
        }
        if (rowA + 8 < N_NODES) {
#pragma unroll
            for (int h = 0; h < 4; h++) {
                g_asrc[(rowA + 8) * HEADS + h] = psB[h] + sRs[lr + 8][h];
                g_adst[(rowA + 8) * HEADS + h] = pdB[h] + sRd[lr + 8][h];
            }
        }
    }
}

// ---------------- per-node softmax + weighted aggregation ----------------
__device__ __forceinline__ float leaky(float e) { return e > 0.f ? e : NEG_SLOPE * e; }

__device__ __forceinline__ void acc8(float* acc, uint4 v, float al) {
    float2 f0 = __half22float2(*(__half2*)&v.x);
    float2 f1 = __half22float2(*(__half2*)&v.y);
    float2 f2 = __half22float2(*(__half2*)&v.z);
    float2 f3 = __half22float2(*(__half2*)&v.w);
    acc[0] += f0.x * al; acc[1] += f0.y * al;
    acc[2] += f1.x * al; acc[3] += f1.y * al;
    acc[4] += f2.x * al; acc[5] += f2.y * al;
    acc[6] += f3.x * al; acc[7] += f3.y * al;
}

__global__ __launch_bounds__(128) void agg_k(const float* __restrict__ gat_bias) {
    __shared__ int   sadj[CAP];
    __shared__ float se[HEADS][CAP];
    __shared__ float sinv[HEADS], smx[HEADS], sadh[HEADS];
    __shared__ float sacc[64][9];
    int d = blockIdx.x;
    int tid = threadIdx.x;
    int w = tid >> 5;            // warp = head (softmax phase)
    int lane = tid & 31;
    int beg = g_off[d];
    int deg = g_off[d + 1] - beg;
    float adh = g_adst[d * HEADS + w];
    bool cached = (deg <= CAP);

    float mx = -1e30f, sum = 0.f;
    if (cached) {
        for (int i = lane; i < deg; i += 32) {
            int s = g_adj[beg + i];
            if (w == 0) sadj[i] = s;
            float e = leaky(g_asrc[s * HEADS + w] + adh);
            se[w][i] = e;
            mx = fmaxf(mx, e);
        }
#pragma unroll
        for (int o = 16; o; o >>= 1) mx = fmaxf(mx, __shfl_xor_sync(0xffffffffu, mx, o));
        for (int i = lane; i < deg; i += 32) {
            float a = __expf(se[w][i] - mx);
            se[w][i] = a;
            sum += a;
        }
#pragma unroll
        for (int o = 16; o; o >>= 1) sum += __shfl_xor_sync(0xffffffffu, sum, o);
    } else {
        for (int i = lane; i < deg; i += 32) {
            int s = g_adj[beg + i];
            mx = fmaxf(mx, leaky(g_asrc[s * HEADS + w] + adh));
        }
#pragma unroll
        for (int o = 16; o; o >>= 1) mx = fmaxf(mx, __shfl_xor_sync(0xffffffffu, mx, o));
        for (int i = lane; i < deg; i += 32) {
            int s = g_adj[beg + i];
            sum += __expf(leaky(g_asrc[s * HEADS + w] + adh) - mx);
        }
#pragma unroll
        for (int o = 16; o; o >>= 1) sum += __shfl_xor_sync(0xffffffffu, sum, o);
    }
    if (lane == 0) {
        sinv[w] = 1.f / (sum + 1e-16f);
        smx[w] = mx;
        sadh[w] = adh;
    }
    __syncthreads();

    int g = tid >> 6;
    int t6 = tid & 63;
    int ch = t6 * 8;
    int head = t6 >> 4;
    float inv = sinv[head];
    float acc[8] = {0.f, 0.f, 0.f, 0.f, 0.f, 0.f, 0.f, 0.f};
    const __half* hbase = g_h16;

    if (cached) {
        int i = g;
        for (; i + 6 < deg; i += 8) {
            float al0 = se[head][i] * inv;
            float al1 = se[head][i + 2] * inv;
            float al2 = se[head][i + 4] * inv;
            float al3 = se[head][i + 6] * inv;
            uint4 v0 = *(const uint4*)&hbase[(size_t)sadj[i]     * HID + ch];
            uint4 v1 = *(const uint4*)&hbase[(size_t)sadj[i + 2] * HID + ch];
            uint4 v2 = *(const uint4*)&hbase[(size_t)sadj[i + 4] * HID + ch];
            uint4 v3 = *(const uint4*)&hbase[(size_t)sadj[i + 6] * HID + ch];
            acc8(acc, v0, al0);
            acc8(acc, v1, al1);
            acc8(acc, v2, al2);
            acc8(acc, v3, al3);
        }
        for (; i < deg; i += 2) {
            float al = se[head][i] * inv;
            uint4 v = *(const uint4*)&hbase[(size_t)sadj[i] * HID + ch];
            acc8(acc, v, al);
        }
    } else {
        float mxh = smx[head], adhh = sadh[head];
        for (int i = g; i < deg; i += 2) {
            int s = g_adj[beg + i];
            float al = __expf(leaky(g_asrc[s * HEADS + head] + adhh) - mxh) * inv;
            uint4 v = *(const uint4*)&hbase[(size_t)s * HID + ch];
            acc8(acc, v, al);
        }
    }

    if (g == 1) {
#pragma unroll
        for (int j = 0; j < 8; j++) sacc[t6][j] = acc[j];
    }
    __syncthreads();
    if (g == 0) {
        float4 b0 = *(const float4*)&gat_bias[ch];
        float4 b1 = *(const float4*)&gat_bias[ch + 4];
        float r0 = fmaxf(acc[0] + sacc[t6][0] + b0.x, 0.f);
        float r1 = fmaxf(acc[1] + sacc[t6][1] + b0.y, 0.f);
        float r2 = fmaxf(acc[2] + sacc[t6][2] + b0.z, 0.f);
        float r3 = fmaxf(acc[3] + sacc[t6][3] + b0.w, 0.f);
        float r4 = fmaxf(acc[4] + sacc[t6][4] + b1.x, 0.f);
        float r5 = fmaxf(acc[5] + sacc[t6][5] + b1.y, 0.f);
        float r6 = fmaxf(acc[6] + sacc[t6][6] + b1.z, 0.f);
        float r7 = fmaxf(acc[7] + sacc[t6][7] + b1.w, 0.f);
        uint4 st;
        *(__half2*)&st.x = __floats2half2_rn(r0, r1);
        *(__half2*)&st.y = __floats2half2_rn(r2, r3);
        *(__half2*)&st.z = __floats2half2_rn(r4, r5);
        *(__half2*)&st.w = __floats2half2_rn(r6, r7);
        *(uint4*)&g_act16[(size_t)d * HID + ch] = st;
    }
}

// ------- GEMM2 (fp16 mma m16n8k16) + bias + residual + LayerNorm --------
__global__ __launch_bounds__(256) void gemm2_ln_k(const float* __restrict__ proj_b,
                                                  const float* __restrict__ x,
                                                  const float* __restrict__ lng,
                                                  const float* __restrict__ lnb,
                                                  float* __restrict__ out) {
    __shared__ uint32_t buf[64 * 132];      // 33 KB (epilogue size), aliased
    uint32_t* sA = buf;                     // 64 x 20
    uint32_t* sB = buf + 64 * 20;           // 16 x 136
    float* sY = (float*)buf;                // 64 x 132 (epilogue)
    int tid = threadIdx.x;
    int lane = tid & 31, wid = tid >> 5;
    int warp_m = wid & 3, warp_n = wid >> 2;
    int m0 = blockIdx.x * 64;

    float c[8][4];
#pragma unroll
    for (int nt = 0; nt < 8; nt++)
#pragma unroll
        for (int r = 0; r < 4; r++) c[nt][r] = 0.f;

    int aRow = warp_m * 16 + (lane >> 2);
    int kq = lane & 3;

    for (int kc = 0; kc < HID; kc += 32) {
        __syncthreads();
#pragma unroll
        for (int p = 0; p < 2; p++) {
            int idx = tid + p * 256;          // 512
            int row = idx >> 3, h2 = (idx & 7) * 2;
            int gr = m0 + row;
            uint2 v = (gr < N_NODES)
                ? *(const uint2*)&g_act16[(size_t)gr * HID + kc + h2 * 2]
                : make_uint2(0u, 0u);
            sA[row * 20 + h2] = v.x;
            sA[row * 20 + h2 + 1] = v.y;
        }
#pragma unroll
        for (int p = 0; p < 2; p++) {
            int idx = tid + p * 256;          // 512 uint4
            int row = idx >> 5, q = (idx & 31) * 4;
            uint4 v = *(const uint4*)&g_w16[(size_t)(kc / 2 + row) * OUT_CH + q];
            *(uint4*)&sB[row * 136 + q] = v;
        }
        __syncthreads();

#pragma unroll
        for (int ks = 0; ks < 32; ks += 16) {
            int ho = ks >> 1;
            uint32_t a0 = sA[aRow * 20 + ho + kq];
            uint32_t a1 = sA[(aRow + 8) * 20 + ho + kq];
            uint32_t a2 = sA[aRow * 20 + ho + kq + 4];
            uint32_t a3 = sA[(aRow + 8) * 20 + ho + kq + 4];
#pragma unroll
            for (int nt = 0; nt < 8; nt++) {
                int nb = warp_n * 64 + nt * 8 + (lane >> 2);
                uint32_t b0 = sB[(ho + kq) * 136 + nb];
                uint32_t b1 = sB[(ho + kq + 4) * 136 + nb];
                asm volatile(
                    "mma.sync.aligned.m16n8k16.row.col.f32.f16.f16.f32 "
                    "{%0,%1,%2,%3}, {%4,%5,%6,%7}, {%8,%9}, {%0,%1,%2,%3};"
                    : "+f"(c[nt][0]), "+f"(c[nt][1]), "+f"(c[nt][2]), "+f"(c[nt][3])
                    : "r"(a0), "r"(a1), "r"(a2), "r"(a3), "r"(b0), "r"(b1));
            }
        }
    }
    __syncthreads();   // mainloop buffers dead; reuse as sY

    int lr = warp_m * 16 + (lane >> 2);
#pragma unroll
    for (int nt = 0; nt < 8; nt++) {
        int col = warp_n * 64 + nt * 8 + (lane & 3) * 2;
        int gr0 = m0 + lr, gr1 = gr0 + 8;
        float pb0 = proj_b[col], pb1 = proj_b[col + 1];
        float x00 = 0.f, x01 = 0.f, x10 = 0.f, x11 = 0.f;
        if (gr0 < N_NODES) {
            x00 = x[(size_t)gr0 * OUT_CH + col];
            x01 = x[(size_t)gr0 * OUT_CH + col + 1];
        }
        if (gr1 < N_NODES) {
            x10 = x[(size_t)gr1 * OUT_CH + col];
            x11 = x[(size_t)gr1 * OUT_CH + col + 1];
        }
        sY[lr * 132 + col]           = c[nt][0] + pb0 + x00;
        sY[lr * 132 + col + 1]       = c[nt][1] + pb1 + x01;
        sY[(lr + 8) * 132 + col]     = c[nt][2] + pb0 + x10;
        sY[(lr + 8) * 132 + col + 1] = c[nt][3] + pb1 + x11;
    }
    __syncthreads();

    float gg[4], bb[4];
#pragma unroll
    for (int q = 0; q < 4; q++) {
        gg[q] = lng[lane + q * 32];
        bb[q] = lnb[lane + q * 32];
    }
#pragma unroll
    for (int q = 0; q < 8; q++) {
        int r = wid * 8 + q;
        int gr = m0 + r;
        float v0 = sY[r * 132 + lane];
        float v1 = sY[r * 132 + lane + 32];
        float v2 = sY[r * 132 + lane + 64];
        float v3 = sY[r * 132 + lane + 96];
        float s1 = v0 + v1 + v2 + v3;
        float s2 = v0 * v0 + v1 * v1 + v2 * v2 + v3 * v3;
#pragma unroll
        for (int o = 16; o; o >>= 1) {
            s1 += __shfl_xor_sync(0xffffffffu, s1, o);
            s2 += __shfl_xor_sync(0xffffffffu, s2, o);
        }
        float mu = s1 * (1.f / 128.f);
        float rs = rsqrtf(s2 * (1.f / 128.f) - mu * mu + LN_EPS);
        if (gr < N_NODES) {
            out[(size_t)gr * OUT_CH + lane]      = (v0 - mu) * rs * gg[0] + bb[0];
            out[(size_t)gr * OUT_CH + lane + 32] = (v1 - mu) * rs * gg[1] + bb[1];
            out[(size_t)gr * OUT_CH + lane + 64] = (v2 - mu) * rs * gg[2] + bb[2];
            out[(size_t)gr * OUT_CH + lane + 96] = (v3 - mu) * rs * gg[3] + bb[3];
        }
    }
}

// ---------------- launch: CSR chain forked onto a side stream -----------
extern "C" void kernel_launch(void* const* d_in, const int* in_sizes, int n_in,
                              void* d_out, int out_size) {
    const float* x        = (const float*)d_in[0];
    const void*  ei       = d_in[1];
    const float* lin_w    = (const float*)d_in[2];
    const float* att_src  = (const float*)d_in[3];
    const float* att_dst  = (const float*)d_in[4];
    const float* gat_bias = (const float*)d_in[5];
    const float* proj_w   = (const float*)d_in[6];
    const float* proj_b   = (const float*)d_in[7];
    const float* ln_g     = (const float*)d_in[8];
    const float* ln_b     = (const float*)d_in[9];
    float* out = (float*)d_out;

    cudaStream_t sc;
    cudaEvent_t evF, evJ;
    cudaStreamCreateWithFlags(&sc, cudaStreamNonBlocking);
    cudaEventCreateWithFlags(&evF, cudaEventDisableTiming);
    cudaEventCreateWithFlags(&evJ, cudaEventDisableTiming);

    cudaEventRecord(evF, 0);
    cudaStreamWaitEvent(sc, evF, 0);

    // ---- side stream: proj_w pack + CSR build ----
    wconv_k<<<((HID / 2) * OUT_CH + 255) / 256, 256, 0, sc>>>(proj_w);
    initdet_k<<<(N_NODES + 255) / 256, 256, 0, sc>>>(ei);
    hist_k<<<(N_EDGES + 255) / 256, 256, 0, sc>>>(ei);
    partial_k<<<NPART, SCAN_BLK, 0, sc>>>();
    scanpart_k<<<1, 256, 0, sc>>>();
    offsets_k<<<NPART, SCAN_BLK, 0, sc>>>();
    scatter_k<<<(N_EDGES + 255) / 256, 256, 0, sc>>>(ei);
    cudaEventRecord(evJ, sc);

    // ---- main stream: feature path (attn fused into gemm1) ----
    lwconv_k<<<((IN_CH / 2) * HID + 255) / 256, 256>>>(lin_w);
    gemm1_k<<<(N_NODES + 63) / 64, 256>>>(x, att_src, att_dst);

    cudaStreamWaitEvent(0, evJ, 0);
    agg_k<<<N_NODES, 128>>>(gat_bias);
    gemm2_ln_k<<<(N_NODES + 63) / 64, 256>>>(proj_b, x, ln_g, ln_b, out);
}

// round 13
// speedup vs baseline: 3.0269x; 1.0380x over previous
#include <cuda_runtime.h>
#include <cuda_fp16.h>
#include <cstdint>

#define N_NODES 50000
#define N_EDGES 800000
#define TOT_ADJ (N_EDGES + N_NODES)
#define HID 512           // HEADS*OUT_CH
#define IN_CH 128
#define OUT_CH 128
#define HEADS 4
#define NEG_SLOPE 0.2f
#define LN_EPS 1e-5f
#define CAP 256
#define SCAN_BLK 256
#define NPART ((N_NODES + SCAN_BLK - 1) / SCAN_BLK)   // 196

// ---------------- device scratch (static, no allocation) ----------------
__device__ __half g_h16[(size_t)N_NODES * HID];    // h  (fp16, 51 MB, ~L2-resident)
__device__ __half g_act16[(size_t)N_NODES * HID];  // relu(agg + gat_bias) fp16
__device__ __half2 g_w16[(HID / 2) * OUT_CH];      // proj_w, k-pair packed fp16
__device__ __half2 g_lw16[(IN_CH / 2) * HID];      // lin_w, k-pair packed fp16
__device__ float g_asrc[N_NODES * HEADS];
__device__ float g_adst[N_NODES * HEADS];
__device__ int   g_cnt[N_NODES];
__device__ int   g_cur[N_NODES];
__device__ int   g_off[N_NODES + 1];
__device__ int   g_adj[TOT_ADJ];
__device__ int   g_part[NPART];
__device__ int   g_is64;

// ---------------- init counts + parallel dtype probe ---------------------
__global__ void initdet_k(const void* ei) {
    int i = blockIdx.x * blockDim.x + threadIdx.x;
    if (i < N_NODES) g_cnt[i] = 1;   // self loop
    if (blockIdx.x == 0 && threadIdx.x < 32) {
        const long long* p = (const long long*)ei;
        int ok = 1;
        for (int j = (int)threadIdx.x; j < 1024; j += 32) {
            long long v = p[j * 3];
            if (v < 0 || v >= N_NODES) ok = 0;
        }
        ok = __all_sync(0xffffffffu, ok);
        if (threadIdx.x == 0) g_is64 = ok;
    }
}

__device__ __forceinline__ int load_idx(const void* ei, size_t pos, int is64) {
    if (is64) return (int)((const long long*)ei)[pos];
    return ((const int*)ei)[pos];
}

__global__ void hist_k(const void* ei) {
    int i = blockIdx.x * blockDim.x + threadIdx.x;
    if (i >= N_EDGES) return;
    int d = load_idx(ei, (size_t)N_EDGES + i, g_is64);
    atomicAdd(&g_cnt[d], 1);
}

__global__ void partial_k() {
    __shared__ int sd[SCAN_BLK];
    int i = blockIdx.x * SCAN_BLK + threadIdx.x;
    sd[threadIdx.x] = (i < N_NODES) ? g_cnt[i] : 0;
    __syncthreads();
    for (int st = SCAN_BLK / 2; st; st >>= 1) {
        if (threadIdx.x < st) sd[threadIdx.x] += sd[threadIdx.x + st];
        __syncthreads();
    }
    if (threadIdx.x == 0) g_part[blockIdx.x] = sd[0];
}

__global__ void scanpart_k() {
    __shared__ int sp[256];
    int t = threadIdx.x;
    int own = (t < NPART) ? g_part[t] : 0;
    sp[t] = own;
    __syncthreads();
    for (int st = 1; st < 256; st <<= 1) {
        int v = (t >= st) ? sp[t - st] : 0;
        __syncthreads();
        sp[t] += v;
        __syncthreads();
    }
    if (t < NPART) g_part[t] = sp[t] - own;     // exclusive
    if (t == 255) g_off[N_NODES] = sp[255];     // total
}

__global__ void offsets_k() {
    __shared__ int sd[SCAN_BLK];
    int i = blockIdx.x * SCAN_BLK + threadIdx.x;
    int own = (i < N_NODES) ? g_cnt[i] : 0;
    sd[threadIdx.x] = own;
    __syncthreads();
    for (int st = 1; st < SCAN_BLK; st <<= 1) {
        int v = (threadIdx.x >= st) ? sd[threadIdx.x - st] : 0;
        __syncthreads();
        sd[threadIdx.x] += v;
        __syncthreads();
    }
    if (i < N_NODES) {
        int off = g_part[blockIdx.x] + sd[threadIdx.x] - own;
        g_off[i] = off;
        g_adj[off] = i;     // self loop first
        g_cur[i] = 1;
    }
}

__global__ void scatter_k(const void* ei) {
    int i = blockIdx.x * blockDim.x + threadIdx.x;
    if (i >= N_EDGES) return;
    int is64 = g_is64;
    int s = load_idx(ei, (size_t)i, is64);
    int d = load_idx(ei, (size_t)N_EDGES + i, is64);
    int pos = g_off[d] + atomicAdd(&g_cur[d], 1);
    g_adj[pos] = s;
}

// ---------------- weight packs: k-pair fp16 ------------------------------
__global__ void wconv_k(const float* __restrict__ w) {
    int i = blockIdx.x * blockDim.x + threadIdx.x;   // kp*128 + n
    if (i >= (HID / 2) * OUT_CH) return;
    int kp = i >> 7, n = i & 127;
    g_w16[i] = __floats2half2_rn(w[(2 * kp) * OUT_CH + n],
                                 w[(2 * kp + 1) * OUT_CH + n]);
}

__global__ void lwconv_k(const float* __restrict__ w) {
    int i = blockIdx.x * blockDim.x + threadIdx.x;   // kp*512 + n
    if (i >= (IN_CH / 2) * HID) return;
    int kp = i >> 9, n = i & 511;
    g_lw16[i] = __floats2half2_rn(w[(2 * kp) * HID + n],
                                  w[(2 * kp + 1) * HID + n]);
}

// ---- GEMM1: one block per 64 rows, loops all 8 N-tiles, sA resident ----
__global__ __launch_bounds__(256) void gemm1_k(const float* __restrict__ x,
                                               const float* __restrict__ att_src,
                                               const float* __restrict__ att_dst) {
    __shared__ uint32_t sA[64 * 68];    // 17 KB
    __shared__ uint32_t sB[64 * 72];    // 18 KB
    __shared__ float sRs[64][4], sRd[64][4];   // 2 KB cross-warp_n combine
    int tid = threadIdx.x;
    int lane = tid & 31, wid = tid >> 5;
    int warp_m = wid & 3, warp_n = wid >> 2;
    int m0 = blockIdx.x * 64;

#pragma unroll
    for (int p = 0; p < 8; p++) {
        int idx = tid + p * 256;
        int row = idx >> 5, kp = (idx & 31) * 2;
        int gr = m0 + row;
        float4 v = (gr < N_NODES) ? *(const float4*)&x[(size_t)gr * 128 + kp * 2]
                                  : make_float4(0.f, 0.f, 0.f, 0.f);
        __half2 h0 = __floats2half2_rn(v.x, v.y);
        __half2 h1 = __floats2half2_rn(v.z, v.w);
        sA[row * 68 + kp]     = *(uint32_t*)&h0;
        sA[row * 68 + kp + 1] = *(uint32_t*)&h1;
    }

    int aRow = warp_m * 16 + (lane >> 2);
    int kq = lane & 3;
    int rowA = m0 + aRow;

    float psA[4] = {0.f, 0.f, 0.f, 0.f}, psB[4] = {0.f, 0.f, 0.f, 0.f};
    float pdA[4] = {0.f, 0.f, 0.f, 0.f}, pdB[4] = {0.f, 0.f, 0.f, 0.f};

#pragma unroll
    for (int t = 0; t < 8; t++) {
        int n0 = t * 64;
        int head = t >> 1;
        __syncthreads();
#pragma unroll
        for (int p = 0; p < 4; p++) {
            int idx = tid + p * 256;
            int kp = idx >> 4, q = (idx & 15) * 4;
            uint4 v = *(const uint4*)&g_lw16[(size_t)kp * HID + n0 + q];
            *(uint4*)&sB[kp * 72 + q] = v;
        }
        __syncthreads();

        float c[4][4];
#pragma unroll
        for (int nt = 0; nt < 4; nt++)
#pragma unroll
            for (int r = 0; r < 4; r++) c[nt][r] = 0.f;

#pragma unroll
        for (int ks = 0; ks < 8; ks++) {
            int o = ks * 8;
            uint32_t a0 = sA[aRow * 68 + o + kq];
            uint32_t a1 = sA[(aRow + 8) * 68 + o + kq];
            uint32_t a2 = sA[aRow * 68 + o + kq + 4];
            uint32_t a3 = sA[(aRow + 8) * 68 + o + kq + 4];
#pragma unroll
            for (int nt = 0; nt < 4; nt++) {
                int nb = warp_n * 32 + nt * 8 + (lane >> 2);
                uint32_t b0 = sB[(o + kq) * 72 + nb];
                uint32_t b1 = sB[(o + kq + 4) * 72 + nb];
                asm volatile(
                    "mma.sync.aligned.m16n8k16.row.col.f32.f16.f16.f32 "
                    "{%0,%1,%2,%3}, {%4,%5,%6,%7}, {%8,%9}, {%0,%1,%2,%3};"
                    : "+f"(c[nt][0]), "+f"(c[nt][1]), "+f"(c[nt][2]), "+f"(c[nt][3])
                    : "r"(a0), "r"(a1), "r"(a2), "r"(a3), "r"(b0), "r"(b1));
            }
        }

#pragma unroll
        for (int nt = 0; nt < 4; nt++) {
            int col = n0 + warp_n * 32 + nt * 8 + (lane & 3) * 2;
            if (rowA < N_NODES)
                *(__half2*)&g_h16[(size_t)rowA * HID + col] =
                    __floats2half2_rn(c[nt][0], c[nt][1]);
            if (rowA + 8 < N_NODES)
                *(__half2*)&g_h16[(size_t)(rowA + 8) * HID + col] =
                    __floats2half2_rn(c[nt][2], c[nt][3]);
            int cc = col & 127;
            float s0 = att_src[head * 128 + cc], s1 = att_src[head * 128 + cc + 1];
            float d0 = att_dst[head * 128 + cc], d1 = att_dst[head * 128 + cc + 1];
            psA[head] += c[nt][0] * s0 + c[nt][1] * s1;
            pdA[head] += c[nt][0] * d0 + c[nt][1] * d1;
            psB[head] += c[nt][2] * s0 + c[nt][3] * s1;
            pdB[head] += c[nt][2] * d0 + c[nt][3] * d1;
        }
    }

#pragma unroll
    for (int h = 0; h < 4; h++) {
#pragma unroll
        for (int o = 1; o < 4; o <<= 1) {
            psA[h] += __shfl_xor_sync(0xffffffffu, psA[h], o);
            psB[h] += __shfl_xor_sync(0xffffffffu, psB[h], o);
            pdA[h] += __shfl_xor_sync(0xffffffffu, pdA[h], o);
            pdB[h] += __shfl_xor_sync(0xffffffffu, pdB[h], o);
        }
    }
    int lr = warp_m * 16 + (lane >> 2);
    __syncthreads();
    if (warp_n == 1 && (lane & 3) == 0) {
#pragma unroll
        for (int h = 0; h < 4; h++) {
            sRs[lr][h] = psA[h];     sRd[lr][h] = pdA[h];
            sRs[lr + 8][h] = psB[h]; sRd[lr + 8][h] = pdB[h];
        }
    }
    __syncthreads();
    if (warp_n == 0 && (lane & 3) == 0) {
        if (rowA < N_NODES) {
#pragma unroll
            for (int h = 0; h < 4; h++) {
                g_asrc[rowA * HEADS + h] = psA[h] + sRs[lr][h];
                g_adst[rowA * HEADS + h] = pdA[h] + sRd[lr][h];
            }
        }
        if (rowA + 8 < N_NODES) {
#pragma unroll
            for (int h = 0; h < 4; h++) {
                g_asrc[(rowA + 8) * HEADS + h] = psB[h] + sRs[lr + 8][h];
                g_adst[(rowA + 8) * HEADS + h] = pdB[h] + sRd[lr + 8][h];
            }
        }
    }
}

// ---------------- per-node softmax + weighted aggregation ----------------
// Single-pass softmax (no max-subtraction: e bounded, exp()/sum identical).
__device__ __forceinline__ float leaky(float e) { return e > 0.f ? e : NEG_SLOPE * e; }

__device__ __forceinline__ void acc8(float* acc, uint4 v, float al) {
    float2 f0 = __half22float2(*(__half2*)&v.x);
    float2 f1 = __half22float2(*(__half2*)&v.y);
    float2 f2 = __half22float2(*(__half2*)&v.z);
    float2 f3 = __half22float2(*(__half2*)&v.w);
    acc[0] += f0.x * al; acc[1] += f0.y * al;
    acc[2] += f1.x * al; acc[3] += f1.y * al;
    acc[4] += f2.x * al; acc[5] += f2.y * al;
    acc[6] += f3.x * al; acc[7] += f3.y * al;
}

__global__ __launch_bounds__(128) void agg_k(const float* __restrict__ gat_bias) {
    __shared__ int   sadj[CAP];
    __shared__ float se[HEADS][CAP];
    __shared__ float sinv[HEADS], sadh[HEADS];
    __shared__ float sacc[64][9];
    int d = blockIdx.x;
    int tid = threadIdx.x;
    int w = tid >> 5;            // warp = head (softmax phase)
    int lane = tid & 31;
    int beg = g_off[d];
    int deg = g_off[d + 1] - beg;
    float adh = g_adst[d * HEADS + w];
    bool cached = (deg <= CAP);

    float sum = 0.f;
    if (cached) {
        for (int i = lane; i < deg; i += 32) {
            int s = g_adj[beg + i];
            if (w == 0) sadj[i] = s;
            float a = __expf(leaky(g_asrc[s * HEADS + w] + adh));
            se[w][i] = a;
            sum += a;
        }
    } else {
        for (int i = lane; i < deg; i += 32) {
            int s = g_adj[beg + i];
            sum += __expf(leaky(g_asrc[s * HEADS + w] + adh));
        }
    }
#pragma unroll
    for (int o = 16; o; o >>= 1) sum += __shfl_xor_sync(0xffffffffu, sum, o);
    if (lane == 0) {
        sinv[w] = 1.f / (sum + 1e-16f);
        sadh[w] = adh;
    }
    __syncthreads();

    int g = tid >> 6;
    int t6 = tid & 63;
    int ch = t6 * 8;
    int head = t6 >> 4;
    float inv = sinv[head];
    float acc[8] = {0.f, 0.f, 0.f, 0.f, 0.f, 0.f, 0.f, 0.f};
    const __half* hbase = g_h16;

    if (cached) {
        int i = g;
        for (; i + 6 < deg; i += 8) {
            float al0 = se[head][i] * inv;
            float al1 = se[head][i + 2] * inv;
            float al2 = se[head][i + 4] * inv;
            float al3 = se[head][i + 6] * inv;
            uint4 v0 = *(const uint4*)&hbase[(size_t)sadj[i]     * HID + ch];
            uint4 v1 = *(const uint4*)&hbase[(size_t)sadj[i + 2] * HID + ch];
            uint4 v2 = *(const uint4*)&hbase[(size_t)sadj[i + 4] * HID + ch];
            uint4 v3 = *(const uint4*)&hbase[(size_t)sadj[i + 6] * HID + ch];
            acc8(acc, v0, al0);
            acc8(acc, v1, al1);
            acc8(acc, v2, al2);
            acc8(acc, v3, al3);
        }
        for (; i < deg; i += 2) {
            float al = se[head][i] * inv;
            uint4 v = *(const uint4*)&hbase[(size_t)sadj[i] * HID + ch];
            acc8(acc, v, al);
        }
    } else {
        float adhh = sadh[head];
        for (int i = g; i < deg; i += 2) {
            int s = g_adj[beg + i];
            float al = __expf(leaky(g_asrc[s * HEADS + head] + adhh)) * inv;
            uint4 v = *(const uint4*)&hbase[(size_t)s * HID + ch];
            acc8(acc, v, al);
        }
    }

    if (g == 1) {
#pragma unroll
        for (int j = 0; j < 8; j++) sacc[t6][j] = acc[j];
    }
    __syncthreads();
    if (g == 0) {
        float4 b0 = *(const float4*)&gat_bias[ch];
        float4 b1 = *(const float4*)&gat_bias[ch + 4];
        float r0 = fmaxf(acc[0] + sacc[t6][0] + b0.x, 0.f);
        float r1 = fmaxf(acc[1] + sacc[t6][1] + b0.y, 0.f);
        float r2 = fmaxf(acc[2] + sacc[t6][2] + b0.z, 0.f);
        float r3 = fmaxf(acc[3] + sacc[t6][3] + b0.w, 0.f);
        float r4 = fmaxf(acc[4] + sacc[t6][4] + b1.x, 0.f);
        float r5 = fmaxf(acc[5] + sacc[t6][5] + b1.y, 0.f);
        float r6 = fmaxf(acc[6] + sacc[t6][6] + b1.z, 0.f);
        float r7 = fmaxf(acc[7] + sacc[t6][7] + b1.w, 0.f);
        uint4 st;
        *(__half2*)&st.x = __floats2half2_rn(r0, r1);
        *(__half2*)&st.y = __floats2half2_rn(r2, r3);
        *(__half2*)&st.z = __floats2half2_rn(r4, r5);
        *(__half2*)&st.w = __floats2half2_rn(r6, r7);
        *(uint4*)&g_act16[(size_t)d * HID + ch] = st;
    }
}

// ------- GEMM2 (fp16 mma) + bias + residual + LayerNorm (register LN) ---
__global__ __launch_bounds__(256) void gemm2_ln_k(const float* __restrict__ proj_b,
                                                  const float* __restrict__ x,
                                                  const float* __restrict__ lng,
                                                  const float* __restrict__ lnb,
                                                  float* __restrict__ out) {
    __shared__ uint32_t sA[64 * 20];        // 5 KB
    __shared__ uint32_t sB[16 * 136];       // 8.5 KB
    __shared__ float sP1[2][64], sP2[2][64];// 1 KB LN partials per warp_n
    int tid = threadIdx.x;
    int lane = tid & 31, wid = tid >> 5;
    int warp_m = wid & 3, warp_n = wid >> 2;
    int m0 = blockIdx.x * 64;

    float c[8][4];
#pragma unroll
    for (int nt = 0; nt < 8; nt++)
#pragma unroll
        for (int r = 0; r < 4; r++) c[nt][r] = 0.f;

    int aRow = warp_m * 16 + (lane >> 2);
    int kq = lane & 3;

    for (int kc = 0; kc < HID; kc += 32) {
        __syncthreads();
#pragma unroll
        for (int p = 0; p < 2; p++) {
            int idx = tid + p * 256;
            int row = idx >> 3, h2 = (idx & 7) * 2;
            int gr = m0 + row;
            uint2 v = (gr < N_NODES)
                ? *(const uint2*)&g_act16[(size_t)gr * HID + kc + h2 * 2]
                : make_uint2(0u, 0u);
            sA[row * 20 + h2] = v.x;
            sA[row * 20 + h2 + 1] = v.y;
        }
#pragma unroll
        for (int p = 0; p < 2; p++) {
            int idx = tid + p * 256;
            int row = idx >> 5, q = (idx & 31) * 4;
            uint4 v = *(const uint4*)&g_w16[(size_t)(kc / 2 + row) * OUT_CH + q];
            *(uint4*)&sB[row * 136 + q] = v;
        }
        __syncthreads();

#pragma unroll
        for (int ks = 0; ks < 32; ks += 16) {
            int ho = ks >> 1;
            uint32_t a0 = sA[aRow * 20 + ho + kq];
            uint32_t a1 = sA[(aRow + 8) * 20 + ho + kq];
            uint32_t a2 = sA[aRow * 20 + ho + kq + 4];
            uint32_t a3 = sA[(aRow + 8) * 20 + ho + kq + 4];
#pragma unroll
            for (int nt = 0; nt < 8; nt++) {
                int nb = warp_n * 64 + nt * 8 + (lane >> 2);
                uint32_t b0 = sB[(ho + kq) * 136 + nb];
                uint32_t b1 = sB[(ho + kq + 4) * 136 + nb];
                asm volatile(
                    "mma.sync.aligned.m16n8k16.row.col.f32.f16.f16.f32 "
                    "{%0,%1,%2,%3}, {%4,%5,%6,%7}, {%8,%9}, {%0,%1,%2,%3};"
                    : "+f"(c[nt][0]), "+f"(c[nt][1]), "+f"(c[nt][2]), "+f"(c[nt][3])
                    : "r"(a0), "r"(a1), "r"(a2), "r"(a3), "r"(b0), "r"(b1));
            }
        }
    }

    // epilogue: y = c + proj_b + x (registers), then register LN
    int lr = warp_m * 16 + (lane >> 2);
    int gr0 = m0 + lr, gr1 = gr0 + 8;
    float s1r0 = 0.f, s2r0 = 0.f, s1r1 = 0.f, s2r1 = 0.f;
#pragma unroll
    for (int nt = 0; nt < 8; nt++) {
        int col = warp_n * 64 + nt * 8 + (lane & 3) * 2;
        float pb0 = proj_b[col], pb1 = proj_b[col + 1];
        float x00 = 0.f, x01 = 0.f, x10 = 0.f, x11 = 0.f;
        if (gr0 < N_NODES) {
            x00 = x[(size_t)gr0 * OUT_CH + col];
            x01 = x[(size_t)gr0 * OUT_CH + col + 1];
        }
        if (gr1 < N_NODES) {
            x10 = x[(size_t)gr1 * OUT_CH + col];
            x11 = x[(size_t)gr1 * OUT_CH + col + 1];
        }
        c[nt][0] += pb0 + x00;
        c[nt][1] += pb1 + x01;
        c[nt][2] += pb0 + x10;
        c[nt][3] += pb1 + x11;
        s1r0 += c[nt][0] + c[nt][1];
        s2r0 += c[nt][0] * c[nt][0] + c[nt][1] * c[nt][1];
        s1r1 += c[nt][2] + c[nt][3];
        s2r1 += c[nt][2] * c[nt][2] + c[nt][3] * c[nt][3];
    }
    // quarter-warp reduce (offsets 1,2 stay within the 4-lane group)
#pragma unroll
    for (int o = 1; o < 4; o <<= 1) {
        s1r0 += __shfl_xor_sync(0xffffffffu, s1r0, o);
        s2r0 += __shfl_xor_sync(0xffffffffu, s2r0, o);
        s1r1 += __shfl_xor_sync(0xffffffffu, s1r1, o);
        s2r1 += __shfl_xor_sync(0xffffffffu, s2r1, o);
    }
    __syncthreads();
    if ((lane & 3) == 0) {
        sP1[warp_n][lr] = s1r0;     sP2[warp_n][lr] = s2r0;
        sP1[warp_n][lr + 8] = s1r1; sP2[warp_n][lr + 8] = s2r1;
    }
    __syncthreads();
    float t1r0 = sP1[0][lr] + sP1[1][lr];
    float t2r0 = sP2[0][lr] + sP2[1][lr];
    float t1r1 = sP1[0][lr + 8] + sP1[1][lr + 8];
    float t2r1 = sP2[0][lr + 8] + sP2[1][lr + 8];
    float mu0 = t1r0 * (1.f / 128.f);
    float rs0 = rsqrtf(t2r0 * (1.f / 128.f) - mu0 * mu0 + LN_EPS);
    float mu1 = t1r1 * (1.f / 128.f);
    float rs1 = rsqrtf(t2r1 * (1.f / 128.f) - mu1 * mu1 + LN_EPS);

#pragma unroll
    for (int nt = 0; nt < 8; nt++) {
        int col = warp_n * 64 + nt * 8 + (lane & 3) * 2;
        float g0 = lng[col], g1 = lng[col + 1];
        float b0 = lnb[col], b1 = lnb[col + 1];
        if (gr0 < N_NODES) {
            float2 o0 = make_float2((c[nt][0] - mu0) * rs0 * g0 + b0,
                                    (c[nt][1] - mu0) * rs0 * g1 + b1);
            *(float2*)&out[(size_t)gr0 * OUT_CH + col] = o0;
        }
        if (gr1 < N_NODES) {
            float2 o1 = make_float2((c[nt][2] - mu1) * rs1 * g0 + b0,
                                    (c[nt][3] - mu1) * rs1 * g1 + b1);
            *(float2*)&out[(size_t)gr1 * OUT_CH + col] = o1;
        }
    }
}

// ---------------- launch: CSR chain forked onto a side stream -----------
extern "C" void kernel_launch(void* const* d_in, const int* in_sizes, int n_in,
                              void* d_out, int out_size) {
    const float* x        = (const float*)d_in[0];
    const void*  ei       = d_in[1];
    const float* lin_w    = (const float*)d_in[2];
    const float* att_src  = (const float*)d_in[3];
    const float* att_dst  = (const float*)d_in[4];
    const float* gat_bias = (const float*)d_in[5];
    const float* proj_w   = (const float*)d_in[6];
    const float* proj_b   = (const float*)d_in[7];
    const float* ln_g     = (const float*)d_in[8];
    const float* ln_b     = (const float*)d_in[9];
    float* out = (float*)d_out;

    cudaStream_t sc;
    cudaEvent_t evF, evJ;
    cudaStreamCreateWithFlags(&sc, cudaStreamNonBlocking);
    cudaEventCreateWithFlags(&evF, cudaEventDisableTiming);
    cudaEventCreateWithFlags(&evJ, cudaEventDisableTiming);

    cudaEventRecord(evF, 0);
    cudaStreamWaitEvent(sc, evF, 0);

    // ---- side stream: proj_w pack + CSR build ----
    wconv_k<<<((HID / 2) * OUT_CH + 255) / 256, 256, 0, sc>>>(proj_w);
    initdet_k<<<(N_NODES + 255) / 256, 256, 0, sc>>>(ei);
    hist_k<<<(N_EDGES + 255) / 256, 256, 0, sc>>>(ei);
    partial_k<<<NPART, SCAN_BLK, 0, sc>>>();
    scanpart_k<<<1, 256, 0, sc>>>();
    offsets_k<<<NPART, SCAN_BLK, 0, sc>>>();
    scatter_k<<<(N_EDGES + 255) / 256, 256, 0, sc>>>(ei);
    cudaEventRecord(evJ, sc);

    // ---- main stream: feature path (attn fused into gemm1) ----
    lwconv_k<<<((IN_CH / 2) * HID + 255) / 256, 256>>>(lin_w);
    gemm1_k<<<(N_NODES + 63) / 64, 256>>>(x, att_src, att_dst);

    cudaStreamWaitEvent(0, evJ, 0);
    agg_k<<<N_NODES, 128>>>(gat_bias);
    gemm2_ln_k<<<(N_NODES + 63) / 64, 256>>>(proj_b, x, ln_g, ln_b, out);
}

// round 14
// speedup vs baseline: 3.0449x; 1.0059x over previous
#include <cuda_runtime.h>
#include <cuda_fp16.h>
#include <cstdint>

#define N_NODES 50000
#define N_EDGES 800000
#define TOT_ADJ (N_EDGES + N_NODES)
#define HID 512           // HEADS*OUT_CH
#define IN_CH 128
#define OUT_CH 128
#define HEADS 4
#define NEG_SLOPE 0.2f
#define LN_EPS 1e-5f
#define CAP 256
#define SCAN_BLK 256
#define NPART ((N_NODES + SCAN_BLK - 1) / SCAN_BLK)   // 196

// ---------------- device scratch (static, no allocation) ----------------
__device__ __half g_h16[(size_t)N_NODES * HID];    // h  (fp16, 51 MB, ~L2-resident)
__device__ __half g_act16[(size_t)N_NODES * HID];  // relu(agg + gat_bias) fp16
__device__ __half2 g_w16[(HID / 2) * OUT_CH];      // proj_w, k-pair packed fp16
__device__ __half2 g_lw16[(IN_CH / 2) * HID];      // lin_w, k-pair packed fp16
__device__ float g_asrc[N_NODES * HEADS];
__device__ float g_adst[N_NODES * HEADS];
__device__ int   g_cnt[N_NODES];
__device__ int   g_cur[N_NODES];
__device__ int   g_off[N_NODES + 1];
__device__ int   g_adj[TOT_ADJ];
__device__ int   g_part[NPART];
__device__ int   g_is64;

// ---------------- init counts + parallel dtype probe ---------------------
__global__ void initdet_k(const void* ei) {
    int i = blockIdx.x * blockDim.x + threadIdx.x;
    if (i < N_NODES) g_cnt[i] = 1;   // self loop
    if (blockIdx.x == 0 && threadIdx.x < 32) {
        const long long* p = (const long long*)ei;
        int ok = 1;
        for (int j = (int)threadIdx.x; j < 1024; j += 32) {
            long long v = p[j * 3];
            if (v < 0 || v >= N_NODES) ok = 0;
        }
        ok = __all_sync(0xffffffffu, ok);
        if (threadIdx.x == 0) g_is64 = ok;
    }
}

__device__ __forceinline__ int load_idx(const void* ei, size_t pos, int is64) {
    if (is64) return (int)((const long long*)ei)[pos];
    return ((const int*)ei)[pos];
}

__global__ void hist_k(const void* ei) {
    int i = blockIdx.x * blockDim.x + threadIdx.x;
    if (i >= N_EDGES) return;
    int d = load_idx(ei, (size_t)N_EDGES + i, g_is64);
    atomicAdd(&g_cnt[d], 1);
}

__global__ void partial_k() {
    __shared__ int sd[SCAN_BLK];
    int i = blockIdx.x * SCAN_BLK + threadIdx.x;
    sd[threadIdx.x] = (i < N_NODES) ? g_cnt[i] : 0;
    __syncthreads();
    for (int st = SCAN_BLK / 2; st; st >>= 1) {
        if (threadIdx.x < st) sd[threadIdx.x] += sd[threadIdx.x + st];
        __syncthreads();
    }
    if (threadIdx.x == 0) g_part[blockIdx.x] = sd[0];
}

__global__ void scanpart_k() {
    __shared__ int sp[256];
    int t = threadIdx.x;
    int own = (t < NPART) ? g_part[t] : 0;
    sp[t] = own;
    __syncthreads();
    for (int st = 1; st < 256; st <<= 1) {
        int v = (t >= st) ? sp[t - st] : 0;
        __syncthreads();
        sp[t] += v;
        __syncthreads();
    }
    if (t < NPART) g_part[t] = sp[t] - own;     // exclusive
    if (t == 255) g_off[N_NODES] = sp[255];     // total
}

__global__ void offsets_k() {
    __shared__ int sd[SCAN_BLK];
    int i = blockIdx.x * SCAN_BLK + threadIdx.x;
    int own = (i < N_NODES) ? g_cnt[i] : 0;
    sd[threadIdx.x] = own;
    __syncthreads();
    for (int st = 1; st < SCAN_BLK; st <<= 1) {
        int v = (threadIdx.x >= st) ? sd[threadIdx.x - st] : 0;
        __syncthreads();
        sd[threadIdx.x] += v;
        __syncthreads();
    }
    if (i < N_NODES) {
        int off = g_part[blockIdx.x] + sd[threadIdx.x] - own;
        g_off[i] = off;
        g_adj[off] = i;     // self loop first
        g_cur[i] = 1;
    }
}

__global__ void scatter_k(const void* ei) {
    int i = blockIdx.x * blockDim.x + threadIdx.x;
    if (i >= N_EDGES) return;
    int is64 = g_is64;
    int s = load_idx(ei, (size_t)i, is64);
    int d = load_idx(ei, (size_t)N_EDGES + i, is64);
    int pos = g_off[d] + atomicAdd(&g_cur[d], 1);
    g_adj[pos] = s;
}

// ---------------- weight packs: k-pair fp16 ------------------------------
__global__ void wconv_k(const float* __restrict__ w) {
    int i = blockIdx.x * blockDim.x + threadIdx.x;   // kp*128 + n
    if (i >= (HID / 2) * OUT_CH) return;
    int kp = i >> 7, n = i & 127;
    g_w16[i] = __floats2half2_rn(w[(2 * kp) * OUT_CH + n],
                                 w[(2 * kp + 1) * OUT_CH + n]);
}

__global__ void lwconv_k(const float* __restrict__ w) {
    int i = blockIdx.x * blockDim.x + threadIdx.x;   // kp*512 + n
    if (i >= (IN_CH / 2) * HID) return;
    int kp = i >> 9, n = i & 511;
    g_lw16[i] = __floats2half2_rn(w[(2 * kp) * HID + n],
                                  w[(2 * kp + 1) * HID + n]);
}

// ---- GEMM1: one block per 64 rows, loops all 8 N-tiles, sA resident ----
__global__ __launch_bounds__(256) void gemm1_k(const float* __restrict__ x,
                                               const float* __restrict__ att_src,
                                               const float* __restrict__ att_dst) {
    __shared__ uint32_t sA[64 * 68];    // 17 KB
    __shared__ uint32_t sB[64 * 72];    // 18 KB
    __shared__ float sRs[64][4], sRd[64][4];   // 2 KB cross-warp_n combine
    int tid = threadIdx.x;
    int lane = tid & 31, wid = tid >> 5;
    int warp_m = wid & 3, warp_n = wid >> 2;
    int m0 = blockIdx.x * 64;

#pragma unroll
    for (int p = 0; p < 8; p++) {
        int idx = tid + p * 256;
        int row = idx >> 5, kp = (idx & 31) * 2;
        int gr = m0 + row;
        float4 v = (gr < N_NODES) ? *(const float4*)&x[(size_t)gr * 128 + kp * 2]
                                  : make_float4(0.f, 0.f, 0.f, 0.f);
        __half2 h0 = __floats2half2_rn(v.x, v.y);
        __half2 h1 = __floats2half2_rn(v.z, v.w);
        sA[row * 68 + kp]     = *(uint32_t*)&h0;
        sA[row * 68 + kp + 1] = *(uint32_t*)&h1;
    }

    int aRow = warp_m * 16 + (lane >> 2);
    int kq = lane & 3;
    int rowA = m0 + aRow;

    float psA[4] = {0.f, 0.f, 0.f, 0.f}, psB[4] = {0.f, 0.f, 0.f, 0.f};
    float pdA[4] = {0.f, 0.f, 0.f, 0.f}, pdB[4] = {0.f, 0.f, 0.f, 0.f};

#pragma unroll
    for (int t = 0; t < 8; t++) {
        int n0 = t * 64;
        int head = t >> 1;
        __syncthreads();
#pragma unroll
        for (int p = 0; p < 4; p++) {
            int idx = tid + p * 256;
            int kp = idx >> 4, q = (idx & 15) * 4;
            uint4 v = *(const uint4*)&g_lw16[(size_t)kp * HID + n0 + q];
            *(uint4*)&sB[kp * 72 + q] = v;
        }
        __syncthreads();

        float c[4][4];
#pragma unroll
        for (int nt = 0; nt < 4; nt++)
#pragma unroll
            for (int r = 0; r < 4; r++) c[nt][r] = 0.f;

#pragma unroll
        for (int ks = 0; ks < 8; ks++) {
            int o = ks * 8;
            uint32_t a0 = sA[aRow * 68 + o + kq];
            uint32_t a1 = sA[(aRow + 8) * 68 + o + kq];
            uint32_t a2 = sA[aRow * 68 + o + kq + 4];
            uint32_t a3 = sA[(aRow + 8) * 68 + o + kq + 4];
#pragma unroll
            for (int nt = 0; nt < 4; nt++) {
                int nb = warp_n * 32 + nt * 8 + (lane >> 2);
                uint32_t b0 = sB[(o + kq) * 72 + nb];
                uint32_t b1 = sB[(o + kq + 4) * 72 + nb];
                asm volatile(
                    "mma.sync.aligned.m16n8k16.row.col.f32.f16.f16.f32 "
                    "{%0,%1,%2,%3}, {%4,%5,%6,%7}, {%8,%9}, {%0,%1,%2,%3};"
                    : "+f"(c[nt][0]), "+f"(c[nt][1]), "+f"(c[nt][2]), "+f"(c[nt][3])
                    : "r"(a0), "r"(a1), "r"(a2), "r"(a3), "r"(b0), "r"(b1));
            }
        }

#pragma unroll
        for (int nt = 0; nt < 4; nt++) {
            int col = n0 + warp_n * 32 + nt * 8 + (lane & 3) * 2;
            if (rowA < N_NODES)
                *(__half2*)&g_h16[(size_t)rowA * HID + col] =
                    __floats2half2_rn(c[nt][0], c[nt][1]);
            if (rowA + 8 < N_NODES)
                *(__half2*)&g_h16[(size_t)(rowA + 8) * HID + col] =
                    __floats2half2_rn(c[nt][2], c[nt][3]);
            int cc = col & 127;
            float s0 = att_src[head * 128 + cc], s1 = att_src[head * 128 + cc + 1];
            float d0 = att_dst[head * 128 + cc], d1 = att_dst[head * 128 + cc + 1];
            psA[head] += c[nt][0] * s0 + c[nt][1] * s1;
            pdA[head] += c[nt][0] * d0 + c[nt][1] * d1;
            psB[head] += c[nt][2] * s0 + c[nt][3] * s1;
            pdB[head] += c[nt][2] * d0 + c[nt][3] * d1;
        }
    }

#pragma unroll
    for (int h = 0; h < 4; h++) {
#pragma unroll
        for (int o = 1; o < 4; o <<= 1) {
            psA[h] += __shfl_xor_sync(0xffffffffu, psA[h], o);
            psB[h] += __shfl_xor_sync(0xffffffffu, psB[h], o);
            pdA[h] += __shfl_xor_sync(0xffffffffu, pdA[h], o);
            pdB[h] += __shfl_xor_sync(0xffffffffu, pdB[h], o);
        }
    }
    int lr = warp_m * 16 + (lane >> 2);
    __syncthreads();
    if (warp_n == 1 && (lane & 3) == 0) {
#pragma unroll
        for (int h = 0; h < 4; h++) {
            sRs[lr][h] = psA[h];     sRd[lr][h] = pdA[h];
            sRs[lr + 8][h] = psB[h]; sRd[lr + 8][h] = pdB[h];
        }
    }
    __syncthreads();
    if (warp_n == 0 && (lane & 3) == 0) {
        if (rowA < N_NODES) {
#pragma unroll
            for (int h = 0; h < 4; h++) {
                g_asrc[rowA * HEADS + h] = psA[h] + sRs[lr][h];
                g_adst[rowA * HEADS + h] = pdA[h] + sRd[lr][h];
            }
        }
        if (rowA + 8 < N_NODES) {
#pragma unroll
            for (int h = 0; h < 4; h++) {
                g_asrc[(rowA + 8) * HEADS + h] = psB[h] + sRs[lr + 8][h];
                g_adst[(rowA + 8) * HEADS + h] = pdB[h] + sRd[lr + 8][h];
            }
        }
    }
}

// ---------------- per-node softmax + weighted aggregation ----------------
// Single-pass softmax over edges spread across all 128 threads (float4 asrc).
__device__ __forceinline__ float leaky(float e) { return e > 0.f ? e : NEG_SLOPE * e; }

__device__ __forceinline__ void acc8(float* acc, uint4 v, float al) {
    float2 f0 = __half22float2(*(__half2*)&v.x);
    float2 f1 = __half22float2(*(__half2*)&v.y);
    float2 f2 = __half22float2(*(__half2*)&v.z);
    float2 f3 = __half22float2(*(__half2*)&v.w);
    acc[0] += f0.x * al; acc[1] += f0.y * al;
    acc[2] += f1.x * al; acc[3] += f1.y * al;
    acc[4] += f2.x * al; acc[5] += f2.y * al;
    acc[6] += f3.x * al; acc[7] += f3.y * al;
}

__global__ __launch_bounds__(128) void agg_k(const float* __restrict__ gat_bias) {
    __shared__ int   sadj[CAP];
    __shared__ float se[HEADS][CAP];
    __shared__ float sinv[HEADS], sadh[HEADS];
    __shared__ float swsum[4][HEADS];
    __shared__ float sacc[64][9];
    int d = blockIdx.x;
    int tid = threadIdx.x;
    int w = tid >> 5, lane = tid & 31;
    int beg = g_off[d];
    int deg = g_off[d + 1] - beg;
    bool cached = (deg <= CAP);
    float4 adv = *(const float4*)&g_adst[d * HEADS];

    float s0 = 0.f, s1 = 0.f, s2 = 0.f, s3 = 0.f;
    if (cached) {
        for (int i = tid; i < deg; i += 128) {
            int s = g_adj[beg + i];
            sadj[i] = s;
            float4 as = *(const float4*)&g_asrc[s * HEADS];
            float a0 = __expf(leaky(as.x + adv.x)); se[0][i] = a0; s0 += a0;
            float a1 = __expf(leaky(as.y + adv.y)); se[1][i] = a1; s1 += a1;
            float a2 = __expf(leaky(as.z + adv.z)); se[2][i] = a2; s2 += a2;
            float a3 = __expf(leaky(as.w + adv.w)); se[3][i] = a3; s3 += a3;
        }
    } else {
        for (int i = tid; i < deg; i += 128) {
            int s = g_adj[beg + i];
            float4 as = *(const float4*)&g_asrc[s * HEADS];
            s0 += __expf(leaky(as.x + adv.x));
            s1 += __expf(leaky(as.y + adv.y));
            s2 += __expf(leaky(as.z + adv.z));
            s3 += __expf(leaky(as.w + adv.w));
        }
    }
#pragma unroll
    for (int o = 16; o; o >>= 1) {
        s0 += __shfl_xor_sync(0xffffffffu, s0, o);
        s1 += __shfl_xor_sync(0xffffffffu, s1, o);
        s2 += __shfl_xor_sync(0xffffffffu, s2, o);
        s3 += __shfl_xor_sync(0xffffffffu, s3, o);
    }
    if (lane == 0) {
        swsum[w][0] = s0; swsum[w][1] = s1;
        swsum[w][2] = s2; swsum[w][3] = s3;
    }
    if (tid < HEADS) {
        float v = tid == 0 ? adv.x : tid == 1 ? adv.y : tid == 2 ? adv.z : adv.w;
        sadh[tid] = v;
    }
    __syncthreads();
    if (tid < HEADS) {
        float t = swsum[0][tid] + swsum[1][tid] + swsum[2][tid] + swsum[3][tid];
        sinv[tid] = 1.f / (t + 1e-16f);
    }
    __syncthreads();

    int g = tid >> 6;
    int t6 = tid & 63;
    int ch = t6 * 8;
    int head = t6 >> 4;
    float inv = sinv[head];
    float acc[8] = {0.f, 0.f, 0.f, 0.f, 0.f, 0.f, 0.f, 0.f};
    const __half* hbase = g_h16;

    if (cached) {
        int i = g;
        for (; i + 6 < deg; i += 8) {
            float al0 = se[head][i] * inv;
            float al1 = se[head][i + 2] * inv;
            float al2 = se[head][i + 4] * inv;
            float al3 = se[head][i + 6] * inv;
            uint4 v0 = *(const uint4*)&hbase[(size_t)sadj[i]     * HID + ch];
            uint4 v1 = *(const uint4*)&hbase[(size_t)sadj[i + 2] * HID + ch];
            uint4 v2 = *(const uint4*)&hbase[(size_t)sadj[i + 4] * HID + ch];
            uint4 v3 = *(const uint4*)&hbase[(size_t)sadj[i + 6] * HID + ch];
            acc8(acc, v0, al0);
            acc8(acc, v1, al1);
            acc8(acc, v2, al2);
            acc8(acc, v3, al3);
        }
        for (; i < deg; i += 2) {
            float al = se[head][i] * inv;
            uint4 v = *(const uint4*)&hbase[(size_t)sadj[i] * HID + ch];
            acc8(acc, v, al);
        }
    } else {
        float adhh = sadh[head];
        for (int i = g; i < deg; i += 2) {
            int s = g_adj[beg + i];
            float al = __expf(leaky(g_asrc[s * HEADS + head] + adhh)) * inv;
            uint4 v = *(const uint4*)&hbase[(size_t)s * HID + ch];
            acc8(acc, v, al);
        }
    }

    if (g == 1) {
#pragma unroll
        for (int j = 0; j < 8; j++) sacc[t6][j] = acc[j];
    }
    __syncthreads();
    if (g == 0) {
        float4 b0 = *(const float4*)&gat_bias[ch];
        float4 b1 = *(const float4*)&gat_bias[ch + 4];
        float r0 = fmaxf(acc[0] + sacc[t6][0] + b0.x, 0.f);
        float r1 = fmaxf(acc[1] + sacc[t6][1] + b0.y, 0.f);
        float r2 = fmaxf(acc[2] + sacc[t6][2] + b0.z, 0.f);
        float r3 = fmaxf(acc[3] + sacc[t6][3] + b0.w, 0.f);
        float r4 = fmaxf(acc[4] + sacc[t6][4] + b1.x, 0.f);
        float r5 = fmaxf(acc[5] + sacc[t6][5] + b1.y, 0.f);
        float r6 = fmaxf(acc[6] + sacc[t6][6] + b1.z, 0.f);
        float r7 = fmaxf(acc[7] + sacc[t6][7] + b1.w, 0.f);
        uint4 st;
        *(__half2*)&st.x = __floats2half2_rn(r0, r1);
        *(__half2*)&st.y = __floats2half2_rn(r2, r3);
        *(__half2*)&st.z = __floats2half2_rn(r4, r5);
        *(__half2*)&st.w = __floats2half2_rn(r6, r7);
        *(uint4*)&g_act16[(size_t)d * HID + ch] = st;
    }
}

// ------- GEMM2 (fp16 mma, 64-K chunks) + bias + residual + register LN ---
__global__ __launch_bounds__(256) void gemm2_ln_k(const float* __restrict__ proj_b,
                                                  const float* __restrict__ x,
                                                  const float* __restrict__ lng,
                                                  const float* __restrict__ lnb,
                                                  float* __restrict__ out) {
    __shared__ uint32_t sA[64 * 36];        // 9 KB (64 rows x 32 k-pairs)
    __shared__ uint32_t sB[32 * 136];       // 17 KB (32 k-pairs x 128 n)
    __shared__ float sP1[2][64], sP2[2][64];// 1 KB LN partials per warp_n
    int tid = threadIdx.x;
    int lane = tid & 31, wid = tid >> 5;
    int warp_m = wid & 3, warp_n = wid >> 2;
    int m0 = blockIdx.x * 64;

    float c[8][4];
#pragma unroll
    for (int nt = 0; nt < 8; nt++)
#pragma unroll
        for (int r = 0; r < 4; r++) c[nt][r] = 0.f;

    int aRow = warp_m * 16 + (lane >> 2);
    int kq = lane & 3;

    for (int kc = 0; kc < HID; kc += 64) {
        __syncthreads();
        // sA: 64 rows x 32 k-pairs
#pragma unroll
        for (int p = 0; p < 4; p++) {
            int idx = tid + p * 256;          // 1024 uint2
            int row = idx >> 4, h2 = (idx & 15) * 2;
            int gr = m0 + row;
            uint2 v = (gr < N_NODES)
                ? *(const uint2*)&g_act16[(size_t)gr * HID + kc + h2 * 2]
                : make_uint2(0u, 0u);
            sA[row * 36 + h2] = v.x;
            sA[row * 36 + h2 + 1] = v.y;
        }
        // sB: 32 k-pairs x 128 n
#pragma unroll
        for (int p = 0; p < 4; p++) {
            int idx = tid + p * 256;          // 1024 uint4
            int row = idx >> 5, q = (idx & 31) * 4;
            uint4 v = *(const uint4*)&g_w16[(size_t)(kc / 2 + row) * OUT_CH + q];
            *(uint4*)&sB[row * 136 + q] = v;
        }
        __syncthreads();

#pragma unroll
        for (int ks = 0; ks < 64; ks += 16) {
            int ho = ks >> 1;                 // 0,8,16,24
            uint32_t a0 = sA[aRow * 36 + ho + kq];
            uint32_t a1 = sA[(aRow + 8) * 36 + ho + kq];
            uint32_t a2 = sA[aRow * 36 + ho + kq + 4];
            uint32_t a3 = sA[(aRow + 8) * 36 + ho + kq + 4];
#pragma unroll
            for (int nt = 0; nt < 8; nt++) {
                int nb = warp_n * 64 + nt * 8 + (lane >> 2);
                uint32_t b0 = sB[(ho + kq) * 136 + nb];
                uint32_t b1 = sB[(ho + kq + 4) * 136 + nb];
                asm volatile(
                    "mma.sync.aligned.m16n8k16.row.col.f32.f16.f16.f32 "
                    "{%0,%1,%2,%3}, {%4,%5,%6,%7}, {%8,%9}, {%0,%1,%2,%3};"
                    : "+f"(c[nt][0]), "+f"(c[nt][1]), "+f"(c[nt][2]), "+f"(c[nt][3])
                    : "r"(a0), "r"(a1), "r"(a2), "r"(a3), "r"(b0), "r"(b1));
            }
        }
    }

    // epilogue: y = c + proj_b + x (registers), then register LN
    int lr = warp_m * 16 + (lane >> 2);
    int gr0 = m0 + lr, gr1 = gr0 + 8;
    float s1r0 = 0.f, s2r0 = 0.f, s1r1 = 0.f, s2r1 = 0.f;
#pragma unroll
    for (int nt = 0; nt < 8; nt++) {
        int col = warp_n * 64 + nt * 8 + (lane & 3) * 2;
        float pb0 = proj_b[col], pb1 = proj_b[col + 1];
        float x00 = 0.f, x01 = 0.f, x10 = 0.f, x11 = 0.f;
        if (gr0 < N_NODES) {
            x00 = x[(size_t)gr0 * OUT_CH + col];
            x01 = x[(size_t)gr0 * OUT_CH + col + 1];
        }
        if (gr1 < N_NODES) {
            x10 = x[(size_t)gr1 * OUT_CH + col];
            x11 = x[(size_t)gr1 * OUT_CH + col + 1];
        }
        c[nt][0] += pb0 + x00;
        c[nt][1] += pb1 + x01;
        c[nt][2] += pb0 + x10;
        c[nt][3] += pb1 + x11;
        s1r0 += c[nt][0] + c[nt][1];
        s2r0 += c[nt][0] * c[nt][0] + c[nt][1] * c[nt][1];
        s1r1 += c[nt][2] + c[nt][3];
        s2r1 += c[nt][2] * c[nt][2] + c[nt][3] * c[nt][3];
    }
#pragma unroll
    for (int o = 1; o < 4; o <<= 1) {
        s1r0 += __shfl_xor_sync(0xffffffffu, s1r0, o);
        s2r0 += __shfl_xor_sync(0xffffffffu, s2r0, o);
        s1r1 += __shfl_xor_sync(0xffffffffu, s1r1, o);
        s2r1 += __shfl_xor_sync(0xffffffffu, s2r1, o);
    }
    __syncthreads();
    if ((lane & 3) == 0) {
        sP1[warp_n][lr] = s1r0;     sP2[warp_n][lr] = s2r0;
        sP1[warp_n][lr + 8] = s1r1; sP2[warp_n][lr + 8] = s2r1;
    }
    __syncthreads();
    float t1r0 = sP1[0][lr] + sP1[1][lr];
    float t2r0 = sP2[0][lr] + sP2[1][lr];
    float t1r1 = sP1[0][lr + 8] + sP1[1][lr + 8];
    float t2r1 = sP2[0][lr + 8] + sP2[1][lr + 8];
    float mu0 = t1r0 * (1.f / 128.f);
    float rs0 = rsqrtf(t2r0 * (1.f / 128.f) - mu0 * mu0 + LN_EPS);
    float mu1 = t1r1 * (1.f / 128.f);
    float rs1 = rsqrtf(t2r1 * (1.f / 128.f) - mu1 * mu1 + LN_EPS);

#pragma unroll
    for (int nt = 0; nt < 8; nt++) {
        int col = warp_n * 64 + nt * 8 + (lane & 3) * 2;
        float g0 = lng[col], g1 = lng[col + 1];
        float b0 = lnb[col], b1 = lnb[col + 1];
        if (gr0 < N_NODES) {
            float2 o0 = make_float2((c[nt][0] - mu0) * rs0 * g0 + b0,
                                    (c[nt][1] - mu0) * rs0 * g1 + b1);
            *(float2*)&out[(size_t)gr0 * OUT_CH + col] = o0;
        }
        if (gr1 < N_NODES) {
            float2 o1 = make_float2((c[nt][2] - mu1) * rs1 * g0 + b0,
                                    (c[nt][3] - mu1) * rs1 * g1 + b1);
            *(float2*)&out[(size_t)gr1 * OUT_CH + col] = o1;
        }
    }
}

// ---------------- launch: CSR chain forked onto a side stream -----------
extern "C" void kernel_launch(void* const* d_in, const int* in_sizes, int n_in,
                              void* d_out, int out_size) {
    const float* x        = (const float*)d_in[0];
    const void*  ei       = d_in[1];
    const float* lin_w    = (const float*)d_in[2];
    const float* att_src  = (const float*)d_in[3];
    const float* att_dst  = (const float*)d_in[4];
    const float* gat_bias = (const float*)d_in[5];
    const float* proj_w   = (const float*)d_in[6];
    const float* proj_b   = (const float*)d_in[7];
    const float* ln_g     = (const float*)d_in[8];
    const float* ln_b     = (const float*)d_in[9];
    float* out = (float*)d_out;

    cudaStream_t sc;
    cudaEvent_t evF, evJ;
    cudaStreamCreateWithFlags(&sc, cudaStreamNonBlocking);
    cudaEventCreateWithFlags(&evF, cudaEventDisableTiming);
    cudaEventCreateWithFlags(&evJ, cudaEventDisableTiming);

    cudaEventRecord(evF, 0);
    cudaStreamWaitEvent(sc, evF, 0);

    // ---- side stream: proj_w pack + CSR build ----
    wconv_k<<<((HID / 2) * OUT_CH + 255) / 256, 256, 0, sc>>>(proj_w);
    initdet_k<<<(N_NODES + 255) / 256, 256, 0, sc>>>(ei);
    hist_k<<<(N_EDGES + 255) / 256, 256, 0, sc>>>(ei);
    partial_k<<<NPART, SCAN_BLK, 0, sc>>>();
    scanpart_k<<<1, 256, 0, sc>>>();
    offsets_k<<<NPART, SCAN_BLK, 0, sc>>>();
    scatter_k<<<(N_EDGES + 255) / 256, 256, 0, sc>>>(ei);
    cudaEventRecord(evJ, sc);

    // ---- main stream: feature path (attn fused into gemm1) ----
    lwconv_k<<<((IN_CH / 2) * HID + 255) / 256, 256>>>(lin_w);
    gemm1_k<<<(N_NODES + 63) / 64, 256>>>(x, att_src, att_dst);

    cudaStreamWaitEvent(0, evJ, 0);
    agg_k<<<N_NODES, 128>>>(gat_bias);
    gemm2_ln_k<<<(N_NODES + 63) / 64, 256>>>(proj_b, x, ln_g, ln_b, out);
}

// round 15
// speedup vs baseline: 3.0655x; 1.0068x over previous
#include <cuda_runtime.h>
#include <cuda_fp16.h>
#include <cstdint>

#define N_NODES 50000
#define N_EDGES 800000
#define TOT_ADJ (N_EDGES + N_NODES)
#define HID 512           // HEADS*OUT_CH
#define IN_CH 128
#define OUT_CH 128
#define HEADS 4
#define NEG_SLOPE 0.2f
#define LN_EPS 1e-5f
#define CAP 256
#define SCAN_BLK 256
#define NPART ((N_NODES + SCAN_BLK - 1) / SCAN_BLK)   // 196

// ---------------- device scratch (static, no allocation) ----------------
__device__ __half g_h16[(size_t)N_NODES * HID];    // h  (fp16, 51 MB, ~L2-resident)
__device__ __half g_act16[(size_t)N_NODES * HID];  // relu(agg + gat_bias) fp16
__device__ __half2 g_w16[(HID / 2) * OUT_CH];      // proj_w, k-pair packed fp16
__device__ __half2 g_lw16[(IN_CH / 2) * HID];      // lin_w, k-pair packed fp16
__device__ float g_asrc[N_NODES * HEADS];
__device__ float g_adst[N_NODES * HEADS];
__device__ int   g_cnt[N_NODES];
__device__ int   g_cur[N_NODES];
__device__ int   g_off[N_NODES + 1];
__device__ int   g_adj[TOT_ADJ];
__device__ int   g_part[NPART];
__device__ int   g_is64;

// ------- zero counts + parallel dtype probe (self-loops added analytically)
__global__ void initdet_k(const void* ei) {
    int i = blockIdx.x * blockDim.x + threadIdx.x;
    if (i < N_NODES) g_cnt[i] = 0;
    if (blockIdx.x == 0 && threadIdx.x < 32) {
        const long long* p = (const long long*)ei;
        int ok = 1;
        for (int j = (int)threadIdx.x; j < 1024; j += 32) {
            long long v = p[j * 3];
            if (v < 0 || v >= N_NODES) ok = 0;
        }
        ok = __all_sync(0xffffffffu, ok);
        if (threadIdx.x == 0) g_is64 = ok;
    }
}

__device__ __forceinline__ int load_idx(const void* ei, size_t pos, int is64) {
    if (is64) return (int)((const long long*)ei)[pos];
    return ((const int*)ei)[pos];
}

__global__ void hist_k(const void* ei) {
    int i = blockIdx.x * blockDim.x + threadIdx.x;
    if (i >= N_EDGES) return;
    int d = load_idx(ei, (size_t)N_EDGES + i, g_is64);
    atomicAdd(&g_cnt[d], 1);
}

__global__ void partial_k() {
    __shared__ int sd[SCAN_BLK];
    int i = blockIdx.x * SCAN_BLK + threadIdx.x;
    sd[threadIdx.x] = (i < N_NODES) ? g_cnt[i] : 0;
    __syncthreads();
    for (int st = SCAN_BLK / 2; st; st >>= 1) {
        if (threadIdx.x < st) sd[threadIdx.x] += sd[threadIdx.x + st];
        __syncthreads();
    }
    if (threadIdx.x == 0) g_part[blockIdx.x] = sd[0];
}

// fused: per-block base (sum of partials below) + local scan + offsets +
// self-loop seed.  off[i] = edge_prefix(i) + i  (the +i covers self loops).
__global__ void scanoff_k() {
    __shared__ int sd[SCAN_BLK];
    __shared__ int sbase;
    int tid = threadIdx.x;
    int i = blockIdx.x * SCAN_BLK + tid;

    if (tid < 32) {
        int s = 0;
        for (int j = tid; j < blockIdx.x; j += 32) s += g_part[j];
#pragma unroll
        for (int o = 16; o; o >>= 1) s += __shfl_xor_sync(0xffffffffu, s, o);
        if (tid == 0) sbase = s;
    }

    int own = (i < N_NODES) ? g_cnt[i] : 0;
    sd[tid] = own;
    __syncthreads();
    for (int st = 1; st < SCAN_BLK; st <<= 1) {
        int v = (tid >= st) ? sd[tid - st] : 0;
        __syncthreads();
        sd[tid] += v;
        __syncthreads();
    }
    if (i < N_NODES) {
        int off = sbase + (sd[tid] - own) + i;   // +i = self loops before node i
        g_off[i] = off;
        g_adj[off] = i;      // self loop first
        g_cur[i] = 1;
        if (i == N_NODES - 1) g_off[N_NODES] = off + own + 1;
    }
}

__global__ void scatter_k(const void* ei) {
    int i = blockIdx.x * blockDim.x + threadIdx.x;
    if (i >= N_EDGES) return;
    int is64 = g_is64;
    int s = load_idx(ei, (size_t)i, is64);
    int d = load_idx(ei, (size_t)N_EDGES + i, is64);
    int pos = g_off[d] + atomicAdd(&g_cur[d], 1);
    g_adj[pos] = s;
}

// ---------------- weight packs: k-pair fp16 ------------------------------
__global__ void wconv_k(const float* __restrict__ w) {
    int i = blockIdx.x * blockDim.x + threadIdx.x;   // kp*128 + n
    if (i >= (HID / 2) * OUT_CH) return;
    int kp = i >> 7, n = i & 127;
    g_w16[i] = __floats2half2_rn(w[(2 * kp) * OUT_CH + n],
                                 w[(2 * kp + 1) * OUT_CH + n]);
}

__global__ void lwconv_k(const float* __restrict__ w) {
    int i = blockIdx.x * blockDim.x + threadIdx.x;   // kp*512 + n
    if (i >= (IN_CH / 2) * HID) return;
    int kp = i >> 9, n = i & 511;
    g_lw16[i] = __floats2half2_rn(w[(2 * kp) * HID + n],
                                  w[(2 * kp + 1) * HID + n]);
}

// ---- GEMM1: one block per 64 rows, loops all 8 N-tiles, sA resident ----
__global__ __launch_bounds__(256) void gemm1_k(const float* __restrict__ x,
                                               const float* __restrict__ att_src,
                                               const float* __restrict__ att_dst) {
    __shared__ uint32_t sA[64 * 68];    // 17 KB
    __shared__ uint32_t sB[64 * 72];    // 18 KB
    __shared__ float sRs[64][4], sRd[64][4];   // 2 KB cross-warp_n combine
    int tid = threadIdx.x;
    int lane = tid & 31, wid = tid >> 5;
    int warp_m = wid & 3, warp_n = wid >> 2;
    int m0 = blockIdx.x * 64;

#pragma unroll
    for (int p = 0; p < 8; p++) {
        int idx = tid + p * 256;
        int row = idx >> 5, kp = (idx & 31) * 2;
        int gr = m0 + row;
        float4 v = (gr < N_NODES) ? *(const float4*)&x[(size_t)gr * 128 + kp * 2]
                                  : make_float4(0.f, 0.f, 0.f, 0.f);
        __half2 h0 = __floats2half2_rn(v.x, v.y);
        __half2 h1 = __floats2half2_rn(v.z, v.w);
        sA[row * 68 + kp]     = *(uint32_t*)&h0;
        sA[row * 68 + kp + 1] = *(uint32_t*)&h1;
    }

    int aRow = warp_m * 16 + (lane >> 2);
    int kq = lane & 3;
    int rowA = m0 + aRow;

    float psA[4] = {0.f, 0.f, 0.f, 0.f}, psB[4] = {0.f, 0.f, 0.f, 0.f};
    float pdA[4] = {0.f, 0.f, 0.f, 0.f}, pdB[4] = {0.f, 0.f, 0.f, 0.f};

#pragma unroll
    for (int t = 0; t < 8; t++) {
        int n0 = t * 64;
        int head = t >> 1;
        __syncthreads();
#pragma unroll
        for (int p = 0; p < 4; p++) {
            int idx = tid + p * 256;
            int kp = idx >> 4, q = (idx & 15) * 4;
            uint4 v = *(const uint4*)&g_lw16[(size_t)kp * HID + n0 + q];
            *(uint4*)&sB[kp * 72 + q] = v;
        }
        __syncthreads();

        float c[4][4];
#pragma unroll
        for (int nt = 0; nt < 4; nt++)
#pragma unroll
            for (int r = 0; r < 4; r++) c[nt][r] = 0.f;

#pragma unroll
        for (int ks = 0; ks < 8; ks++) {
            int o = ks * 8;
            uint32_t a0 = sA[aRow * 68 + o + kq];
            uint32_t a1 = sA[(aRow + 8) * 68 + o + kq];
            uint32_t a2 = sA[aRow * 68 + o + kq + 4];
            uint32_t a3 = sA[(aRow + 8) * 68 + o + kq + 4];
#pragma unroll
            for (int nt = 0; nt < 4; nt++) {
                int nb = warp_n * 32 + nt * 8 + (lane >> 2);
                uint32_t b0 = sB[(o + kq) * 72 + nb];
                uint32_t b1 = sB[(o + kq + 4) * 72 + nb];
                asm volatile(
                    "mma.sync.aligned.m16n8k16.row.col.f32.f16.f16.f32 "
                    "{%0,%1,%2,%3}, {%4,%5,%6,%7}, {%8,%9}, {%0,%1,%2,%3};"
                    : "+f"(c[nt][0]), "+f"(c[nt][1]), "+f"(c[nt][2]), "+f"(c[nt][3])
                    : "r"(a0), "r"(a1), "r"(a2), "r"(a3), "r"(b0), "r"(b1));
            }
        }

#pragma unroll
        for (int nt = 0; nt < 4; nt++) {
            int col = n0 + warp_n * 32 + nt * 8 + (lane & 3) * 2;
            if (rowA < N_NODES)
                *(__half2*)&g_h16[(size_t)rowA * HID + col] =
                    __floats2half2_rn(c[nt][0], c[nt][1]);
            if (rowA + 8 < N_NODES)
                *(__half2*)&g_h16[(size_t)(rowA + 8) * HID + col] =
                    __floats2half2_rn(c[nt][2], c[nt][3]);
            int cc = col & 127;
            float s0 = att_src[head * 128 + cc], s1 = att_src[head * 128 + cc + 1];
            float d0 = att_dst[head * 128 + cc], d1 = att_dst[head * 128 + cc + 1];
            psA[head] += c[nt][0] * s0 + c[nt][1] * s1;
            pdA[head] += c[nt][0] * d0 + c[nt][1] * d1;
            psB[head] += c[nt][2] * s0 + c[nt][3] * s1;
            pdB[head] += c[nt][2] * d0 + c[nt][3] * d1;
        }
    }

#pragma unroll
    for (int h = 0; h < 4; h++) {
#pragma unroll
        for (int o = 1; o < 4; o <<= 1) {
            psA[h] += __shfl_xor_sync(0xffffffffu, psA[h], o);
            psB[h] += __shfl_xor_sync(0xffffffffu, psB[h], o);
            pdA[h] += __shfl_xor_sync(0xffffffffu, pdA[h], o);
            pdB[h] += __shfl_xor_sync(0xffffffffu, pdB[h], o);
        }
    }
    int lr = warp_m * 16 + (lane >> 2);
    __syncthreads();
    if (warp_n == 1 && (lane & 3) == 0) {
#pragma unroll
        for (int h = 0; h < 4; h++) {
            sRs[lr][h] = psA[h];     sRd[lr][h] = pdA[h];
            sRs[lr + 8][h] = psB[h]; sRd[lr + 8][h] = pdB[h];
        }
    }
    __syncthreads();
    if (warp_n == 0 && (lane & 3) == 0) {
        if (rowA < N_NODES) {
#pragma unroll
            for (int h = 0; h < 4; h++) {
                g_asrc[rowA * HEADS + h] = psA[h] + sRs[lr][h];
                g_adst[rowA * HEADS + h] = pdA[h] + sRd[lr][h];
            }
        }
        if (rowA + 8 < N_NODES) {
#pragma unroll
            for (int h = 0; h < 4; h++) {
                g_asrc[(rowA + 8) * HEADS + h] = psB[h] + sRs[lr + 8][h];
                g_adst[(rowA + 8) * HEADS + h] = pdB[h] + sRd[lr + 8][h];
            }
        }
    }
}

// ---------------- per-node softmax + weighted aggregation ----------------
__device__ __forceinline__ float leaky(float e) { return e > 0.f ? e : NEG_SLOPE * e; }

__device__ __forceinline__ void acc8(float* acc, uint4 v, float al) {
    float2 f0 = __half22float2(*(__half2*)&v.x);
    float2 f1 = __half22float2(*(__half2*)&v.y);
    float2 f2 = __half22float2(*(__half2*)&v.z);
    float2 f3 = __half22float2(*(__half2*)&v.w);
    acc[0] += f0.x * al; acc[1] += f0.y * al;
    acc[2] += f1.x * al; acc[3] += f1.y * al;
    acc[4] += f2.x * al; acc[5] += f2.y * al;
    acc[6] += f3.x * al; acc[7] += f3.y * al;
}

__global__ __launch_bounds__(128) void agg_k(const float* __restrict__ gat_bias) {
    __shared__ int   sadj[CAP];
    __shared__ float se[HEADS][CAP];
    __shared__ float sinv[HEADS], sadh[HEADS];
    __shared__ float swsum[4][HEADS];
    __shared__ float sacc[64][9];
    int d = blockIdx.x;
    int tid = threadIdx.x;
    int w = tid >> 5, lane = tid & 31;
    int beg = g_off[d];
    int deg = g_off[d + 1] - beg;
    bool cached = (deg <= CAP);
    float4 adv = *(const float4*)&g_adst[d * HEADS];

    float s0 = 0.f, s1 = 0.f, s2 = 0.f, s3 = 0.f;
    if (cached) {
        for (int i = tid; i < deg; i += 128) {
            int s = g_adj[beg + i];
            sadj[i] = s;
            float4 as = *(const float4*)&g_asrc[s * HEADS];
            float a0 = __expf(leaky(as.x + adv.x)); se[0][i] = a0; s0 += a0;
            float a1 = __expf(leaky(as.y + adv.y)); se[1][i] = a1; s1 += a1;
            float a2 = __expf(leaky(as.z + adv.z)); se[2][i] = a2; s2 += a2;
            float a3 = __expf(leaky(as.w + adv.w)); se[3][i] = a3; s3 += a3;
        }
    } else {
        for (int i = tid; i < deg; i += 128) {
            int s = g_adj[beg + i];
            float4 as = *(const float4*)&g_asrc[s * HEADS];
            s0 += __expf(leaky(as.x + adv.x));
            s1 += __expf(leaky(as.y + adv.y));
            s2 += __expf(leaky(as.z + adv.z));
            s3 += __expf(leaky(as.w + adv.w));
        }
    }
#pragma unroll
    for (int o = 16; o; o >>= 1) {
        s0 += __shfl_xor_sync(0xffffffffu, s0, o);
        s1 += __shfl_xor_sync(0xffffffffu, s1, o);
        s2 += __shfl_xor_sync(0xffffffffu, s2, o);
        s3 += __shfl_xor_sync(0xffffffffu, s3, o);
    }
    if (lane == 0) {
        swsum[w][0] = s0; swsum[w][1] = s1;
        swsum[w][2] = s2; swsum[w][3] = s3;
    }
    if (tid < HEADS) {
        float v = tid == 0 ? adv.x : tid == 1 ? adv.y : tid == 2 ? adv.z : adv.w;
        sadh[tid] = v;
    }
    __syncthreads();
    if (tid < HEADS) {
        float t = swsum[0][tid] + swsum[1][tid] + swsum[2][tid] + swsum[3][tid];
        sinv[tid] = 1.f / (t + 1e-16f);
    }
    __syncthreads();

    int g = tid >> 6;
    int t6 = tid & 63;
    int ch = t6 * 8;
    int head = t6 >> 4;
    float inv = sinv[head];
    float acc[8] = {0.f, 0.f, 0.f, 0.f, 0.f, 0.f, 0.f, 0.f};
    const __half* hbase = g_h16;

    if (cached) {
        int i = g;
        for (; i + 6 < deg; i += 8) {
            float al0 = se[head][i] * inv;
            float al1 = se[head][i + 2] * inv;
            float al2 = se[head][i + 4] * inv;
            float al3 = se[head][i + 6] * inv;
            uint4 v0 = *(const uint4*)&hbase[(size_t)sadj[i]     * HID + ch];
            uint4 v1 = *(const uint4*)&hbase[(size_t)sadj[i + 2] * HID + ch];
            uint4 v2 = *(const uint4*)&hbase[(size_t)sadj[i + 4] * HID + ch];
            uint4 v3 = *(const uint4*)&hbase[(size_t)sadj[i + 6] * HID + ch];
            acc8(acc, v0, al0);
            acc8(acc, v1, al1);
            acc8(acc, v2, al2);
            acc8(acc, v3, al3);
        }
        for (; i < deg; i += 2) {
            float al = se[head][i] * inv;
            uint4 v = *(const uint4*)&hbase[(size_t)sadj[i] * HID + ch];
            acc8(acc, v, al);
        }
    } else {
        float adhh = sadh[head];
        for (int i = g; i < deg; i += 2) {
            int s = g_adj[beg + i];
            float al = __expf(leaky(g_asrc[s * HEADS + head] + adhh)) * inv;
            uint4 v = *(const uint4*)&hbase[(size_t)s * HID + ch];
            acc8(acc, v, al);
        }
    }

    if (g == 1) {
#pragma unroll
        for (int j = 0; j < 8; j++) sacc[t6][j] = acc[j];
    }
    __syncthreads();
    if (g == 0) {
        float4 b0 = *(const float4*)&gat_bias[ch];
        float4 b1 = *(const float4*)&gat_bias[ch + 4];
        float r0 = fmaxf(acc[0] + sacc[t6][0] + b0.x, 0.f);
        float r1 = fmaxf(acc[1] + sacc[t6][1] + b0.y, 0.f);
        float r2 = fmaxf(acc[2] + sacc[t6][2] + b0.z, 0.f);
        float r3 = fmaxf(acc[3] + sacc[t6][3] + b0.w, 0.f);
        float r4 = fmaxf(acc[4] + sacc[t6][4] + b1.x, 0.f);
        float r5 = fmaxf(acc[5] + sacc[t6][5] + b1.y, 0.f);
        float r6 = fmaxf(acc[6] + sacc[t6][6] + b1.z, 0.f);
        float r7 = fmaxf(acc[7] + sacc[t6][7] + b1.w, 0.f);
        uint4 st;
        *(__half2*)&st.x = __floats2half2_rn(r0, r1);
        *(__half2*)&st.y = __floats2half2_rn(r2, r3);
        *(__half2*)&st.z = __floats2half2_rn(r4, r5);
        *(__half2*)&st.w = __floats2half2_rn(r6, r7);
        *(uint4*)&g_act16[(size_t)d * HID + ch] = st;
    }
}

// ------- GEMM2 (fp16 mma, 64-K chunks) + bias + residual + register LN ---
__global__ __launch_bounds__(256) void gemm2_ln_k(const float* __restrict__ proj_b,
                                                  const float* __restrict__ x,
                                                  const float* __restrict__ lng,
                                                  const float* __restrict__ lnb,
                                                  float* __restrict__ out) {
    __shared__ uint32_t sA[64 * 36];        // 9 KB
    __shared__ uint32_t sB[32 * 136];       // 17 KB
    __shared__ float sP1[2][64], sP2[2][64];// 1 KB LN partials per warp_n
    int tid = threadIdx.x;
    int lane = tid & 31, wid = tid >> 5;
    int warp_m = wid & 3, warp_n = wid >> 2;
    int m0 = blockIdx.x * 64;

    float c[8][4];
#pragma unroll
    for (int nt = 0; nt < 8; nt++)
#pragma unroll
        for (int r = 0; r < 4; r++) c[nt][r] = 0.f;

    int aRow = warp_m * 16 + (lane >> 2);
    int kq = lane & 3;

    for (int kc = 0; kc < HID; kc += 64) {
        __syncthreads();
#pragma unroll
        for (int p = 0; p < 4; p++) {
            int idx = tid + p * 256;
            int row = idx >> 4, h2 = (idx & 15) * 2;
            int gr = m0 + row;
            uint2 v = (gr < N_NODES)
                ? *(const uint2*)&g_act16[(size_t)gr * HID + kc + h2 * 2]
                : make_uint2(0u, 0u);
            sA[row * 36 + h2] = v.x;
            sA[row * 36 + h2 + 1] = v.y;
        }
#pragma unroll
        for (int p = 0; p < 4; p++) {
            int idx = tid + p * 256;
            int row = idx >> 5, q = (idx & 31) * 4;
            uint4 v = *(const uint4*)&g_w16[(size_t)(kc / 2 + row) * OUT_CH + q];
            *(uint4*)&sB[row * 136 + q] = v;
        }
        __syncthreads();

#pragma unroll
        for (int ks = 0; ks < 64; ks += 16) {
            int ho = ks >> 1;
            uint32_t a0 = sA[aRow * 36 + ho + kq];
            uint32_t a1 = sA[(aRow + 8) * 36 + ho + kq];
            uint32_t a2 = sA[aRow * 36 + ho + kq + 4];
            uint32_t a3 = sA[(aRow + 8) * 36 + ho + kq + 4];
#pragma unroll
            for (int nt = 0; nt < 8; nt++) {
                int nb = warp_n * 64 + nt * 8 + (lane >> 2);
                uint32_t b0 = sB[(ho + kq) * 136 + nb];
                uint32_t b1 = sB[(ho + kq + 4) * 136 + nb];
                asm volatile(
                    "mma.sync.aligned.m16n8k16.row.col.f32.f16.f16.f32 "
                    "{%0,%1,%2,%3}, {%4,%5,%6,%7}, {%8,%9}, {%0,%1,%2,%3};"
                    : "+f"(c[nt][0]), "+f"(c[nt][1]), "+f"(c[nt][2]), "+f"(c[nt][3])
                    : "r"(a0), "r"(a1), "r"(a2), "r"(a3), "r"(b0), "r"(b1));
            }
        }
    }

    int lr = warp_m * 16 + (lane >> 2);
    int gr0 = m0 + lr, gr1 = gr0 + 8;
    float s1r0 = 0.f, s2r0 = 0.f, s1r1 = 0.f, s2r1 = 0.f;
#pragma unroll
    for (int nt = 0; nt < 8; nt++) {
        int col = warp_n * 64 + nt * 8 + (lane & 3) * 2;
        float pb0 = proj_b[col], pb1 = proj_b[col + 1];
        float x00 = 0.f, x01 = 0.f, x10 = 0.f, x11 = 0.f;
        if (gr0 < N_NODES) {
            x00 = x[(size_t)gr0 * OUT_CH + col];
            x01 = x[(size_t)gr0 * OUT_CH + col + 1];
        }
        if (gr1 < N_NODES) {
            x10 = x[(size_t)gr1 * OUT_CH + col];
            x11 = x[(size_t)gr1 * OUT_CH + col + 1];
        }
        c[nt][0] += pb0 + x00;
        c[nt][1] += pb1 + x01;
        c[nt][2] += pb0 + x10;
        c[nt][3] += pb1 + x11;
        s1r0 += c[nt][0] + c[nt][1];
        s2r0 += c[nt][0] * c[nt][0] + c[nt][1] * c[nt][1];
        s1r1 += c[nt][2] + c[nt][3];
        s2r1 += c[nt][2] * c[nt][2] + c[nt][3] * c[nt][3];
    }
#pragma unroll
    for (int o = 1; o < 4; o <<= 1) {
        s1r0 += __shfl_xor_sync(0xffffffffu, s1r0, o);
        s2r0 += __shfl_xor_sync(0xffffffffu, s2r0, o);
        s1r1 += __shfl_xor_sync(0xffffffffu, s1r1, o);
        s2r1 += __shfl_xor_sync(0xffffffffu, s2r1, o);
    }
    __syncthreads();
    if ((lane & 3) == 0) {
        sP1[warp_n][lr] = s1r0;     sP2[warp_n][lr] = s2r0;
        sP1[warp_n][lr + 8] = s1r1; sP2[warp_n][lr + 8] = s2r1;
    }
    __syncthreads();
    float t1r0 = sP1[0][lr] + sP1[1][lr];
    float t2r0 = sP2[0][lr] + sP2[1][lr];
    float t1r1 = sP1[0][lr + 8] + sP1[1][lr + 8];
    float t2r1 = sP2[0][lr + 8] + sP2[1][lr + 8];
    float mu0 = t1r0 * (1.f / 128.f);
    float rs0 = rsqrtf(t2r0 * (1.f / 128.f) - mu0 * mu0 + LN_EPS);
    float mu1 = t1r1 * (1.f / 128.f);
    float rs1 = rsqrtf(t2r1 * (1.f / 128.f) - mu1 * mu1 + LN_EPS);

#pragma unroll
    for (int nt = 0; nt < 8; nt++) {
        int col = warp_n * 64 + nt * 8 + (lane & 3) * 2;
        float g0 = lng[col], g1 = lng[col + 1];
        float b0 = lnb[col], b1 = lnb[col + 1];
        if (gr0 < N_NODES) {
            float2 o0 = make_float2((c[nt][0] - mu0) * rs0 * g0 + b0,
                                    (c[nt][1] - mu0) * rs0 * g1 + b1);
            *(float2*)&out[(size_t)gr0 * OUT_CH + col] = o0;
        }
        if (gr1 < N_NODES) {
            float2 o1 = make_float2((c[nt][2] - mu1) * rs1 * g0 + b0,
                                    (c[nt][3] - mu1) * rs1 * g1 + b1);
            *(float2*)&out[(size_t)gr1 * OUT_CH + col] = o1;
        }
    }
}

// ----- launch: CSR on main stream (critical path), GEMM1 on side --------
extern "C" void kernel_launch(void* const* d_in, const int* in_sizes, int n_in,
                              void* d_out, int out_size) {
    const float* x        = (const float*)d_in[0];
    const void*  ei       = d_in[1];
    const float* lin_w    = (const float*)d_in[2];
    const float* att_src  = (const float*)d_in[3];
    const float* att_dst  = (const float*)d_in[4];
    const float* gat_bias = (const float*)d_in[5];
    const float* proj_w   = (const float*)d_in[6];
    const float* proj_b   = (const float*)d_in[7];
    const float* ln_g     = (const float*)d_in[8];
    const float* ln_b     = (const float*)d_in[9];
    float* out = (float*)d_out;

    cudaStream_t sc;
    cudaEvent_t evF, evJ;
    cudaStreamCreateWithFlags(&sc, cudaStreamNonBlocking);
    cudaEventCreateWithFlags(&evF, cudaEventDisableTiming);
    cudaEventCreateWithFlags(&evJ, cudaEventDisableTiming);

    cudaEventRecord(evF, 0);
    cudaStreamWaitEvent(sc, evF, 0);

    // ---- side stream: feature path (attn fused into gemm1) + wconv ----
    lwconv_k<<<((IN_CH / 2) * HID + 255) / 256, 256, 0, sc>>>(lin_w);
    gemm1_k<<<(N_NODES + 63) / 64, 256, 0, sc>>>(x, att_src, att_dst);
    wconv_k<<<((HID / 2) * OUT_CH + 255) / 256, 256, 0, sc>>>(proj_w);
    cudaEventRecord(evJ, sc);

    // ---- main stream: CSR build (the critical path) ----
    initdet_k<<<(N_NODES + 255) / 256, 256>>>(ei);
    hist_k<<<(N_EDGES + 255) / 256, 256>>>(ei);
    partial_k<<<NPART, SCAN_BLK>>>();
    scanoff_k<<<NPART, SCAN_BLK>>>();
    scatter_k<<<(N_EDGES + 255) / 256, 256>>>(ei);

    cudaStreamWaitEvent(0, evJ, 0);
    agg_k<<<N_NODES, 128>>>(gat_bias);
    gemm2_ln_k<<<(N_NODES + 63) / 64, 256>>>(proj_b, x, ln_g, ln_b, out);
}